// round 7
// baseline (speedup 1.0000x reference)
#include <cuda_runtime.h>
#include <cuda_bf16.h>
#include <math.h>
#include <cstdint>

#define NHEAD 16
#define NKV   4
#define DH    64
#define BATCH 2
#define SEQ   2048
#define MTOK  (BATCH*SEQ)     // 4096
#define DM    1024
#define NQKV  1536            // 1024(Q) + 256(K) + 256(V)

// static int8 scales (x and W are well-conditioned vs these)
#define S_X   (6.5f/127.0f)
#define S_W   (0.13f/127.0f)
#define INV_SX   (127.0f/6.5f)
#define INV_SW   (127.0f/0.13f)

// ---------------------------------------------------------------------------
// Scratch (static device globals -- no allocation allowed)
// ---------------------------------------------------------------------------
__device__ int8_t g_A2[(size_t)MTOK * 2048];           // x limbs [h|l]   8 MB
__device__ int8_t g_W2[(size_t)NQKV * 2048];           // Wq|Wk|Wv limbs  3 MB
__device__ int8_t g_Wo2[(size_t)DM * 2048];            // Wo limbs        2 MB
__device__ int8_t g_C2[(size_t)MTOK * 2048];           // ctx limbs       8 MB
__device__ float  g_Sctx[(size_t)MTOK * NHEAD];        // ctx scales 256 KB
__device__ __nv_bfloat16 g_Qhi[(size_t)MTOK * NQKV];   // QKV hi plane 12 MB
__device__ __nv_bfloat16 g_Qlo[(size_t)MTOK * NQKV];   // QKV lo plane 12 MB

// ---------------------------------------------------------------------------
// PTX helpers (portable sm_80-class)
// ---------------------------------------------------------------------------
__device__ __forceinline__ uint32_t smem_u32(const void* p) {
    return (uint32_t)__cvta_generic_to_shared(p);
}
__device__ __forceinline__ void cp_async16(uint32_t saddr, const void* gaddr) {
    asm volatile("cp.async.cg.shared.global [%0], [%1], 16;" :: "r"(saddr), "l"(gaddr));
}
__device__ __forceinline__ void cp_commit() {
    asm volatile("cp.async.commit_group;" ::: "memory");
}
template<int N>
__device__ __forceinline__ void cp_wait() {
    asm volatile("cp.async.wait_group %0;" :: "n"(N) : "memory");
}
__device__ __forceinline__ void ldmatrix_x4(uint32_t& r0, uint32_t& r1,
                                            uint32_t& r2, uint32_t& r3, uint32_t a) {
    asm volatile("ldmatrix.sync.aligned.m8n8.x4.shared.b16 {%0,%1,%2,%3}, [%4];"
                 : "=r"(r0), "=r"(r1), "=r"(r2), "=r"(r3) : "r"(a));
}
__device__ __forceinline__ void ldmatrix_x4_t(uint32_t& r0, uint32_t& r1,
                                              uint32_t& r2, uint32_t& r3, uint32_t a) {
    asm volatile("ldmatrix.sync.aligned.m8n8.x4.trans.shared.b16 {%0,%1,%2,%3}, [%4];"
                 : "=r"(r0), "=r"(r1), "=r"(r2), "=r"(r3) : "r"(a));
}
__device__ __forceinline__ void mma_bf16(float* c, uint32_t a0, uint32_t a1,
                                         uint32_t a2, uint32_t a3,
                                         uint32_t b0, uint32_t b1) {
    asm volatile("mma.sync.aligned.m16n8k16.row.col.f32.bf16.bf16.f32 "
                 "{%0,%1,%2,%3}, {%4,%5,%6,%7}, {%8,%9}, {%0,%1,%2,%3};"
                 : "+f"(c[0]), "+f"(c[1]), "+f"(c[2]), "+f"(c[3])
                 : "r"(a0), "r"(a1), "r"(a2), "r"(a3), "r"(b0), "r"(b1));
}
__device__ __forceinline__ void mma_s8(int* c, uint32_t a0, uint32_t a1,
                                       uint32_t a2, uint32_t a3,
                                       uint32_t b0, uint32_t b1) {
    asm volatile("mma.sync.aligned.m16n8k32.row.col.s32.s8.s8.s32 "
                 "{%0,%1,%2,%3}, {%4,%5,%6,%7}, {%8,%9}, {%0,%1,%2,%3};"
                 : "+r"(c[0]), "+r"(c[1]), "+r"(c[2]), "+r"(c[3])
                 : "r"(a0), "r"(a1), "r"(a2), "r"(a3), "r"(b0), "r"(b1));
}
__device__ __forceinline__ float ex2(float x) {
    float r; asm("ex2.approx.f32 %0, %1;" : "=f"(r) : "f"(x)); return r;
}
__device__ __forceinline__ uint32_t pack_bf2(float x, float y) {
    uint32_t r; asm("cvt.rn.bf16x2.f32 %0, %1, %2;" : "=r"(r) : "f"(y), "f"(x)); return r;
}
__device__ __forceinline__ float bflo_f(uint32_t p) { return __uint_as_float(p << 16); }
__device__ __forceinline__ float bfhi_f(uint32_t p) { return __uint_as_float(p & 0xffff0000u); }

// two-limb int8 quantization
__device__ __forceinline__ void q2(float v, float invs, int& h, int& l) {
    float t = v * invs;
    int hh = __float2int_rn(t);
    hh = hh > 127 ? 127 : (hh < -127 ? -127 : hh);
    int ll = __float2int_rn((t - (float)hh) * 256.0f);
    ll = ll > 127 ? 127 : (ll < -127 ? -127 : ll);
    h = hh; l = ll;
}

// ---------------------------------------------------------------------------
// Prep: quantize fp32 rows -> int8 limb planes [m][0..1023]=h, [1024..2047]=l
// ---------------------------------------------------------------------------
__global__ void quant8_rows(const float* __restrict__ in, int8_t* __restrict__ out,
                            int M, float invs)
{
    int tot = M * (DM / 4);
    for (int idx = blockIdx.x * blockDim.x + threadIdx.x; idx < tot;
         idx += gridDim.x * blockDim.x) {
        int m = idx / (DM / 4);
        int k4 = (idx % (DM / 4)) * 4;
        float4 v = ((const float4*)in)[idx];
        int h0, l0, h1, l1, h2, l2, h3, l3;
        q2(v.x, invs, h0, l0); q2(v.y, invs, h1, l1);
        q2(v.z, invs, h2, l2); q2(v.w, invs, h3, l3);
        *(char4*)&out[(size_t)m * 2048 + k4] =
            make_char4((char)h0, (char)h1, (char)h2, (char)h3);
        *(char4*)&out[(size_t)m * 2048 + 1024 + k4] =
            make_char4((char)l0, (char)l1, (char)l2, (char)l3);
    }
}

// W[1024, Ndim] row-major -> out[(rowoff+n)][k limbs]
__global__ void transpose_quant8(const float* __restrict__ W, int8_t* __restrict__ out,
                                 int Ndim, int rowoff, float invs)
{
    __shared__ float t[32][33];
    int n0 = blockIdx.x * 32, k0 = blockIdx.y * 32;
    int tx = threadIdx.x, ty = threadIdx.y;
    #pragma unroll
    for (int i = 0; i < 32; i += 8)
        t[ty + i][tx] = W[(size_t)(k0 + ty + i) * Ndim + (n0 + tx)];
    __syncthreads();
    #pragma unroll
    for (int i = 0; i < 32; i += 8) {
        float v = t[tx][ty + i];
        int h, l; q2(v, invs, h, l);
        size_t row = (size_t)(rowoff + n0 + ty + i);
        out[row * 2048 + (k0 + tx)]        = (int8_t)h;
        out[row * 2048 + 1024 + (k0 + tx)] = (int8_t)l;
    }
}

// ---------------------------------------------------------------------------
// int8 two-limb tensor-core GEMM. CTA tile 128x64, 8 warps (32x32), 3-stage.
// OUT_MODE 1 (QKV): static scale, full-K int accumulation, bf16 hi/lo out.
// OUT_MODE 0 (Wo):  per-(row,chunk) dynamic scales from Sctx, per-chunk
//                   fold into fp32 accumulator, fp32 out.
// ---------------------------------------------------------------------------
#define IROW 80
#define ST_AH 0
#define ST_AL (128*IROW)          // 10240
#define ST_BH (2*128*IROW)        // 20480
#define ST_BL (ST_BH + 64*IROW)   // 25600
#define ISTG  (ST_BL + 64*IROW)   // 30720
#define IMMA_SMEM (3*ISTG)        // 92160

template<int OUT_MODE>
__global__ __launch_bounds__(256, 2) void imma_gemm(
    const int8_t* __restrict__ A2, const int8_t* __restrict__ B2,
    const float* __restrict__ Sctx,
    float* __restrict__ C, __nv_bfloat16* __restrict__ Chi,
    __nv_bfloat16* __restrict__ Clo, int M, int N, float outscale)
{
    extern __shared__ char gsm[];
    uint32_t sb = smem_u32(gsm);

    int tid = threadIdx.x;
    int lane = tid & 31;
    int wid = tid >> 5;
    int wm = wid & 3;          // 32-row band
    int wn = wid >> 2;         // 32-col band
    int m0 = blockIdx.y * 128;
    int n0 = blockIdx.x * 64;
    int cr = lane >> 2;

    int acc1[2][4][4], acc2[2][4][4];
    float accf[2][4][4];
    #pragma unroll
    for (int i = 0; i < 2; i++)
        #pragma unroll
        for (int j = 0; j < 4; j++)
            #pragma unroll
            for (int q = 0; q < 4; q++) { acc1[i][j][q] = 0; acc2[i][j][q] = 0; accf[i][j][q] = 0.0f; }

    auto issue = [&](int kc, int s) {
        int k0 = kc * 64;
        uint32_t stg = sb + s * ISTG;
        #pragma unroll
        for (int i = 0; i < 2; i++) {
            int idx = tid + i * 256;
            int r = idx >> 2, c = idx & 3;
            cp_async16(stg + ST_AH + r * IROW + c * 16,
                       A2 + (size_t)(m0 + r) * 2048 + k0 + c * 16);
            cp_async16(stg + ST_AL + r * IROW + c * 16,
                       A2 + (size_t)(m0 + r) * 2048 + 1024 + k0 + c * 16);
        }
        {
            int r = tid >> 2, c = tid & 3;
            cp_async16(stg + ST_BH + r * IROW + c * 16,
                       B2 + (size_t)(n0 + r) * 2048 + k0 + c * 16);
            cp_async16(stg + ST_BL + r * IROW + c * 16,
                       B2 + (size_t)(n0 + r) * 2048 + 1024 + k0 + c * 16);
        }
        cp_commit();
    };

    const int nk = 16;   // 1024 limb-bytes / 64
    issue(0, 0);
    issue(1, 1);

    int a_row = wm * 32 + (lane & 15);
    int a_byte = (lane >> 4) * 16;
    int b_row = (lane & 7) + ((lane >> 4) << 3);
    int b_byte = ((lane >> 3) & 1) * 16;

    int buf = 0;
    for (int kc = 0; kc < nk; kc++) {
        if (kc + 2 < nk) { issue(kc + 2, (kc + 2) % 3); cp_wait<2>(); }
        else if (kc + 1 < nk) { cp_wait<1>(); }
        else { cp_wait<0>(); }
        __syncthreads();

        uint32_t stg = sb + buf * ISTG;
        #pragma unroll
        for (int ks = 0; ks < 2; ks++) {
            uint32_t ah[2][4], al[2][4];
            #pragma unroll
            for (int mi = 0; mi < 2; mi++) {
                uint32_t ao = (a_row + mi * 16) * IROW + ks * 32 + a_byte;
                ldmatrix_x4(ah[mi][0], ah[mi][1], ah[mi][2], ah[mi][3], stg + ST_AH + ao);
                ldmatrix_x4(al[mi][0], al[mi][1], al[mi][2], al[mi][3], stg + ST_AL + ao);
            }
            uint32_t bh[2][4], bl[2][4];
            #pragma unroll
            for (int g = 0; g < 2; g++) {
                uint32_t bo = (wn * 32 + g * 16 + b_row) * IROW + ks * 32 + b_byte;
                ldmatrix_x4(bh[g][0], bh[g][1], bh[g][2], bh[g][3], stg + ST_BH + bo);
                ldmatrix_x4(bl[g][0], bl[g][1], bl[g][2], bl[g][3], stg + ST_BL + bo);
            }
            #pragma unroll
            for (int mi = 0; mi < 2; mi++)
                #pragma unroll
                for (int j = 0; j < 4; j++) {
                    int g = j >> 1, pr = (j & 1) * 2;
                    mma_s8(acc1[mi][j], ah[mi][0], ah[mi][1], ah[mi][2], ah[mi][3],
                           bh[g][pr], bh[g][pr + 1]);
                    mma_s8(acc2[mi][j], ah[mi][0], ah[mi][1], ah[mi][2], ah[mi][3],
                           bl[g][pr], bl[g][pr + 1]);
                    mma_s8(acc2[mi][j], al[mi][0], al[mi][1], al[mi][2], al[mi][3],
                           bh[g][pr], bh[g][pr + 1]);
                }
        }
        __syncthreads();

        if (OUT_MODE == 0) {
            // fold this chunk (= head kc) with its per-row dynamic scale
            #pragma unroll
            for (int mi = 0; mi < 2; mi++) {
                float sA = Sctx[(size_t)(m0 + wm * 32 + mi * 16 + cr) * NHEAD + kc];
                float sB = Sctx[(size_t)(m0 + wm * 32 + mi * 16 + cr + 8) * NHEAD + kc];
                #pragma unroll
                for (int j = 0; j < 4; j++) {
                    accf[mi][j][0] += sA * ((float)acc1[mi][j][0] + (float)acc2[mi][j][0] * 0.00390625f);
                    accf[mi][j][1] += sA * ((float)acc1[mi][j][1] + (float)acc2[mi][j][1] * 0.00390625f);
                    accf[mi][j][2] += sB * ((float)acc1[mi][j][2] + (float)acc2[mi][j][2] * 0.00390625f);
                    accf[mi][j][3] += sB * ((float)acc1[mi][j][3] + (float)acc2[mi][j][3] * 0.00390625f);
                    #pragma unroll
                    for (int q = 0; q < 4; q++) { acc1[mi][j][q] = 0; acc2[mi][j][q] = 0; }
                }
            }
        }
        buf = (buf + 1 == 3) ? 0 : buf + 1;
    }

    // epilogue
    int cc = (lane & 3) * 2;
    #pragma unroll
    for (int mi = 0; mi < 2; mi++) {
        #pragma unroll
        for (int j = 0; j < 4; j++) {
            int row = m0 + wm * 32 + mi * 16 + cr;
            int col = n0 + wn * 32 + j * 8 + cc;
            if (OUT_MODE == 0) {
                float v0 = outscale * accf[mi][j][0];
                float v1 = outscale * accf[mi][j][1];
                float v2 = outscale * accf[mi][j][2];
                float v3 = outscale * accf[mi][j][3];
                *(float2*)&C[(size_t)row * N + col]       = make_float2(v0, v1);
                *(float2*)&C[(size_t)(row + 8) * N + col] = make_float2(v2, v3);
            } else {
                float v0 = outscale * ((float)acc1[mi][j][0] + (float)acc2[mi][j][0] * 0.00390625f);
                float v1 = outscale * ((float)acc1[mi][j][1] + (float)acc2[mi][j][1] * 0.00390625f);
                float v2 = outscale * ((float)acc1[mi][j][2] + (float)acc2[mi][j][2] * 0.00390625f);
                float v3 = outscale * ((float)acc1[mi][j][3] + (float)acc2[mi][j][3] * 0.00390625f);
                uint32_t h0 = pack_bf2(v0, v1);
                uint32_t l0 = pack_bf2(v0 - bflo_f(h0), v1 - bfhi_f(h0));
                uint32_t h1 = pack_bf2(v2, v3);
                uint32_t l1 = pack_bf2(v2 - bflo_f(h1), v3 - bfhi_f(h1));
                *(uint32_t*)&Chi[(size_t)row * N + col] = h0;
                *(uint32_t*)&Clo[(size_t)row * N + col] = l0;
                *(uint32_t*)&Chi[(size_t)(row + 8) * N + col] = h1;
                *(uint32_t*)&Clo[(size_t)(row + 8) * N + col] = l1;
            }
        }
    }
}

// ---------------------------------------------------------------------------
// RoPE in-place on bf16 hi/lo planes [MTOK, 1536]
// ---------------------------------------------------------------------------
__global__ void rope_kernel(__nv_bfloat16* __restrict__ hi,
                            __nv_bfloat16* __restrict__ lo)
{
    const int tot = MTOK * 20 * 32;
    int idx = blockIdx.x * blockDim.x + threadIdx.x;
    if (idx >= tot) return;

    int i    = idx & 31;
    int hh   = (idx >> 5) % 20;
    int tok  = idx / (32 * 20);
    int s    = tok % SEQ;
    int col  = (hh < 16) ? hh * DH : 1024 + (hh - 16) * DH;
    size_t base = (size_t)tok * NQKV + col;

    float invf = exp10f(-(float)i * 0.125f);
    float ang  = (float)s * invf;
    float c = cosf(ang), sn = sinf(ang);

    float x0 = __bfloat162float(hi[base + i])      + __bfloat162float(lo[base + i]);
    float x1 = __bfloat162float(hi[base + i + 32]) + __bfloat162float(lo[base + i + 32]);
    float y0 = x0 * c - x1 * sn;
    float y1 = x1 * c + x0 * sn;

    __nv_bfloat16 h0 = __float2bfloat16(y0);
    __nv_bfloat16 h1 = __float2bfloat16(y1);
    hi[base + i]      = h0;
    lo[base + i]      = __float2bfloat16(y0 - __bfloat162float(h0));
    hi[base + i + 32] = h1;
    lo[base + i + 32] = __float2bfloat16(y1 - __bfloat162float(h1));
}

// ---------------------------------------------------------------------------
// Tensor-core flash attention (bf16 hi/lo planes, double-buffered KV).
// Epilogue: per-(token,head) dynamic scale -> int8 two-limb ctx + g_Sctx.
// ---------------------------------------------------------------------------
#define AROW 72
#define ROWB (AROW*2)
#define SQ_HI 0
#define SQ_LO (128*ROWB)
#define SKV0  (2*128*ROWB)
#define KVSTG (4*64*ROWB)
#define ATTN_SMEM (SKV0 + 2*KVSTG)   // 110592

__global__ __launch_bounds__(256) void attn_mma(
    const __nv_bfloat16* __restrict__ Phi, const __nv_bfloat16* __restrict__ Plo,
    int8_t* __restrict__ C2, float* __restrict__ Sctx)
{
    extern __shared__ char smc[];
    uint32_t sb = smem_u32(smc);

    int qt = (int)gridDim.x - 1 - (int)blockIdx.x;
    int h  = blockIdx.y;
    int b  = blockIdx.z;
    int kh = h >> 2;

    int tid  = threadIdx.x;
    int lane = tid & 31;
    int wm   = tid >> 5;

    const int kcol = 1024 + kh * DH;
    const int vcol = 1280 + kh * DH;

    {
        #pragma unroll
        for (int it = 0; it < 8; it++) {
            int idx = tid + it * 256;
            int pl = idx >> 10;
            int j = idx & 1023;
            int r = j >> 3, c = j & 7;
            const __nv_bfloat16* src = (pl ? Plo : Phi)
                + (size_t)(b * SEQ + qt * 128 + r) * NQKV + h * DH + c * 8;
            uint32_t dst = sb + (pl ? SQ_LO : SQ_HI) + r * ROWB + c * 16;
            cp_async16(dst, src);
        }
        #pragma unroll
        for (int it = 0; it < 8; it++) {
            int idx = tid + it * 256;
            int sel = idx >> 9;
            int j = idx & 511;
            int r = j >> 3, c = j & 7;
            const __nv_bfloat16* base = (sel & 1) ? Plo : Phi;
            int colb = (sel < 2) ? kcol : vcol;
            const __nv_bfloat16* src = base + (size_t)(b * SEQ + r) * NQKV + colb + c * 8;
            uint32_t dst = sb + SKV0 + sel * (64 * ROWB) + r * ROWB + c * 16;
            cp_async16(dst, src);
        }
        cp_commit();
    }

    uint32_t qa_off = (uint32_t)((wm * 16 + (lane & 7) + ((lane >> 3) & 1) * 8) * ROWB
                                 + (lane >> 4) * 16);
    uint32_t kb_off = (uint32_t)(((lane & 7) + (lane >> 4) * 8) * ROWB
                                 + ((lane >> 3) & 1) * 16);
    uint32_t vb_off = (uint32_t)(((lane & 7) + ((lane >> 3) & 1) * 8) * ROWB
                                 + (lane >> 4) * 16);

    float acc[8][4];
    #pragma unroll
    for (int j = 0; j < 8; j++)
        #pragma unroll
        for (int q = 0; q < 4; q++) acc[j][q] = 0.0f;
    float m0 = -1e30f, m1 = -1e30f, l0 = 0.0f, l1 = 0.0f;

    const float SCL = 0.125f * 1.44269504f;
    int row0g = qt * 128 + wm * 16 + (lane >> 2);
    int colbase = 2 * (lane & 3);

    int nkt = 2 * qt + 2;
    for (int kt = 0; kt < nkt; kt++) {
        if (kt + 1 < nkt) {
            int stg = (kt + 1) & 1;
            #pragma unroll
            for (int it = 0; it < 8; it++) {
                int idx = tid + it * 256;
                int sel = idx >> 9;
                int j = idx & 511;
                int r = j >> 3, c = j & 7;
                const __nv_bfloat16* base = (sel & 1) ? Plo : Phi;
                int colb = (sel < 2) ? kcol : vcol;
                const __nv_bfloat16* src = base
                    + (size_t)(b * SEQ + (kt + 1) * 64 + r) * NQKV + colb + c * 8;
                uint32_t dst = sb + SKV0 + stg * KVSTG + sel * (64 * ROWB) + r * ROWB + c * 16;
                cp_async16(dst, src);
            }
            cp_commit();
            cp_wait<1>();
        } else {
            cp_wait<0>();
        }
        __syncthreads();

        uint32_t kvb = sb + SKV0 + (kt & 1) * KVSTG;
        uint32_t skh = kvb, skl = kvb + 64 * ROWB;
        uint32_t svh = kvb + 2 * 64 * ROWB, svl = kvb + 3 * 64 * ROWB;

        float sf[8][4];
        #pragma unroll
        for (int j = 0; j < 8; j++)
            #pragma unroll
            for (int q = 0; q < 4; q++) sf[j][q] = 0.0f;

        #pragma unroll
        for (int t = 0; t < 4; t++) {
            uint32_t qh[4], ql[4];
            ldmatrix_x4(qh[0], qh[1], qh[2], qh[3], sb + SQ_HI + qa_off + t * 32);
            ldmatrix_x4(ql[0], ql[1], ql[2], ql[3], sb + SQ_LO + qa_off + t * 32);
            #pragma unroll
            for (int jj = 0; jj < 4; jj++) {
                uint32_t kmh[4], kml[4];
                uint32_t off = kb_off + jj * 16 * ROWB + t * 32;
                ldmatrix_x4(kmh[0], kmh[1], kmh[2], kmh[3], skh + off);
                ldmatrix_x4(kml[0], kml[1], kml[2], kml[3], skl + off);
                mma_bf16(sf[2*jj],   qh[0], qh[1], qh[2], qh[3], kmh[0], kmh[1]);
                mma_bf16(sf[2*jj],   ql[0], ql[1], ql[2], ql[3], kmh[0], kmh[1]);
                mma_bf16(sf[2*jj],   qh[0], qh[1], qh[2], qh[3], kml[0], kml[1]);
                mma_bf16(sf[2*jj+1], qh[0], qh[1], qh[2], qh[3], kmh[2], kmh[3]);
                mma_bf16(sf[2*jj+1], ql[0], ql[1], ql[2], ql[3], kmh[2], kmh[3]);
                mma_bf16(sf[2*jj+1], qh[0], qh[1], qh[2], qh[3], kml[2], kml[3]);
            }
        }

        bool need_mask = (kt * 64 + 63 > qt * 128 + wm * 16);
        if (need_mask) {
            #pragma unroll
            for (int j = 0; j < 8; j++) {
                int c0 = kt * 64 + 8 * j + colbase;
                sf[j][0] = (c0     <= row0g)     ? sf[j][0] * SCL : -1e30f;
                sf[j][1] = (c0 + 1 <= row0g)     ? sf[j][1] * SCL : -1e30f;
                sf[j][2] = (c0     <= row0g + 8) ? sf[j][2] * SCL : -1e30f;
                sf[j][3] = (c0 + 1 <= row0g + 8) ? sf[j][3] * SCL : -1e30f;
            }
        } else {
            #pragma unroll
            for (int j = 0; j < 8; j++)
                #pragma unroll
                for (int q = 0; q < 4; q++) sf[j][q] *= SCL;
        }

        float mx0 = m0, mx1 = m1;
        #pragma unroll
        for (int j = 0; j < 8; j++) {
            mx0 = fmaxf(mx0, fmaxf(sf[j][0], sf[j][1]));
            mx1 = fmaxf(mx1, fmaxf(sf[j][2], sf[j][3]));
        }
        mx0 = fmaxf(mx0, __shfl_xor_sync(0xffffffffu, mx0, 1));
        mx0 = fmaxf(mx0, __shfl_xor_sync(0xffffffffu, mx0, 2));
        mx1 = fmaxf(mx1, __shfl_xor_sync(0xffffffffu, mx1, 1));
        mx1 = fmaxf(mx1, __shfl_xor_sync(0xffffffffu, mx1, 2));
        float corr0 = ex2(m0 - mx0);
        float corr1 = ex2(m1 - mx1);
        m0 = mx0; m1 = mx1;

        float ls0 = 0.0f, ls1 = 0.0f;
        #pragma unroll
        for (int j = 0; j < 8; j++) {
            sf[j][0] = ex2(sf[j][0] - mx0);
            sf[j][1] = ex2(sf[j][1] - mx0);
            sf[j][2] = ex2(sf[j][2] - mx1);
            sf[j][3] = ex2(sf[j][3] - mx1);
            ls0 += sf[j][0] + sf[j][1];
            ls1 += sf[j][2] + sf[j][3];
        }
        l0 = l0 * corr0 + ls0;
        l1 = l1 * corr1 + ls1;
        #pragma unroll
        for (int j = 0; j < 8; j++) {
            acc[j][0] *= corr0; acc[j][1] *= corr0;
            acc[j][2] *= corr1; acc[j][3] *= corr1;
        }

        #pragma unroll
        for (int t = 0; t < 4; t++) {
            uint32_t aph[4], apl[4];
            {
                float p00 = sf[2*t][0],   p01 = sf[2*t][1];
                float p10 = sf[2*t][2],   p11 = sf[2*t][3];
                float p20 = sf[2*t+1][0], p21 = sf[2*t+1][1];
                float p30 = sf[2*t+1][2], p31 = sf[2*t+1][3];
                aph[0] = pack_bf2(p00, p01);
                aph[1] = pack_bf2(p10, p11);
                aph[2] = pack_bf2(p20, p21);
                aph[3] = pack_bf2(p30, p31);
                apl[0] = pack_bf2(p00 - bflo_f(aph[0]), p01 - bfhi_f(aph[0]));
                apl[1] = pack_bf2(p10 - bflo_f(aph[1]), p11 - bfhi_f(aph[1]));
                apl[2] = pack_bf2(p20 - bflo_f(aph[2]), p21 - bfhi_f(aph[2]));
                apl[3] = pack_bf2(p30 - bflo_f(aph[3]), p31 - bfhi_f(aph[3]));
            }
            #pragma unroll
            for (int jj = 0; jj < 4; jj++) {
                uint32_t vh[4], vl[4];
                uint32_t off = vb_off + t * 16 * ROWB + jj * 32;
                ldmatrix_x4_t(vh[0], vh[1], vh[2], vh[3], svh + off);
                ldmatrix_x4_t(vl[0], vl[1], vl[2], vl[3], svl + off);
                mma_bf16(acc[2*jj],   aph[0], aph[1], aph[2], aph[3], vh[0], vh[1]);
                mma_bf16(acc[2*jj],   apl[0], apl[1], apl[2], apl[3], vh[0], vh[1]);
                mma_bf16(acc[2*jj],   aph[0], aph[1], aph[2], aph[3], vl[0], vl[1]);
                mma_bf16(acc[2*jj+1], aph[0], aph[1], aph[2], aph[3], vh[2], vh[3]);
                mma_bf16(acc[2*jj+1], apl[0], apl[1], apl[2], apl[3], vh[2], vh[3]);
                mma_bf16(acc[2*jj+1], aph[0], aph[1], aph[2], aph[3], vl[2], vl[3]);
            }
        }
        __syncthreads();
    }

    // --- final normalize, per-(row,head) dynamic scale, int8 two-limb ctx ---
    l0 += __shfl_xor_sync(0xffffffffu, l0, 1);
    l0 += __shfl_xor_sync(0xffffffffu, l0, 2);
    l1 += __shfl_xor_sync(0xffffffffu, l1, 1);
    l1 += __shfl_xor_sync(0xffffffffu, l1, 2);
    float inv0 = 1.0f / l0, inv1 = 1.0f / l1;

    float vv[8][4];
    float max0 = 1e-30f, max1 = 1e-30f;
    #pragma unroll
    for (int j = 0; j < 8; j++) {
        vv[j][0] = acc[j][0] * inv0;
        vv[j][1] = acc[j][1] * inv0;
        vv[j][2] = acc[j][2] * inv1;
        vv[j][3] = acc[j][3] * inv1;
        max0 = fmaxf(max0, fmaxf(fabsf(vv[j][0]), fabsf(vv[j][1])));
        max1 = fmaxf(max1, fmaxf(fabsf(vv[j][2]), fabsf(vv[j][3])));
    }
    max0 = fmaxf(max0, __shfl_xor_sync(0xffffffffu, max0, 1));
    max0 = fmaxf(max0, __shfl_xor_sync(0xffffffffu, max0, 2));
    max1 = fmaxf(max1, __shfl_xor_sync(0xffffffffu, max1, 1));
    max1 = fmaxf(max1, __shfl_xor_sync(0xffffffffu, max1, 2));
    float s0 = max0 * (1.0f / 127.0f), is0 = 127.0f / max0;
    float s1 = max1 * (1.0f / 127.0f), is1 = 127.0f / max1;

    if ((lane & 3) == 0) {
        Sctx[(size_t)(b * SEQ + row0g) * NHEAD + h]     = s0;
        Sctx[(size_t)(b * SEQ + row0g + 8) * NHEAD + h] = s1;
    }

    size_t rb0 = (size_t)(b * SEQ + row0g) * 2048;
    size_t rb1 = rb0 + 8 * 2048;
    int dcol = h * DH + colbase;
    #pragma unroll
    for (int j = 0; j < 8; j++) {
        int d = dcol + 8 * j;
        int h0, lq0, h1, lq1, h2, lq2, h3, lq3;
        q2(vv[j][0], is0, h0, lq0);
        q2(vv[j][1], is0, h1, lq1);
        q2(vv[j][2], is1, h2, lq2);
        q2(vv[j][3], is1, h3, lq3);
        *(char2*)&C2[rb0 + d]        = make_char2((char)h0, (char)h1);
        *(char2*)&C2[rb0 + 1024 + d] = make_char2((char)lq0, (char)lq1);
        *(char2*)&C2[rb1 + d]        = make_char2((char)h2, (char)h3);
        *(char2*)&C2[rb1 + 1024 + d] = make_char2((char)lq2, (char)lq3);
    }
}

// ---------------------------------------------------------------------------
// Launch
// ---------------------------------------------------------------------------
extern "C" void kernel_launch(void* const* d_in, const int* in_sizes, int n_in,
                              void* d_out, int out_size)
{
    const float* x  = (const float*)d_in[0];
    const float* Wq = (const float*)d_in[1];
    const float* Wk = (const float*)d_in[2];
    const float* Wv = (const float*)d_in[3];
    const float* Wo = (const float*)d_in[4];
    float* out = (float*)d_out;

    int8_t *pA2, *pW2, *pWo2, *pC2;
    float *pSctx;
    __nv_bfloat16 *pQhi, *pQlo;
    cudaGetSymbolAddress((void**)&pA2, g_A2);
    cudaGetSymbolAddress((void**)&pW2, g_W2);
    cudaGetSymbolAddress((void**)&pWo2, g_Wo2);
    cudaGetSymbolAddress((void**)&pC2, g_C2);
    cudaGetSymbolAddress((void**)&pSctx, g_Sctx);
    cudaGetSymbolAddress((void**)&pQhi, g_Qhi);
    cudaGetSymbolAddress((void**)&pQlo, g_Qlo);

    // Weight transpose + quantize
    {
        dim3 blk(32, 8);
        transpose_quant8<<<dim3(32, 32), blk>>>(Wq, pW2, DM, 0, INV_SW);
        transpose_quant8<<<dim3(8, 32), blk>>>(Wk, pW2, 256, 1024, INV_SW);
        transpose_quant8<<<dim3(8, 32), blk>>>(Wv, pW2, 256, 1280, INV_SW);
        transpose_quant8<<<dim3(32, 32), blk>>>(Wo, pWo2, DM, 0, INV_SW);
    }

    // x -> int8 limbs
    quant8_rows<<<2048, 256>>>(x, pA2, MTOK, INV_SX);

    // QKV projection (int8 IMMA) -> bf16 hi/lo planes
    cudaFuncSetAttribute(imma_gemm<1>, cudaFuncAttributeMaxDynamicSharedMemorySize, IMMA_SMEM);
    cudaFuncSetAttribute(imma_gemm<0>, cudaFuncAttributeMaxDynamicSharedMemorySize, IMMA_SMEM);
    {
        dim3 g(NQKV / 64, MTOK / 128);
        imma_gemm<1><<<g, 256, IMMA_SMEM>>>(pA2, pW2, nullptr, nullptr, pQhi, pQlo,
                                            MTOK, NQKV, S_X * S_W);
    }

    // RoPE on planes
    {
        int total = MTOK * 20 * 32;
        rope_kernel<<<(total + 255) / 256, 256>>>(pQhi, pQlo);
    }

    // Flash attention -> int8 limb ctx + dynamic scales
    {
        cudaFuncSetAttribute(attn_mma,
                             cudaFuncAttributeMaxDynamicSharedMemorySize,
                             ATTN_SMEM);
        dim3 ga(SEQ / 128, NHEAD, BATCH);
        attn_mma<<<ga, 256, ATTN_SMEM>>>(pQhi, pQlo, pC2, pSctx);
    }

    // Output projection (int8 IMMA, per-(row,head) scales) -> fp32
    {
        dim3 g(DM / 64, MTOK / 128);
        imma_gemm<0><<<g, 256, IMMA_SMEM>>>(pC2, pWo2, pSctx, out, nullptr, nullptr,
                                            MTOK, DM, S_W);
    }
}

// round 8
// speedup vs baseline: 2.0198x; 2.0198x over previous
#include <cuda_runtime.h>
#include <cuda_fp16.h>
#include <math.h>
#include <cstdint>

#define NHEAD 16
#define NKV   4
#define DH    64
#define BATCH 2
#define SEQ   2048
#define MTOK  (BATCH*SEQ)     // 4096
#define DM    1024
#define NQKV  1536            // 1024(Q) + 256(K) + 256(V)
#define K2    2048            // stacked-K (hi | lo)

// ---------------------------------------------------------------------------
// Scratch (static device globals -- no allocation allowed)
// ---------------------------------------------------------------------------
__device__ __half g_x2[(size_t)MTOK * K2];       // x limbs [h|l]      16 MB
__device__ __half g_Wc2[(size_t)NQKV * K2];      // [Wq|Wk|Wv] dup      6 MB
__device__ __half g_Wo2[(size_t)DM * K2];        // Wo dup              4 MB
__device__ __half g_C2[(size_t)MTOK * K2];       // ctx limbs [h|l]    16 MB
__device__ __half g_Qhi[(size_t)MTOK * NQKV];    // QKV hi plane       12 MB
__device__ __half g_Qlo[(size_t)MTOK * NQKV];    // QKV lo plane       12 MB

// ---------------------------------------------------------------------------
// PTX helpers (portable sm_80-class)
// ---------------------------------------------------------------------------
__device__ __forceinline__ uint32_t smem_u32(const void* p) {
    return (uint32_t)__cvta_generic_to_shared(p);
}
__device__ __forceinline__ void cp_async16(uint32_t saddr, const void* gaddr) {
    asm volatile("cp.async.cg.shared.global [%0], [%1], 16;" :: "r"(saddr), "l"(gaddr));
}
__device__ __forceinline__ void cp_commit() {
    asm volatile("cp.async.commit_group;" ::: "memory");
}
template<int N>
__device__ __forceinline__ void cp_wait() {
    asm volatile("cp.async.wait_group %0;" :: "n"(N) : "memory");
}
__device__ __forceinline__ void ldmatrix_x4(uint32_t& r0, uint32_t& r1,
                                            uint32_t& r2, uint32_t& r3, uint32_t a) {
    asm volatile("ldmatrix.sync.aligned.m8n8.x4.shared.b16 {%0,%1,%2,%3}, [%4];"
                 : "=r"(r0), "=r"(r1), "=r"(r2), "=r"(r3) : "r"(a));
}
__device__ __forceinline__ void ldmatrix_x4_t(uint32_t& r0, uint32_t& r1,
                                              uint32_t& r2, uint32_t& r3, uint32_t a) {
    asm volatile("ldmatrix.sync.aligned.m8n8.x4.trans.shared.b16 {%0,%1,%2,%3}, [%4];"
                 : "=r"(r0), "=r"(r1), "=r"(r2), "=r"(r3) : "r"(a));
}
__device__ __forceinline__ void mma_f16(float* c, uint32_t a0, uint32_t a1,
                                        uint32_t a2, uint32_t a3,
                                        uint32_t b0, uint32_t b1) {
    asm volatile("mma.sync.aligned.m16n8k16.row.col.f32.f16.f16.f32 "
                 "{%0,%1,%2,%3}, {%4,%5,%6,%7}, {%8,%9}, {%0,%1,%2,%3};"
                 : "+f"(c[0]), "+f"(c[1]), "+f"(c[2]), "+f"(c[3])
                 : "r"(a0), "r"(a1), "r"(a2), "r"(a3), "r"(b0), "r"(b1));
}
__device__ __forceinline__ float ex2(float x) {
    float r; asm("ex2.approx.f32 %0, %1;" : "=f"(r) : "f"(x)); return r;
}
// pack two f32 -> f16x2 reg (lo = x, hi = y)
__device__ __forceinline__ uint32_t pack_h2(float x, float y) {
    __half2 t = __floats2half2_rn(x, y);
    return *reinterpret_cast<uint32_t*>(&t);
}
__device__ __forceinline__ float h2_lo(uint32_t p) {
    __half2 t = *reinterpret_cast<__half2*>(&p); return __low2float(t);
}
__device__ __forceinline__ float h2_hi(uint32_t p) {
    __half2 t = *reinterpret_cast<__half2*>(&p); return __high2float(t);
}

// ---------------------------------------------------------------------------
// Prep: split fp32 x rows -> stacked fp16 [h | l]
// ---------------------------------------------------------------------------
__global__ void split2_rows(const float* __restrict__ in, __half* __restrict__ out,
                            int M)
{
    int n = M * DM;
    for (int i = blockIdx.x * blockDim.x + threadIdx.x; i < n; i += gridDim.x * blockDim.x) {
        int m = i / DM, k = i % DM;
        float v = in[i];
        __half h = __float2half_rn(v);
        __half l = __float2half_rn(v - __half2float(h));
        out[(size_t)m * K2 + k]       = h;
        out[(size_t)m * K2 + DM + k]  = l;
    }
}

// W[1024, Ndim] row-major -> out[(rowoff+n)][w1 | w1] (duplicated fp16)
__global__ void transpose_dup(const float* __restrict__ W, __half* __restrict__ out,
                              int Ndim, int rowoff)
{
    __shared__ float t[32][33];
    int n0 = blockIdx.x * 32, k0 = blockIdx.y * 32;
    int tx = threadIdx.x, ty = threadIdx.y;
    #pragma unroll
    for (int i = 0; i < 32; i += 8)
        t[ty + i][tx] = W[(size_t)(k0 + ty + i) * Ndim + (n0 + tx)];
    __syncthreads();
    #pragma unroll
    for (int i = 0; i < 32; i += 8) {
        __half w1 = __float2half_rn(t[tx][ty + i]);
        size_t base = (size_t)(rowoff + n0 + ty + i) * K2 + (k0 + tx);
        out[base]      = w1;
        out[base + DM] = w1;
    }
}

// ---------------------------------------------------------------------------
// fp16 tensor-core GEMM, 3-stage cp.async: C[M,N] = A2[M,K2] @ B2[N,K2]^T
// OUT_MODE 0: fp32 C.  OUT_MODE 1: fp16 hi/lo planes.
// ---------------------------------------------------------------------------
#define BM 128
#define BN 128
#define BKK 32
#define LDS_ROW 40
#define GEMM_BUF (BM * LDS_ROW * 2)
#define GEMM_SMEM (6 * GEMM_BUF)           // 61440

template<int OUT_MODE>
__global__ __launch_bounds__(256, 2) void mma_gemm(
    const __half* __restrict__ A, const __half* __restrict__ B,
    float* __restrict__ C, __half* __restrict__ Chi,
    __half* __restrict__ Clo, int M, int N)
{
    extern __shared__ char gsm[];
    uint32_t sabase = smem_u32(gsm);
    const int Kg = K2;

    int tid = threadIdx.x;
    int lane = tid & 31;
    int wid = tid >> 5;
    int wm = wid & 3;
    int wn = wid >> 2;
    int m0 = blockIdx.y * BM;
    int n0 = blockIdx.x * BN;

    int r0 = (tid + 0)   >> 2, c0 = (tid + 0)   & 3;
    int r1 = (tid + 256) >> 2, c1 = (tid + 256) & 3;

    const __half* Ag = A + (size_t)m0 * Kg;
    const __half* Bg = B + (size_t)n0 * Kg;

    float acc[2][8][4];
    #pragma unroll
    for (int i = 0; i < 2; i++)
        #pragma unroll
        for (int j = 0; j < 8; j++)
            #pragma unroll
            for (int q = 0; q < 4; q++) acc[i][j][q] = 0.0f;

    const int nk = Kg / BKK;   // 64

    auto issue = [&](int kt, int s) {
        int kg = kt * BKK;
        uint32_t sa = sabase + s * GEMM_BUF;
        uint32_t sb = sabase + (3 + s) * GEMM_BUF;
        cp_async16(sa + (r0 * LDS_ROW + c0 * 8) * 2, Ag + (size_t)r0 * Kg + kg + c0 * 8);
        cp_async16(sa + (r1 * LDS_ROW + c1 * 8) * 2, Ag + (size_t)r1 * Kg + kg + c1 * 8);
        cp_async16(sb + (r0 * LDS_ROW + c0 * 8) * 2, Bg + (size_t)r0 * Kg + kg + c0 * 8);
        cp_async16(sb + (r1 * LDS_ROW + c1 * 8) * 2, Bg + (size_t)r1 * Kg + kg + c1 * 8);
        cp_commit();
    };

    issue(0, 0);
    issue(1, 1);

    int a_row = wm * 32 + (lane & 15);
    int a_colp = (lane >> 4) * 8;
    int b_row = wn * 64 + (lane & 7) + ((lane >> 4) << 3);
    int b_colp = ((lane >> 3) & 1) * 8;

    int buf = 0;
    for (int kt = 0; kt < nk; kt++) {
        if (kt + 2 < nk) { issue(kt + 2, (kt + 2) % 3); cp_wait<2>(); }
        else if (kt + 1 < nk) { cp_wait<1>(); }
        else { cp_wait<0>(); }
        __syncthreads();

        uint32_t sa = sabase + buf * GEMM_BUF;
        uint32_t sb = sabase + (3 + buf) * GEMM_BUF;
        #pragma unroll
        for (int k16 = 0; k16 < 2; k16++) {
            uint32_t af[2][4];
            #pragma unroll
            for (int mi = 0; mi < 2; mi++) {
                uint32_t addr = sa + (((a_row + mi * 16) * LDS_ROW) + k16 * 16 + a_colp) * 2;
                ldmatrix_x4(af[mi][0], af[mi][1], af[mi][2], af[mi][3], addr);
            }
            uint32_t bfr[4][4];
            #pragma unroll
            for (int ni2 = 0; ni2 < 4; ni2++) {
                uint32_t addr = sb + (((b_row + ni2 * 16) * LDS_ROW) + k16 * 16 + b_colp) * 2;
                ldmatrix_x4(bfr[ni2][0], bfr[ni2][1], bfr[ni2][2], bfr[ni2][3], addr);
            }
            #pragma unroll
            for (int mi = 0; mi < 2; mi++)
                #pragma unroll
                for (int ni = 0; ni < 8; ni++) {
                    uint32_t bb0 = bfr[ni >> 1][(ni & 1) * 2];
                    uint32_t bb1 = bfr[ni >> 1][(ni & 1) * 2 + 1];
                    mma_f16(acc[mi][ni], af[mi][0], af[mi][1], af[mi][2], af[mi][3], bb0, bb1);
                }
        }
        __syncthreads();
        buf = (buf + 1 == 3) ? 0 : buf + 1;
    }

    int cr = lane >> 2;
    int cc = (lane & 3) * 2;
    #pragma unroll
    for (int mi = 0; mi < 2; mi++) {
        #pragma unroll
        for (int ni = 0; ni < 8; ni++) {
            int row = m0 + wm * 32 + mi * 16 + cr;
            int col = n0 + wn * 64 + ni * 8 + cc;
            if (OUT_MODE == 0) {
                *(float2*)&C[(size_t)row * N + col] =
                    make_float2(acc[mi][ni][0], acc[mi][ni][1]);
                *(float2*)&C[(size_t)(row + 8) * N + col] =
                    make_float2(acc[mi][ni][2], acc[mi][ni][3]);
            } else {
                float v0 = acc[mi][ni][0], v1 = acc[mi][ni][1];
                float v2 = acc[mi][ni][2], v3 = acc[mi][ni][3];
                uint32_t h0 = pack_h2(v0, v1);
                uint32_t l0 = pack_h2(v0 - h2_lo(h0), v1 - h2_hi(h0));
                uint32_t h1 = pack_h2(v2, v3);
                uint32_t l1 = pack_h2(v2 - h2_lo(h1), v3 - h2_hi(h1));
                *(uint32_t*)&Chi[(size_t)row * N + col] = h0;
                *(uint32_t*)&Clo[(size_t)row * N + col] = l0;
                *(uint32_t*)&Chi[(size_t)(row + 8) * N + col] = h1;
                *(uint32_t*)&Clo[(size_t)(row + 8) * N + col] = l1;
            }
        }
    }
}

// ---------------------------------------------------------------------------
// RoPE in-place on fp16 hi/lo planes [MTOK, 1536]
// ---------------------------------------------------------------------------
__global__ void rope_kernel(__half* __restrict__ hi, __half* __restrict__ lo)
{
    const int tot = MTOK * 20 * 32;
    int idx = blockIdx.x * blockDim.x + threadIdx.x;
    if (idx >= tot) return;

    int i    = idx & 31;
    int hh   = (idx >> 5) % 20;
    int tok  = idx / (32 * 20);
    int s    = tok % SEQ;
    int col  = (hh < 16) ? hh * DH : 1024 + (hh - 16) * DH;
    size_t base = (size_t)tok * NQKV + col;

    float invf = exp10f(-(float)i * 0.125f);
    float ang  = (float)s * invf;
    float c = cosf(ang), sn = sinf(ang);

    float x0 = __half2float(hi[base + i])      + __half2float(lo[base + i]);
    float x1 = __half2float(hi[base + i + 32]) + __half2float(lo[base + i + 32]);
    float y0 = x0 * c - x1 * sn;
    float y1 = x1 * c + x0 * sn;

    __half h0 = __float2half_rn(y0);
    __half h1 = __float2half_rn(y1);
    hi[base + i]      = h0;
    lo[base + i]      = __float2half_rn(y0 - __half2float(h0));
    hi[base + i + 32] = h1;
    lo[base + i + 32] = __float2half_rn(y1 - __half2float(h1));
}

// ---------------------------------------------------------------------------
// fp16 tensor-core flash attention. Q hi/lo compensated, K hi-only,
// V hi/lo compensated. Double-buffered KV (Khi,Vhi,Vlo per stage).
// Writes ctx as stacked fp16 [h|l] into g_C2.
// ---------------------------------------------------------------------------
#define AROW 72
#define ROWB (AROW*2)          // 144 bytes per row
#define SQ_HI 0
#define SQ_LO (128*ROWB)       // 18432
#define SKV0  (2*128*ROWB)     // 36864
#define KVSTG (3*64*ROWB)      // 27648 per stage (Khi,Vhi,Vlo)
#define ATTN_SMEM (SKV0 + 2*KVSTG)   // 92160

__global__ __launch_bounds__(256) void attn_mma(
    const __half* __restrict__ Phi, const __half* __restrict__ Plo,
    __half* __restrict__ C2)
{
    extern __shared__ char smc[];
    uint32_t sb = smem_u32(smc);

    int qt = (int)gridDim.x - 1 - (int)blockIdx.x;
    int h  = blockIdx.y;
    int b  = blockIdx.z;
    int kh = h >> 2;

    int tid  = threadIdx.x;
    int lane = tid & 31;
    int wm   = tid >> 5;

    const int kcol = 1024 + kh * DH;
    const int vcol = 1280 + kh * DH;

    // --- issue Q tile (hi/lo) + KV tile 0 ---
    {
        #pragma unroll
        for (int it = 0; it < 8; it++) {
            int idx = tid + it * 256;
            int pl = idx >> 10;
            int j = idx & 1023;
            int r = j >> 3, c = j & 7;
            const __half* src = (pl ? Plo : Phi)
                + (size_t)(b * SEQ + qt * 128 + r) * NQKV + h * DH + c * 8;
            uint32_t dst = sb + (pl ? SQ_LO : SQ_HI) + r * ROWB + c * 16;
            cp_async16(dst, src);
        }
        #pragma unroll
        for (int it = 0; it < 6; it++) {
            int idx = tid + it * 256;        // 1536 chunks
            int sel = idx >> 9;              // 0 Khi, 1 Vhi, 2 Vlo
            int j = idx & 511;
            int r = j >> 3, c = j & 7;
            const __half* base = (sel == 2) ? Plo : Phi;
            int colb = (sel == 0) ? kcol : vcol;
            const __half* src = base + (size_t)(b * SEQ + r) * NQKV + colb + c * 8;
            uint32_t dst = sb + SKV0 + sel * (64 * ROWB) + r * ROWB + c * 16;
            cp_async16(dst, src);
        }
        cp_commit();
    }

    uint32_t qa_off = (uint32_t)((wm * 16 + (lane & 7) + ((lane >> 3) & 1) * 8) * ROWB
                                 + (lane >> 4) * 16);
    uint32_t kb_off = (uint32_t)(((lane & 7) + (lane >> 4) * 8) * ROWB
                                 + ((lane >> 3) & 1) * 16);
    uint32_t vb_off = (uint32_t)(((lane & 7) + ((lane >> 3) & 1) * 8) * ROWB
                                 + (lane >> 4) * 16);

    float acc[8][4];
    #pragma unroll
    for (int j = 0; j < 8; j++)
        #pragma unroll
        for (int q = 0; q < 4; q++) acc[j][q] = 0.0f;
    float m0 = -1e30f, m1 = -1e30f, l0 = 0.0f, l1 = 0.0f;

    const float SCL = 0.125f * 1.44269504f;
    int row0g = qt * 128 + wm * 16 + (lane >> 2);
    int colbase = 2 * (lane & 3);

    int nkt = 2 * qt + 2;
    for (int kt = 0; kt < nkt; kt++) {
        if (kt + 1 < nkt) {
            int stg = (kt + 1) & 1;
            #pragma unroll
            for (int it = 0; it < 6; it++) {
                int idx = tid + it * 256;
                int sel = idx >> 9;
                int j = idx & 511;
                int r = j >> 3, c = j & 7;
                const __half* base = (sel == 2) ? Plo : Phi;
                int colb = (sel == 0) ? kcol : vcol;
                const __half* src = base
                    + (size_t)(b * SEQ + (kt + 1) * 64 + r) * NQKV + colb + c * 8;
                uint32_t dst = sb + SKV0 + stg * KVSTG + sel * (64 * ROWB) + r * ROWB + c * 16;
                cp_async16(dst, src);
            }
            cp_commit();
            cp_wait<1>();
        } else {
            cp_wait<0>();
        }
        __syncthreads();

        uint32_t kvb = sb + SKV0 + (kt & 1) * KVSTG;
        uint32_t skh = kvb;
        uint32_t svh = kvb + 64 * ROWB;
        uint32_t svl = kvb + 2 * 64 * ROWB;

        // --- S = Q K^T  ((qh + ql) * kh : 4 mmas per (t,jj)) ---
        float sf[8][4];
        #pragma unroll
        for (int j = 0; j < 8; j++)
            #pragma unroll
            for (int q = 0; q < 4; q++) sf[j][q] = 0.0f;

        #pragma unroll
        for (int t = 0; t < 4; t++) {
            uint32_t qh[4], ql[4];
            ldmatrix_x4(qh[0], qh[1], qh[2], qh[3], sb + SQ_HI + qa_off + t * 32);
            ldmatrix_x4(ql[0], ql[1], ql[2], ql[3], sb + SQ_LO + qa_off + t * 32);
            #pragma unroll
            for (int jj = 0; jj < 4; jj++) {
                uint32_t kmh[4];
                uint32_t off = kb_off + jj * 16 * ROWB + t * 32;
                ldmatrix_x4(kmh[0], kmh[1], kmh[2], kmh[3], skh + off);
                mma_f16(sf[2*jj],   qh[0], qh[1], qh[2], qh[3], kmh[0], kmh[1]);
                mma_f16(sf[2*jj],   ql[0], ql[1], ql[2], ql[3], kmh[0], kmh[1]);
                mma_f16(sf[2*jj+1], qh[0], qh[1], qh[2], qh[3], kmh[2], kmh[3]);
                mma_f16(sf[2*jj+1], ql[0], ql[1], ql[2], ql[3], kmh[2], kmh[3]);
            }
        }

        // --- scale + causal mask ---
        bool need_mask = (kt * 64 + 63 > qt * 128 + wm * 16);
        if (need_mask) {
            #pragma unroll
            for (int j = 0; j < 8; j++) {
                int c0 = kt * 64 + 8 * j + colbase;
                sf[j][0] = (c0     <= row0g)     ? sf[j][0] * SCL : -1e30f;
                sf[j][1] = (c0 + 1 <= row0g)     ? sf[j][1] * SCL : -1e30f;
                sf[j][2] = (c0     <= row0g + 8) ? sf[j][2] * SCL : -1e30f;
                sf[j][3] = (c0 + 1 <= row0g + 8) ? sf[j][3] * SCL : -1e30f;
            }
        } else {
            #pragma unroll
            for (int j = 0; j < 8; j++)
                #pragma unroll
                for (int q = 0; q < 4; q++) sf[j][q] *= SCL;
        }

        // --- online softmax ---
        float mx0 = m0, mx1 = m1;
        #pragma unroll
        for (int j = 0; j < 8; j++) {
            mx0 = fmaxf(mx0, fmaxf(sf[j][0], sf[j][1]));
            mx1 = fmaxf(mx1, fmaxf(sf[j][2], sf[j][3]));
        }
        mx0 = fmaxf(mx0, __shfl_xor_sync(0xffffffffu, mx0, 1));
        mx0 = fmaxf(mx0, __shfl_xor_sync(0xffffffffu, mx0, 2));
        mx1 = fmaxf(mx1, __shfl_xor_sync(0xffffffffu, mx1, 1));
        mx1 = fmaxf(mx1, __shfl_xor_sync(0xffffffffu, mx1, 2));
        float corr0 = ex2(m0 - mx0);
        float corr1 = ex2(m1 - mx1);
        m0 = mx0; m1 = mx1;

        float ls0 = 0.0f, ls1 = 0.0f;
        #pragma unroll
        for (int j = 0; j < 8; j++) {
            sf[j][0] = ex2(sf[j][0] - mx0);
            sf[j][1] = ex2(sf[j][1] - mx0);
            sf[j][2] = ex2(sf[j][2] - mx1);
            sf[j][3] = ex2(sf[j][3] - mx1);
            ls0 += sf[j][0] + sf[j][1];
            ls1 += sf[j][2] + sf[j][3];
        }
        l0 = l0 * corr0 + ls0;
        l1 = l1 * corr1 + ls1;
        #pragma unroll
        for (int j = 0; j < 8; j++) {
            acc[j][0] *= corr0; acc[j][1] *= corr0;
            acc[j][2] *= corr1; acc[j][3] *= corr1;
        }

        // --- PV ((ph + pl) * vh + ph * vl : 6 mmas per (t,jj)) ---
        #pragma unroll
        for (int t = 0; t < 4; t++) {
            uint32_t aph[4], apl[4];
            {
                float p00 = sf[2*t][0],   p01 = sf[2*t][1];
                float p10 = sf[2*t][2],   p11 = sf[2*t][3];
                float p20 = sf[2*t+1][0], p21 = sf[2*t+1][1];
                float p30 = sf[2*t+1][2], p31 = sf[2*t+1][3];
                aph[0] = pack_h2(p00, p01);
                aph[1] = pack_h2(p10, p11);
                aph[2] = pack_h2(p20, p21);
                aph[3] = pack_h2(p30, p31);
                apl[0] = pack_h2(p00 - h2_lo(aph[0]), p01 - h2_hi(aph[0]));
                apl[1] = pack_h2(p10 - h2_lo(aph[1]), p11 - h2_hi(aph[1]));
                apl[2] = pack_h2(p20 - h2_lo(aph[2]), p21 - h2_hi(aph[2]));
                apl[3] = pack_h2(p30 - h2_lo(aph[3]), p31 - h2_hi(aph[3]));
            }
            #pragma unroll
            for (int jj = 0; jj < 4; jj++) {
                uint32_t vh[4], vl[4];
                uint32_t off = vb_off + t * 16 * ROWB + jj * 32;
                ldmatrix_x4_t(vh[0], vh[1], vh[2], vh[3], svh + off);
                ldmatrix_x4_t(vl[0], vl[1], vl[2], vl[3], svl + off);
                mma_f16(acc[2*jj],   aph[0], aph[1], aph[2], aph[3], vh[0], vh[1]);
                mma_f16(acc[2*jj],   apl[0], apl[1], apl[2], apl[3], vh[0], vh[1]);
                mma_f16(acc[2*jj],   aph[0], aph[1], aph[2], aph[3], vl[0], vl[1]);
                mma_f16(acc[2*jj+1], aph[0], aph[1], aph[2], aph[3], vh[2], vh[3]);
                mma_f16(acc[2*jj+1], apl[0], apl[1], apl[2], apl[3], vh[2], vh[3]);
                mma_f16(acc[2*jj+1], aph[0], aph[1], aph[2], aph[3], vl[2], vl[3]);
            }
        }
        __syncthreads();
    }

    // --- final normalize + write stacked [h|l] ctx into C2 ---
    l0 += __shfl_xor_sync(0xffffffffu, l0, 1);
    l0 += __shfl_xor_sync(0xffffffffu, l0, 2);
    l1 += __shfl_xor_sync(0xffffffffu, l1, 1);
    l1 += __shfl_xor_sync(0xffffffffu, l1, 2);
    float inv0 = 1.0f / l0, inv1 = 1.0f / l1;

    size_t rb0 = (size_t)(b * SEQ + row0g) * K2;
    size_t rb1 = rb0 + 8 * K2;
    int dcol = h * DH + colbase;
    #pragma unroll
    for (int j = 0; j < 8; j++) {
        int d = dcol + 8 * j;
        float v0 = acc[j][0] * inv0, v1 = acc[j][1] * inv0;
        float v2 = acc[j][2] * inv1, v3 = acc[j][3] * inv1;
        uint32_t h0 = pack_h2(v0, v1);
        uint32_t lo0 = pack_h2(v0 - h2_lo(h0), v1 - h2_hi(h0));
        uint32_t h1 = pack_h2(v2, v3);
        uint32_t lo1 = pack_h2(v2 - h2_lo(h1), v3 - h2_hi(h1));
        *(uint32_t*)&C2[rb0 + d]        = h0;
        *(uint32_t*)&C2[rb0 + DM + d]   = lo0;
        *(uint32_t*)&C2[rb1 + d]        = h1;
        *(uint32_t*)&C2[rb1 + DM + d]   = lo1;
    }
}

// ---------------------------------------------------------------------------
// Launch
// ---------------------------------------------------------------------------
extern "C" void kernel_launch(void* const* d_in, const int* in_sizes, int n_in,
                              void* d_out, int out_size)
{
    const float* x  = (const float*)d_in[0];
    const float* Wq = (const float*)d_in[1];
    const float* Wk = (const float*)d_in[2];
    const float* Wv = (const float*)d_in[3];
    const float* Wo = (const float*)d_in[4];
    float* out = (float*)d_out;

    __half *px2, *pWc2, *pWo2, *pC2, *pQhi, *pQlo;
    cudaGetSymbolAddress((void**)&px2, g_x2);
    cudaGetSymbolAddress((void**)&pWc2, g_Wc2);
    cudaGetSymbolAddress((void**)&pWo2, g_Wo2);
    cudaGetSymbolAddress((void**)&pC2, g_C2);
    cudaGetSymbolAddress((void**)&pQhi, g_Qhi);
    cudaGetSymbolAddress((void**)&pQlo, g_Qlo);

    // Weight transpose + fp16 dup
    {
        dim3 blk(32, 8);
        transpose_dup<<<dim3(32, 32), blk>>>(Wq, pWc2, DM, 0);
        transpose_dup<<<dim3(8, 32), blk>>>(Wk, pWc2, 256, 1024);
        transpose_dup<<<dim3(8, 32), blk>>>(Wv, pWc2, 256, 1280);
        transpose_dup<<<dim3(32, 32), blk>>>(Wo, pWo2, DM, 0);
    }

    // x -> stacked fp16 [h|l]
    split2_rows<<<2048, 256>>>(x, px2, MTOK);

    // QKV projection GEMM -> fp16 hi/lo planes
    cudaFuncSetAttribute(mma_gemm<1>, cudaFuncAttributeMaxDynamicSharedMemorySize, GEMM_SMEM);
    cudaFuncSetAttribute(mma_gemm<0>, cudaFuncAttributeMaxDynamicSharedMemorySize, GEMM_SMEM);
    {
        dim3 g(NQKV / BN, MTOK / BM);
        mma_gemm<1><<<g, 256, GEMM_SMEM>>>(px2, pWc2, nullptr, pQhi, pQlo, MTOK, NQKV);
    }

    // RoPE on planes
    {
        int total = MTOK * 20 * 32;
        rope_kernel<<<(total + 255) / 256, 256>>>(pQhi, pQlo);
    }

    // Flash attention -> stacked fp16 ctx
    {
        cudaFuncSetAttribute(attn_mma,
                             cudaFuncAttributeMaxDynamicSharedMemorySize,
                             ATTN_SMEM);
        dim3 ga(SEQ / 128, NHEAD, BATCH);
        attn_mma<<<ga, 256, ATTN_SMEM>>>(pQhi, pQlo, pC2);
    }

    // Output projection GEMM -> fp32 out
    {
        dim3 g(DM / BN, MTOK / BM);
        mma_gemm<0><<<g, 256, GEMM_SMEM>>>(pC2, pWo2, out, nullptr, nullptr, MTOK, DM);
    }
}

// round 9
// speedup vs baseline: 2.5225x; 1.2489x over previous
#include <cuda_runtime.h>
#include <cuda_fp16.h>
#include <math.h>
#include <cstdint>

#define NHEAD 16
#define NKV   4
#define DH    64
#define BATCH 2
#define SEQ   2048
#define MTOK  (BATCH*SEQ)     // 4096
#define DM    1024
#define NQKV  1536            // 1024(Q) + 256(K) + 256(V)
#define K2    2048            // stacked-K (hi | lo) for x

// ---------------------------------------------------------------------------
// Scratch (static device globals -- no allocation allowed)
// ---------------------------------------------------------------------------
__device__ __half g_x2[(size_t)MTOK * K2];       // x limbs [h|l]      16 MB
__device__ __half g_Wc2[(size_t)NQKV * K2];      // [Wq|Wk|Wv] dup      6 MB
__device__ __half g_Wot[(size_t)DM * DM];        // Wo^T single         2 MB
__device__ __half g_Ch[(size_t)MTOK * DM];       // ctx hi plane        8 MB
__device__ __half g_Qhi[(size_t)MTOK * NQKV];    // QKV hi plane       12 MB
__device__ __half g_Qlo[(size_t)MTOK * NQKV];    // QKV lo plane       12 MB

// ---------------------------------------------------------------------------
// PTX helpers (portable sm_80-class)
// ---------------------------------------------------------------------------
__device__ __forceinline__ uint32_t smem_u32(const void* p) {
    return (uint32_t)__cvta_generic_to_shared(p);
}
__device__ __forceinline__ void cp_async16(uint32_t saddr, const void* gaddr) {
    asm volatile("cp.async.cg.shared.global [%0], [%1], 16;" :: "r"(saddr), "l"(gaddr));
}
__device__ __forceinline__ void cp_commit() {
    asm volatile("cp.async.commit_group;" ::: "memory");
}
template<int N>
__device__ __forceinline__ void cp_wait() {
    asm volatile("cp.async.wait_group %0;" :: "n"(N) : "memory");
}
__device__ __forceinline__ void ldmatrix_x4(uint32_t& r0, uint32_t& r1,
                                            uint32_t& r2, uint32_t& r3, uint32_t a) {
    asm volatile("ldmatrix.sync.aligned.m8n8.x4.shared.b16 {%0,%1,%2,%3}, [%4];"
                 : "=r"(r0), "=r"(r1), "=r"(r2), "=r"(r3) : "r"(a));
}
__device__ __forceinline__ void ldmatrix_x4_t(uint32_t& r0, uint32_t& r1,
                                              uint32_t& r2, uint32_t& r3, uint32_t a) {
    asm volatile("ldmatrix.sync.aligned.m8n8.x4.trans.shared.b16 {%0,%1,%2,%3}, [%4];"
                 : "=r"(r0), "=r"(r1), "=r"(r2), "=r"(r3) : "r"(a));
}
__device__ __forceinline__ void mma_f16(float* c, uint32_t a0, uint32_t a1,
                                        uint32_t a2, uint32_t a3,
                                        uint32_t b0, uint32_t b1) {
    asm volatile("mma.sync.aligned.m16n8k16.row.col.f32.f16.f16.f32 "
                 "{%0,%1,%2,%3}, {%4,%5,%6,%7}, {%8,%9}, {%0,%1,%2,%3};"
                 : "+f"(c[0]), "+f"(c[1]), "+f"(c[2]), "+f"(c[3])
                 : "r"(a0), "r"(a1), "r"(a2), "r"(a3), "r"(b0), "r"(b1));
}
__device__ __forceinline__ float ex2(float x) {
    float r; asm("ex2.approx.f32 %0, %1;" : "=f"(r) : "f"(x)); return r;
}
__device__ __forceinline__ uint32_t pack_h2(float x, float y) {
    __half2 t = __floats2half2_rn(x, y);
    return *reinterpret_cast<uint32_t*>(&t);
}
__device__ __forceinline__ float h2_lo(uint32_t p) {
    __half2 t = *reinterpret_cast<__half2*>(&p); return __low2float(t);
}
__device__ __forceinline__ float h2_hi(uint32_t p) {
    __half2 t = *reinterpret_cast<__half2*>(&p); return __high2float(t);
}

// ---------------------------------------------------------------------------
// Prep: split fp32 x rows -> stacked fp16 [h | l]
// ---------------------------------------------------------------------------
__global__ void split2_rows(const float* __restrict__ in, __half* __restrict__ out,
                            int M)
{
    int n = M * DM;
    for (int i = blockIdx.x * blockDim.x + threadIdx.x; i < n; i += gridDim.x * blockDim.x) {
        int m = i / DM, k = i % DM;
        float v = in[i];
        __half h = __float2half_rn(v);
        __half l = __float2half_rn(v - __half2float(h));
        out[(size_t)m * K2 + k]       = h;
        out[(size_t)m * K2 + DM + k]  = l;
    }
}

// W[1024, Ndim] row-major -> out[(rowoff+n)*ldout + k] fp16; dup: second copy at +DM
__global__ void transpose_h(const float* __restrict__ W, __half* __restrict__ out,
                            int Ndim, int rowoff, int ldout, int dup)
{
    __shared__ float t[32][33];
    int n0 = blockIdx.x * 32, k0 = blockIdx.y * 32;
    int tx = threadIdx.x, ty = threadIdx.y;
    #pragma unroll
    for (int i = 0; i < 32; i += 8)
        t[ty + i][tx] = W[(size_t)(k0 + ty + i) * Ndim + (n0 + tx)];
    __syncthreads();
    #pragma unroll
    for (int i = 0; i < 32; i += 8) {
        __half w1 = __float2half_rn(t[tx][ty + i]);
        size_t base = (size_t)(rowoff + n0 + ty + i) * ldout + (k0 + tx);
        out[base] = w1;
        if (dup) out[base + DM] = w1;
    }
}

// ---------------------------------------------------------------------------
// fp16 tensor-core GEMM, 3-stage cp.async: C[M,N] = A[M,Kg] @ B[N,Kg]^T
// OUT_MODE 0: fp32 C.  OUT_MODE 1: fp16 hi/lo planes.
// ---------------------------------------------------------------------------
#define BM 128
#define BN 128
#define BKK 32
#define LDS_ROW 40
#define GEMM_BUF (BM * LDS_ROW * 2)
#define GEMM_SMEM (6 * GEMM_BUF)           // 61440

template<int OUT_MODE>
__global__ __launch_bounds__(256, 2) void mma_gemm(
    const __half* __restrict__ A, const __half* __restrict__ B,
    float* __restrict__ C, __half* __restrict__ Chi,
    __half* __restrict__ Clo, int M, int N, int Kg)
{
    extern __shared__ char gsm[];
    uint32_t sabase = smem_u32(gsm);

    int tid = threadIdx.x;
    int lane = tid & 31;
    int wid = tid >> 5;
    int wm = wid & 3;
    int wn = wid >> 2;
    int m0 = blockIdx.y * BM;
    int n0 = blockIdx.x * BN;

    int r0 = (tid + 0)   >> 2, c0 = (tid + 0)   & 3;
    int r1 = (tid + 256) >> 2, c1 = (tid + 256) & 3;

    const __half* Ag = A + (size_t)m0 * Kg;
    const __half* Bg = B + (size_t)n0 * Kg;

    float acc[2][8][4];
    #pragma unroll
    for (int i = 0; i < 2; i++)
        #pragma unroll
        for (int j = 0; j < 8; j++)
            #pragma unroll
            for (int q = 0; q < 4; q++) acc[i][j][q] = 0.0f;

    const int nk = Kg / BKK;

    auto issue = [&](int kt, int s) {
        int kg = kt * BKK;
        uint32_t sa = sabase + s * GEMM_BUF;
        uint32_t sb = sabase + (3 + s) * GEMM_BUF;
        cp_async16(sa + (r0 * LDS_ROW + c0 * 8) * 2, Ag + (size_t)r0 * Kg + kg + c0 * 8);
        cp_async16(sa + (r1 * LDS_ROW + c1 * 8) * 2, Ag + (size_t)r1 * Kg + kg + c1 * 8);
        cp_async16(sb + (r0 * LDS_ROW + c0 * 8) * 2, Bg + (size_t)r0 * Kg + kg + c0 * 8);
        cp_async16(sb + (r1 * LDS_ROW + c1 * 8) * 2, Bg + (size_t)r1 * Kg + kg + c1 * 8);
        cp_commit();
    };

    issue(0, 0);
    issue(1, 1);

    int a_row = wm * 32 + (lane & 15);
    int a_colp = (lane >> 4) * 8;
    int b_row = wn * 64 + (lane & 7) + ((lane >> 4) << 3);
    int b_colp = ((lane >> 3) & 1) * 8;

    int buf = 0;
    for (int kt = 0; kt < nk; kt++) {
        if (kt + 2 < nk) { issue(kt + 2, (kt + 2) % 3); cp_wait<2>(); }
        else if (kt + 1 < nk) { cp_wait<1>(); }
        else { cp_wait<0>(); }
        __syncthreads();

        uint32_t sa = sabase + buf * GEMM_BUF;
        uint32_t sb = sabase + (3 + buf) * GEMM_BUF;
        #pragma unroll
        for (int k16 = 0; k16 < 2; k16++) {
            uint32_t af[2][4];
            #pragma unroll
            for (int mi = 0; mi < 2; mi++) {
                uint32_t addr = sa + (((a_row + mi * 16) * LDS_ROW) + k16 * 16 + a_colp) * 2;
                ldmatrix_x4(af[mi][0], af[mi][1], af[mi][2], af[mi][3], addr);
            }
            uint32_t bfr[4][4];
            #pragma unroll
            for (int ni2 = 0; ni2 < 4; ni2++) {
                uint32_t addr = sb + (((b_row + ni2 * 16) * LDS_ROW) + k16 * 16 + b_colp) * 2;
                ldmatrix_x4(bfr[ni2][0], bfr[ni2][1], bfr[ni2][2], bfr[ni2][3], addr);
            }
            #pragma unroll
            for (int mi = 0; mi < 2; mi++)
                #pragma unroll
                for (int ni = 0; ni < 8; ni++) {
                    uint32_t bb0 = bfr[ni >> 1][(ni & 1) * 2];
                    uint32_t bb1 = bfr[ni >> 1][(ni & 1) * 2 + 1];
                    mma_f16(acc[mi][ni], af[mi][0], af[mi][1], af[mi][2], af[mi][3], bb0, bb1);
                }
        }
        __syncthreads();
        buf = (buf + 1 == 3) ? 0 : buf + 1;
    }

    int cr = lane >> 2;
    int cc = (lane & 3) * 2;
    #pragma unroll
    for (int mi = 0; mi < 2; mi++) {
        #pragma unroll
        for (int ni = 0; ni < 8; ni++) {
            int row = m0 + wm * 32 + mi * 16 + cr;
            int col = n0 + wn * 64 + ni * 8 + cc;
            if (OUT_MODE == 0) {
                *(float2*)&C[(size_t)row * N + col] =
                    make_float2(acc[mi][ni][0], acc[mi][ni][1]);
                *(float2*)&C[(size_t)(row + 8) * N + col] =
                    make_float2(acc[mi][ni][2], acc[mi][ni][3]);
            } else {
                float v0 = acc[mi][ni][0], v1 = acc[mi][ni][1];
                float v2 = acc[mi][ni][2], v3 = acc[mi][ni][3];
                uint32_t h0 = pack_h2(v0, v1);
                uint32_t l0 = pack_h2(v0 - h2_lo(h0), v1 - h2_hi(h0));
                uint32_t h1 = pack_h2(v2, v3);
                uint32_t l1 = pack_h2(v2 - h2_lo(h1), v3 - h2_hi(h1));
                *(uint32_t*)&Chi[(size_t)row * N + col] = h0;
                *(uint32_t*)&Clo[(size_t)row * N + col] = l0;
                *(uint32_t*)&Chi[(size_t)(row + 8) * N + col] = h1;
                *(uint32_t*)&Clo[(size_t)(row + 8) * N + col] = l1;
            }
        }
    }
}

// ---------------------------------------------------------------------------
// RoPE on fp16 planes [MTOK, 1536]: reads hi+lo (full precision), writes hi
// only (Q/K lo planes are dead downstream).
// ---------------------------------------------------------------------------
__global__ void rope_kernel(__half* __restrict__ hi, const __half* __restrict__ lo)
{
    const int tot = MTOK * 20 * 32;
    int idx = blockIdx.x * blockDim.x + threadIdx.x;
    if (idx >= tot) return;

    int i    = idx & 31;
    int hh   = (idx >> 5) % 20;
    int tok  = idx / (32 * 20);
    int s    = tok % SEQ;
    int col  = (hh < 16) ? hh * DH : 1024 + (hh - 16) * DH;
    size_t base = (size_t)tok * NQKV + col;

    float invf = exp10f(-(float)i * 0.125f);
    float ang  = (float)s * invf;
    float c = cosf(ang), sn = sinf(ang);

    float x0 = __half2float(hi[base + i])      + __half2float(lo[base + i]);
    float x1 = __half2float(hi[base + i + 32]) + __half2float(lo[base + i + 32]);
    hi[base + i]      = __float2half_rn(x0 * c - x1 * sn);
    hi[base + i + 32] = __float2half_rn(x1 * c + x0 * sn);
}

// ---------------------------------------------------------------------------
// fp16 tensor-core flash attention. Q single, K single, V hi/lo compensated.
// Double-buffered KV (Khi,Vhi,Vlo per stage). Writes ctx hi plane into g_Ch.
// ---------------------------------------------------------------------------
#define AROW 72
#define ROWB (AROW*2)          // 144 bytes per row
#define SQ_HI 0
#define SKV0  (128*ROWB)       // 18432
#define KVSTG (3*64*ROWB)      // 27648 per stage (Khi,Vhi,Vlo)
#define ATTN_SMEM (SKV0 + 2*KVSTG)   // 73728

__global__ __launch_bounds__(256) void attn_mma(
    const __half* __restrict__ Phi, const __half* __restrict__ Plo,
    __half* __restrict__ Ch)
{
    extern __shared__ char smc[];
    uint32_t sb = smem_u32(smc);

    int qt = (int)gridDim.x - 1 - (int)blockIdx.x;
    int h  = blockIdx.y;
    int b  = blockIdx.z;
    int kh = h >> 2;

    int tid  = threadIdx.x;
    int lane = tid & 31;
    int wm   = tid >> 5;

    const int kcol = 1024 + kh * DH;
    const int vcol = 1280 + kh * DH;

    // --- issue Q tile (hi only) + KV tile 0 ---
    {
        #pragma unroll
        for (int it = 0; it < 4; it++) {
            int idx = tid + it * 256;        // 1024 chunks
            int r = idx >> 3, c = idx & 7;
            const __half* src = Phi
                + (size_t)(b * SEQ + qt * 128 + r) * NQKV + h * DH + c * 8;
            cp_async16(sb + SQ_HI + r * ROWB + c * 16, src);
        }
        #pragma unroll
        for (int it = 0; it < 6; it++) {
            int idx = tid + it * 256;        // 1536 chunks
            int sel = idx >> 9;              // 0 Khi, 1 Vhi, 2 Vlo
            int j = idx & 511;
            int r = j >> 3, c = j & 7;
            const __half* base = (sel == 2) ? Plo : Phi;
            int colb = (sel == 0) ? kcol : vcol;
            const __half* src = base + (size_t)(b * SEQ + r) * NQKV + colb + c * 8;
            uint32_t dst = sb + SKV0 + sel * (64 * ROWB) + r * ROWB + c * 16;
            cp_async16(dst, src);
        }
        cp_commit();
    }

    uint32_t qa_off = (uint32_t)((wm * 16 + (lane & 7) + ((lane >> 3) & 1) * 8) * ROWB
                                 + (lane >> 4) * 16);
    uint32_t kb_off = (uint32_t)(((lane & 7) + (lane >> 4) * 8) * ROWB
                                 + ((lane >> 3) & 1) * 16);
    uint32_t vb_off = (uint32_t)(((lane & 7) + ((lane >> 3) & 1) * 8) * ROWB
                                 + (lane >> 4) * 16);

    float acc[8][4];
    #pragma unroll
    for (int j = 0; j < 8; j++)
        #pragma unroll
        for (int q = 0; q < 4; q++) acc[j][q] = 0.0f;
    float m0 = -1e30f, m1 = -1e30f, l0 = 0.0f, l1 = 0.0f;

    const float SCL = 0.125f * 1.44269504f;
    int row0g = qt * 128 + wm * 16 + (lane >> 2);
    int colbase = 2 * (lane & 3);

    int nkt = 2 * qt + 2;
    for (int kt = 0; kt < nkt; kt++) {
        if (kt + 1 < nkt) {
            int stg = (kt + 1) & 1;
            #pragma unroll
            for (int it = 0; it < 6; it++) {
                int idx = tid + it * 256;
                int sel = idx >> 9;
                int j = idx & 511;
                int r = j >> 3, c = j & 7;
                const __half* base = (sel == 2) ? Plo : Phi;
                int colb = (sel == 0) ? kcol : vcol;
                const __half* src = base
                    + (size_t)(b * SEQ + (kt + 1) * 64 + r) * NQKV + colb + c * 8;
                uint32_t dst = sb + SKV0 + stg * KVSTG + sel * (64 * ROWB) + r * ROWB + c * 16;
                cp_async16(dst, src);
            }
            cp_commit();
            cp_wait<1>();
        } else {
            cp_wait<0>();
        }
        __syncthreads();

        uint32_t kvb = sb + SKV0 + (kt & 1) * KVSTG;
        uint32_t skh = kvb;
        uint32_t svh = kvb + 64 * ROWB;
        uint32_t svl = kvb + 2 * 64 * ROWB;

        // --- S = Q K^T  (single x single : 2 mmas per (t,jj)) ---
        float sf[8][4];
        #pragma unroll
        for (int j = 0; j < 8; j++)
            #pragma unroll
            for (int q = 0; q < 4; q++) sf[j][q] = 0.0f;

        #pragma unroll
        for (int t = 0; t < 4; t++) {
            uint32_t qh[4];
            ldmatrix_x4(qh[0], qh[1], qh[2], qh[3], sb + SQ_HI + qa_off + t * 32);
            #pragma unroll
            for (int jj = 0; jj < 4; jj++) {
                uint32_t kmh[4];
                uint32_t off = kb_off + jj * 16 * ROWB + t * 32;
                ldmatrix_x4(kmh[0], kmh[1], kmh[2], kmh[3], skh + off);
                mma_f16(sf[2*jj],   qh[0], qh[1], qh[2], qh[3], kmh[0], kmh[1]);
                mma_f16(sf[2*jj+1], qh[0], qh[1], qh[2], qh[3], kmh[2], kmh[3]);
            }
        }

        // --- scale + causal mask ---
        bool need_mask = (kt * 64 + 63 > qt * 128 + wm * 16);
        if (need_mask) {
            #pragma unroll
            for (int j = 0; j < 8; j++) {
                int c0 = kt * 64 + 8 * j + colbase;
                sf[j][0] = (c0     <= row0g)     ? sf[j][0] * SCL : -1e30f;
                sf[j][1] = (c0 + 1 <= row0g)     ? sf[j][1] * SCL : -1e30f;
                sf[j][2] = (c0     <= row0g + 8) ? sf[j][2] * SCL : -1e30f;
                sf[j][3] = (c0 + 1 <= row0g + 8) ? sf[j][3] * SCL : -1e30f;
            }
        } else {
            #pragma unroll
            for (int j = 0; j < 8; j++)
                #pragma unroll
                for (int q = 0; q < 4; q++) sf[j][q] *= SCL;
        }

        // --- online softmax ---
        float mx0 = m0, mx1 = m1;
        #pragma unroll
        for (int j = 0; j < 8; j++) {
            mx0 = fmaxf(mx0, fmaxf(sf[j][0], sf[j][1]));
            mx1 = fmaxf(mx1, fmaxf(sf[j][2], sf[j][3]));
        }
        mx0 = fmaxf(mx0, __shfl_xor_sync(0xffffffffu, mx0, 1));
        mx0 = fmaxf(mx0, __shfl_xor_sync(0xffffffffu, mx0, 2));
        mx1 = fmaxf(mx1, __shfl_xor_sync(0xffffffffu, mx1, 1));
        mx1 = fmaxf(mx1, __shfl_xor_sync(0xffffffffu, mx1, 2));
        float corr0 = ex2(m0 - mx0);
        float corr1 = ex2(m1 - mx1);
        m0 = mx0; m1 = mx1;

        float ls0 = 0.0f, ls1 = 0.0f;
        #pragma unroll
        for (int j = 0; j < 8; j++) {
            sf[j][0] = ex2(sf[j][0] - mx0);
            sf[j][1] = ex2(sf[j][1] - mx0);
            sf[j][2] = ex2(sf[j][2] - mx1);
            sf[j][3] = ex2(sf[j][3] - mx1);
            ls0 += sf[j][0] + sf[j][1];
            ls1 += sf[j][2] + sf[j][3];
        }
        l0 = l0 * corr0 + ls0;
        l1 = l1 * corr1 + ls1;
        #pragma unroll
        for (int j = 0; j < 8; j++) {
            acc[j][0] *= corr0; acc[j][1] *= corr0;
            acc[j][2] *= corr1; acc[j][3] *= corr1;
        }

        // --- PV (ph * (vh + vl) : 4 mmas per (t,jj)) ---
        #pragma unroll
        for (int t = 0; t < 4; t++) {
            uint32_t aph[4];
            aph[0] = pack_h2(sf[2*t][0],   sf[2*t][1]);
            aph[1] = pack_h2(sf[2*t][2],   sf[2*t][3]);
            aph[2] = pack_h2(sf[2*t+1][0], sf[2*t+1][1]);
            aph[3] = pack_h2(sf[2*t+1][2], sf[2*t+1][3]);
            #pragma unroll
            for (int jj = 0; jj < 4; jj++) {
                uint32_t vh[4], vl[4];
                uint32_t off = vb_off + t * 16 * ROWB + jj * 32;
                ldmatrix_x4_t(vh[0], vh[1], vh[2], vh[3], svh + off);
                ldmatrix_x4_t(vl[0], vl[1], vl[2], vl[3], svl + off);
                mma_f16(acc[2*jj],   aph[0], aph[1], aph[2], aph[3], vh[0], vh[1]);
                mma_f16(acc[2*jj],   aph[0], aph[1], aph[2], aph[3], vl[0], vl[1]);
                mma_f16(acc[2*jj+1], aph[0], aph[1], aph[2], aph[3], vh[2], vh[3]);
                mma_f16(acc[2*jj+1], aph[0], aph[1], aph[2], aph[3], vl[2], vl[3]);
            }
        }
        __syncthreads();
    }

    // --- final normalize + write ctx hi plane ---
    l0 += __shfl_xor_sync(0xffffffffu, l0, 1);
    l0 += __shfl_xor_sync(0xffffffffu, l0, 2);
    l1 += __shfl_xor_sync(0xffffffffu, l1, 1);
    l1 += __shfl_xor_sync(0xffffffffu, l1, 2);
    float inv0 = 1.0f / l0, inv1 = 1.0f / l1;

    size_t rb0 = (size_t)(b * SEQ + row0g) * DM;
    size_t rb1 = rb0 + 8 * DM;
    int dcol = h * DH + colbase;
    #pragma unroll
    for (int j = 0; j < 8; j++) {
        int d = dcol + 8 * j;
        *(uint32_t*)&Ch[rb0 + d] = pack_h2(acc[j][0] * inv0, acc[j][1] * inv0);
        *(uint32_t*)&Ch[rb1 + d] = pack_h2(acc[j][2] * inv1, acc[j][3] * inv1);
    }
}

// ---------------------------------------------------------------------------
// Launch
// ---------------------------------------------------------------------------
extern "C" void kernel_launch(void* const* d_in, const int* in_sizes, int n_in,
                              void* d_out, int out_size)
{
    const float* x  = (const float*)d_in[0];
    const float* Wq = (const float*)d_in[1];
    const float* Wk = (const float*)d_in[2];
    const float* Wv = (const float*)d_in[3];
    const float* Wo = (const float*)d_in[4];
    float* out = (float*)d_out;

    __half *px2, *pWc2, *pWot, *pCh, *pQhi, *pQlo;
    cudaGetSymbolAddress((void**)&px2, g_x2);
    cudaGetSymbolAddress((void**)&pWc2, g_Wc2);
    cudaGetSymbolAddress((void**)&pWot, g_Wot);
    cudaGetSymbolAddress((void**)&pCh, g_Ch);
    cudaGetSymbolAddress((void**)&pQhi, g_Qhi);
    cudaGetSymbolAddress((void**)&pQlo, g_Qlo);

    // Weight transpose: QKV duplicated fp16 (stacked-K), Wo single
    {
        dim3 blk(32, 8);
        transpose_h<<<dim3(32, 32), blk>>>(Wq, pWc2, DM, 0, K2, 1);
        transpose_h<<<dim3(8, 32), blk>>>(Wk, pWc2, 256, 1024, K2, 1);
        transpose_h<<<dim3(8, 32), blk>>>(Wv, pWc2, 256, 1280, K2, 1);
        transpose_h<<<dim3(32, 32), blk>>>(Wo, pWot, DM, 0, DM, 0);
    }

    // x -> stacked fp16 [h|l]
    split2_rows<<<2048, 256>>>(x, px2, MTOK);

    // QKV projection GEMM (compensated, Kg=2048) -> fp16 hi/lo planes
    cudaFuncSetAttribute(mma_gemm<1>, cudaFuncAttributeMaxDynamicSharedMemorySize, GEMM_SMEM);
    cudaFuncSetAttribute(mma_gemm<0>, cudaFuncAttributeMaxDynamicSharedMemorySize, GEMM_SMEM);
    {
        dim3 g(NQKV / BN, MTOK / BM);
        mma_gemm<1><<<g, 256, GEMM_SMEM>>>(px2, pWc2, nullptr, pQhi, pQlo, MTOK, NQKV, K2);
    }

    // RoPE on planes (writes hi only)
    {
        int total = MTOK * 20 * 32;
        rope_kernel<<<(total + 255) / 256, 256>>>(pQhi, pQlo);
    }

    // Flash attention -> ctx hi plane
    {
        cudaFuncSetAttribute(attn_mma,
                             cudaFuncAttributeMaxDynamicSharedMemorySize,
                             ATTN_SMEM);
        dim3 ga(SEQ / 128, NHEAD, BATCH);
        attn_mma<<<ga, 256, ATTN_SMEM>>>(pQhi, pQlo, pCh);
    }

    // Output projection GEMM (single fp16, Kg=1024) -> fp32 out
    {
        dim3 g(DM / BN, MTOK / BM);
        mma_gemm<0><<<g, 256, GEMM_SMEM>>>(pCh, pWot, out, nullptr, nullptr, MTOK, DM, DM);
    }
}

// round 10
// speedup vs baseline: 2.9354x; 1.1637x over previous
#include <cuda_runtime.h>
#include <cuda_fp16.h>
#include <math.h>
#include <cstdint>

#define NHEAD 16
#define NKV   4
#define DH    64
#define BATCH 2
#define SEQ   2048
#define MTOK  (BATCH*SEQ)     // 4096
#define DM    1024
#define NQKV  1536            // 1024(Q) + 256(K) + 256(V)
#define K2    2048            // stacked-K (hi | lo) for x

// ---------------------------------------------------------------------------
// Scratch (static device globals -- no allocation allowed)
// ---------------------------------------------------------------------------
__device__ __half g_x2[(size_t)MTOK * K2];       // x limbs [h|l]      16 MB
__device__ __half g_Wc2[(size_t)NQKV * K2];      // [Wq|Wk|Wv] dup      6 MB
__device__ __half g_Wot[(size_t)DM * DM];        // Wo^T single         2 MB
__device__ __half g_Ch[(size_t)MTOK * DM];       // ctx hi plane        8 MB
__device__ __half g_Qh[(size_t)MTOK * NQKV];     // QKV plane          12 MB

// ---------------------------------------------------------------------------
// PTX helpers (portable sm_80-class)
// ---------------------------------------------------------------------------
__device__ __forceinline__ uint32_t smem_u32(const void* p) {
    return (uint32_t)__cvta_generic_to_shared(p);
}
__device__ __forceinline__ void cp_async16(uint32_t saddr, const void* gaddr) {
    asm volatile("cp.async.cg.shared.global [%0], [%1], 16;" :: "r"(saddr), "l"(gaddr));
}
__device__ __forceinline__ void cp_commit() {
    asm volatile("cp.async.commit_group;" ::: "memory");
}
template<int N>
__device__ __forceinline__ void cp_wait() {
    asm volatile("cp.async.wait_group %0;" :: "n"(N) : "memory");
}
__device__ __forceinline__ void ldmatrix_x4(uint32_t& r0, uint32_t& r1,
                                            uint32_t& r2, uint32_t& r3, uint32_t a) {
    asm volatile("ldmatrix.sync.aligned.m8n8.x4.shared.b16 {%0,%1,%2,%3}, [%4];"
                 : "=r"(r0), "=r"(r1), "=r"(r2), "=r"(r3) : "r"(a));
}
__device__ __forceinline__ void ldmatrix_x4_t(uint32_t& r0, uint32_t& r1,
                                              uint32_t& r2, uint32_t& r3, uint32_t a) {
    asm volatile("ldmatrix.sync.aligned.m8n8.x4.trans.shared.b16 {%0,%1,%2,%3}, [%4];"
                 : "=r"(r0), "=r"(r1), "=r"(r2), "=r"(r3) : "r"(a));
}
__device__ __forceinline__ void mma_f16(float* c, uint32_t a0, uint32_t a1,
                                        uint32_t a2, uint32_t a3,
                                        uint32_t b0, uint32_t b1) {
    asm volatile("mma.sync.aligned.m16n8k16.row.col.f32.f16.f16.f32 "
                 "{%0,%1,%2,%3}, {%4,%5,%6,%7}, {%8,%9}, {%0,%1,%2,%3};"
                 : "+f"(c[0]), "+f"(c[1]), "+f"(c[2]), "+f"(c[3])
                 : "r"(a0), "r"(a1), "r"(a2), "r"(a3), "r"(b0), "r"(b1));
}
__device__ __forceinline__ float ex2(float x) {
    float r; asm("ex2.approx.f32 %0, %1;" : "=f"(r) : "f"(x)); return r;
}
__device__ __forceinline__ uint32_t pack_h2(float x, float y) {
    __half2 t = __floats2half2_rn(x, y);
    return *reinterpret_cast<uint32_t*>(&t);
}

// ---------------------------------------------------------------------------
// Prep: split fp32 x rows -> stacked fp16 [h | l]
// ---------------------------------------------------------------------------
__global__ void split2_rows(const float* __restrict__ in, __half* __restrict__ out,
                            int M)
{
    int n = M * DM;
    for (int i = blockIdx.x * blockDim.x + threadIdx.x; i < n; i += gridDim.x * blockDim.x) {
        int m = i / DM, k = i % DM;
        float v = in[i];
        __half h = __float2half_rn(v);
        __half l = __float2half_rn(v - __half2float(h));
        out[(size_t)m * K2 + k]       = h;
        out[(size_t)m * K2 + DM + k]  = l;
    }
}

// Fused QKV weight transpose: Wq|Wk|Wv -> g_Wc2 rows [0,1536), fp16 duplicated
// at +DM (stacked-K layout). grid (48, 32), block (32, 8).
__global__ void transpose_qkv(const float* __restrict__ Wq,
                              const float* __restrict__ Wk,
                              const float* __restrict__ Wv,
                              __half* __restrict__ out)
{
    __shared__ float t[32][33];
    int n0 = blockIdx.x * 32, k0 = blockIdx.y * 32;
    int tx = threadIdx.x, ty = threadIdx.y;

    const float* W;
    int Ndim, nloc;
    if (n0 < 1024)      { W = Wq; Ndim = 1024; nloc = n0; }
    else if (n0 < 1280) { W = Wk; Ndim = 256;  nloc = n0 - 1024; }
    else                { W = Wv; Ndim = 256;  nloc = n0 - 1280; }

    #pragma unroll
    for (int i = 0; i < 32; i += 8)
        t[ty + i][tx] = W[(size_t)(k0 + ty + i) * Ndim + (nloc + tx)];
    __syncthreads();
    #pragma unroll
    for (int i = 0; i < 32; i += 8) {
        __half w1 = __float2half_rn(t[tx][ty + i]);
        size_t base = (size_t)(n0 + ty + i) * K2 + (k0 + tx);
        out[base]      = w1;
        out[base + DM] = w1;
    }
}

// Wo[1024,1024] -> Wo^T fp16 single
__global__ void transpose_wo(const float* __restrict__ W, __half* __restrict__ out)
{
    __shared__ float t[32][33];
    int n0 = blockIdx.x * 32, k0 = blockIdx.y * 32;
    int tx = threadIdx.x, ty = threadIdx.y;
    #pragma unroll
    for (int i = 0; i < 32; i += 8)
        t[ty + i][tx] = W[(size_t)(k0 + ty + i) * DM + (n0 + tx)];
    __syncthreads();
    #pragma unroll
    for (int i = 0; i < 32; i += 8)
        out[(size_t)(n0 + ty + i) * DM + (k0 + tx)] = __float2half_rn(t[tx][ty + i]);
}

// ---------------------------------------------------------------------------
// fp16 tensor-core GEMM, 3-stage cp.async: C[M,N] = A[M,Kg] @ B[N,Kg]^T
// OUT_MODE 0: fp32 C.  OUT_MODE 1: fp16 plane (hi only).
// ---------------------------------------------------------------------------
#define BM 128
#define BN 128
#define BKK 32
#define LDS_ROW 40
#define GEMM_BUF (BM * LDS_ROW * 2)
#define GEMM_SMEM (6 * GEMM_BUF)           // 61440

template<int OUT_MODE>
__global__ __launch_bounds__(256, 2) void mma_gemm(
    const __half* __restrict__ A, const __half* __restrict__ B,
    float* __restrict__ C, __half* __restrict__ Chi, int M, int N, int Kg)
{
    extern __shared__ char gsm[];
    uint32_t sabase = smem_u32(gsm);

    int tid = threadIdx.x;
    int lane = tid & 31;
    int wid = tid >> 5;
    int wm = wid & 3;
    int wn = wid >> 2;
    int m0 = blockIdx.y * BM;
    int n0 = blockIdx.x * BN;

    int r0 = (tid + 0)   >> 2, c0 = (tid + 0)   & 3;
    int r1 = (tid + 256) >> 2, c1 = (tid + 256) & 3;

    const __half* Ag = A + (size_t)m0 * Kg;
    const __half* Bg = B + (size_t)n0 * Kg;

    float acc[2][8][4];
    #pragma unroll
    for (int i = 0; i < 2; i++)
        #pragma unroll
        for (int j = 0; j < 8; j++)
            #pragma unroll
            for (int q = 0; q < 4; q++) acc[i][j][q] = 0.0f;

    const int nk = Kg / BKK;

    auto issue = [&](int kt, int s) {
        int kg = kt * BKK;
        uint32_t sa = sabase + s * GEMM_BUF;
        uint32_t sb = sabase + (3 + s) * GEMM_BUF;
        cp_async16(sa + (r0 * LDS_ROW + c0 * 8) * 2, Ag + (size_t)r0 * Kg + kg + c0 * 8);
        cp_async16(sa + (r1 * LDS_ROW + c1 * 8) * 2, Ag + (size_t)r1 * Kg + kg + c1 * 8);
        cp_async16(sb + (r0 * LDS_ROW + c0 * 8) * 2, Bg + (size_t)r0 * Kg + kg + c0 * 8);
        cp_async16(sb + (r1 * LDS_ROW + c1 * 8) * 2, Bg + (size_t)r1 * Kg + kg + c1 * 8);
        cp_commit();
    };

    issue(0, 0);
    issue(1, 1);

    int a_row = wm * 32 + (lane & 15);
    int a_colp = (lane >> 4) * 8;
    int b_row = wn * 64 + (lane & 7) + ((lane >> 4) << 3);
    int b_colp = ((lane >> 3) & 1) * 8;

    int buf = 0;
    for (int kt = 0; kt < nk; kt++) {
        if (kt + 2 < nk) { issue(kt + 2, (kt + 2) % 3); cp_wait<2>(); }
        else if (kt + 1 < nk) { cp_wait<1>(); }
        else { cp_wait<0>(); }
        __syncthreads();

        uint32_t sa = sabase + buf * GEMM_BUF;
        uint32_t sb = sabase + (3 + buf) * GEMM_BUF;
        #pragma unroll
        for (int k16 = 0; k16 < 2; k16++) {
            uint32_t af[2][4];
            #pragma unroll
            for (int mi = 0; mi < 2; mi++) {
                uint32_t addr = sa + (((a_row + mi * 16) * LDS_ROW) + k16 * 16 + a_colp) * 2;
                ldmatrix_x4(af[mi][0], af[mi][1], af[mi][2], af[mi][3], addr);
            }
            uint32_t bfr[4][4];
            #pragma unroll
            for (int ni2 = 0; ni2 < 4; ni2++) {
                uint32_t addr = sb + (((b_row + ni2 * 16) * LDS_ROW) + k16 * 16 + b_colp) * 2;
                ldmatrix_x4(bfr[ni2][0], bfr[ni2][1], bfr[ni2][2], bfr[ni2][3], addr);
            }
            #pragma unroll
            for (int mi = 0; mi < 2; mi++)
                #pragma unroll
                for (int ni = 0; ni < 8; ni++) {
                    uint32_t bb0 = bfr[ni >> 1][(ni & 1) * 2];
                    uint32_t bb1 = bfr[ni >> 1][(ni & 1) * 2 + 1];
                    mma_f16(acc[mi][ni], af[mi][0], af[mi][1], af[mi][2], af[mi][3], bb0, bb1);
                }
        }
        __syncthreads();
        buf = (buf + 1 == 3) ? 0 : buf + 1;
    }

    int cr = lane >> 2;
    int cc = (lane & 3) * 2;
    #pragma unroll
    for (int mi = 0; mi < 2; mi++) {
        #pragma unroll
        for (int ni = 0; ni < 8; ni++) {
            int row = m0 + wm * 32 + mi * 16 + cr;
            int col = n0 + wn * 64 + ni * 8 + cc;
            if (OUT_MODE == 0) {
                *(float2*)&C[(size_t)row * N + col] =
                    make_float2(acc[mi][ni][0], acc[mi][ni][1]);
                *(float2*)&C[(size_t)(row + 8) * N + col] =
                    make_float2(acc[mi][ni][2], acc[mi][ni][3]);
            } else {
                *(uint32_t*)&Chi[(size_t)row * N + col] =
                    pack_h2(acc[mi][ni][0], acc[mi][ni][1]);
                *(uint32_t*)&Chi[(size_t)(row + 8) * N + col] =
                    pack_h2(acc[mi][ni][2], acc[mi][ni][3]);
            }
        }
    }
}

// ---------------------------------------------------------------------------
// RoPE in-place on fp16 plane [MTOK, 1536] (Q heads 0-15, K heads at 1024+)
// ---------------------------------------------------------------------------
__global__ void rope_kernel(__half* __restrict__ hi)
{
    const int tot = MTOK * 20 * 32;
    int idx = blockIdx.x * blockDim.x + threadIdx.x;
    if (idx >= tot) return;

    int i    = idx & 31;
    int hh   = (idx >> 5) % 20;
    int tok  = idx / (32 * 20);
    int s    = tok % SEQ;
    int col  = (hh < 16) ? hh * DH : 1024 + (hh - 16) * DH;
    size_t base = (size_t)tok * NQKV + col;

    float invf = exp10f(-(float)i * 0.125f);
    float ang  = (float)s * invf;
    float c = cosf(ang), sn = sinf(ang);

    float x0 = __half2float(hi[base + i]);
    float x1 = __half2float(hi[base + i + 32]);
    hi[base + i]      = __float2half_rn(x0 * c - x1 * sn);
    hi[base + i + 32] = __float2half_rn(x1 * c + x0 * sn);
}

// ---------------------------------------------------------------------------
// fp16 tensor-core flash attention. Q, K, V all single fp16.
// Double-buffered KV (K,V per stage). Writes ctx plane into g_Ch.
// ---------------------------------------------------------------------------
#define AROW 72
#define ROWB (AROW*2)          // 144 bytes per row
#define SQ_HI 0
#define SKV0  (128*ROWB)       // 18432
#define KVSTG (2*64*ROWB)      // 18432 per stage (K,V)
#define ATTN_SMEM (SKV0 + 2*KVSTG)   // 55296

__global__ __launch_bounds__(256) void attn_mma(
    const __half* __restrict__ Phi, __half* __restrict__ Ch)
{
    extern __shared__ char smc[];
    uint32_t sb = smem_u32(smc);

    int qt = (int)gridDim.x - 1 - (int)blockIdx.x;
    int h  = blockIdx.y;
    int b  = blockIdx.z;
    int kh = h >> 2;

    int tid  = threadIdx.x;
    int lane = tid & 31;
    int wm   = tid >> 5;

    const int kcol = 1024 + kh * DH;
    const int vcol = 1280 + kh * DH;

    // --- issue Q tile + KV tile 0 ---
    {
        #pragma unroll
        for (int it = 0; it < 4; it++) {
            int idx = tid + it * 256;        // 1024 chunks
            int r = idx >> 3, c = idx & 7;
            const __half* src = Phi
                + (size_t)(b * SEQ + qt * 128 + r) * NQKV + h * DH + c * 8;
            cp_async16(sb + SQ_HI + r * ROWB + c * 16, src);
        }
        #pragma unroll
        for (int it = 0; it < 4; it++) {
            int idx = tid + it * 256;        // 1024 chunks
            int sel = idx >> 9;              // 0 K, 1 V
            int j = idx & 511;
            int r = j >> 3, c = j & 7;
            int colb = (sel == 0) ? kcol : vcol;
            const __half* src = Phi + (size_t)(b * SEQ + r) * NQKV + colb + c * 8;
            uint32_t dst = sb + SKV0 + sel * (64 * ROWB) + r * ROWB + c * 16;
            cp_async16(dst, src);
        }
        cp_commit();
    }

    uint32_t qa_off = (uint32_t)((wm * 16 + (lane & 7) + ((lane >> 3) & 1) * 8) * ROWB
                                 + (lane >> 4) * 16);
    uint32_t kb_off = (uint32_t)(((lane & 7) + (lane >> 4) * 8) * ROWB
                                 + ((lane >> 3) & 1) * 16);
    uint32_t vb_off = (uint32_t)(((lane & 7) + ((lane >> 3) & 1) * 8) * ROWB
                                 + (lane >> 4) * 16);

    float acc[8][4];
    #pragma unroll
    for (int j = 0; j < 8; j++)
        #pragma unroll
        for (int q = 0; q < 4; q++) acc[j][q] = 0.0f;
    float m0 = -1e30f, m1 = -1e30f, l0 = 0.0f, l1 = 0.0f;

    const float SCL = 0.125f * 1.44269504f;
    int row0g = qt * 128 + wm * 16 + (lane >> 2);
    int colbase = 2 * (lane & 3);

    int nkt = 2 * qt + 2;
    for (int kt = 0; kt < nkt; kt++) {
        if (kt + 1 < nkt) {
            int stg = (kt + 1) & 1;
            #pragma unroll
            for (int it = 0; it < 4; it++) {
                int idx = tid + it * 256;
                int sel = idx >> 9;
                int j = idx & 511;
                int r = j >> 3, c = j & 7;
                int colb = (sel == 0) ? kcol : vcol;
                const __half* src = Phi
                    + (size_t)(b * SEQ + (kt + 1) * 64 + r) * NQKV + colb + c * 8;
                uint32_t dst = sb + SKV0 + stg * KVSTG + sel * (64 * ROWB) + r * ROWB + c * 16;
                cp_async16(dst, src);
            }
            cp_commit();
            cp_wait<1>();
        } else {
            cp_wait<0>();
        }
        __syncthreads();

        uint32_t kvb = sb + SKV0 + (kt & 1) * KVSTG;
        uint32_t skh = kvb;
        uint32_t svh = kvb + 64 * ROWB;

        // --- S = Q K^T ---
        float sf[8][4];
        #pragma unroll
        for (int j = 0; j < 8; j++)
            #pragma unroll
            for (int q = 0; q < 4; q++) sf[j][q] = 0.0f;

        #pragma unroll
        for (int t = 0; t < 4; t++) {
            uint32_t qh[4];
            ldmatrix_x4(qh[0], qh[1], qh[2], qh[3], sb + SQ_HI + qa_off + t * 32);
            #pragma unroll
            for (int jj = 0; jj < 4; jj++) {
                uint32_t kmh[4];
                uint32_t off = kb_off + jj * 16 * ROWB + t * 32;
                ldmatrix_x4(kmh[0], kmh[1], kmh[2], kmh[3], skh + off);
                mma_f16(sf[2*jj],   qh[0], qh[1], qh[2], qh[3], kmh[0], kmh[1]);
                mma_f16(sf[2*jj+1], qh[0], qh[1], qh[2], qh[3], kmh[2], kmh[3]);
            }
        }

        // --- scale + causal mask ---
        bool need_mask = (kt * 64 + 63 > qt * 128 + wm * 16);
        if (need_mask) {
            #pragma unroll
            for (int j = 0; j < 8; j++) {
                int c0 = kt * 64 + 8 * j + colbase;
                sf[j][0] = (c0     <= row0g)     ? sf[j][0] * SCL : -1e30f;
                sf[j][1] = (c0 + 1 <= row0g)     ? sf[j][1] * SCL : -1e30f;
                sf[j][2] = (c0     <= row0g + 8) ? sf[j][2] * SCL : -1e30f;
                sf[j][3] = (c0 + 1 <= row0g + 8) ? sf[j][3] * SCL : -1e30f;
            }
        } else {
            #pragma unroll
            for (int j = 0; j < 8; j++)
                #pragma unroll
                for (int q = 0; q < 4; q++) sf[j][q] *= SCL;
        }

        // --- online softmax ---
        float mx0 = m0, mx1 = m1;
        #pragma unroll
        for (int j = 0; j < 8; j++) {
            mx0 = fmaxf(mx0, fmaxf(sf[j][0], sf[j][1]));
            mx1 = fmaxf(mx1, fmaxf(sf[j][2], sf[j][3]));
        }
        mx0 = fmaxf(mx0, __shfl_xor_sync(0xffffffffu, mx0, 1));
        mx0 = fmaxf(mx0, __shfl_xor_sync(0xffffffffu, mx0, 2));
        mx1 = fmaxf(mx1, __shfl_xor_sync(0xffffffffu, mx1, 1));
        mx1 = fmaxf(mx1, __shfl_xor_sync(0xffffffffu, mx1, 2));
        float corr0 = ex2(m0 - mx0);
        float corr1 = ex2(m1 - mx1);
        m0 = mx0; m1 = mx1;

        float ls0 = 0.0f, ls1 = 0.0f;
        #pragma unroll
        for (int j = 0; j < 8; j++) {
            sf[j][0] = ex2(sf[j][0] - mx0);
            sf[j][1] = ex2(sf[j][1] - mx0);
            sf[j][2] = ex2(sf[j][2] - mx1);
            sf[j][3] = ex2(sf[j][3] - mx1);
            ls0 += sf[j][0] + sf[j][1];
            ls1 += sf[j][2] + sf[j][3];
        }
        l0 = l0 * corr0 + ls0;
        l1 = l1 * corr1 + ls1;
        #pragma unroll
        for (int j = 0; j < 8; j++) {
            acc[j][0] *= corr0; acc[j][1] *= corr0;
            acc[j][2] *= corr1; acc[j][3] *= corr1;
        }

        // --- PV (single V : 2 mmas per (t,jj)) ---
        #pragma unroll
        for (int t = 0; t < 4; t++) {
            uint32_t aph[4];
            aph[0] = pack_h2(sf[2*t][0],   sf[2*t][1]);
            aph[1] = pack_h2(sf[2*t][2],   sf[2*t][3]);
            aph[2] = pack_h2(sf[2*t+1][0], sf[2*t+1][1]);
            aph[3] = pack_h2(sf[2*t+1][2], sf[2*t+1][3]);
            #pragma unroll
            for (int jj = 0; jj < 4; jj++) {
                uint32_t vh[4];
                uint32_t off = vb_off + t * 16 * ROWB + jj * 32;
                ldmatrix_x4_t(vh[0], vh[1], vh[2], vh[3], svh + off);
                mma_f16(acc[2*jj],   aph[0], aph[1], aph[2], aph[3], vh[0], vh[1]);
                mma_f16(acc[2*jj+1], aph[0], aph[1], aph[2], aph[3], vh[2], vh[3]);
            }
        }
        __syncthreads();
    }

    // --- final normalize + write ctx plane ---
    l0 += __shfl_xor_sync(0xffffffffu, l0, 1);
    l0 += __shfl_xor_sync(0xffffffffu, l0, 2);
    l1 += __shfl_xor_sync(0xffffffffu, l1, 1);
    l1 += __shfl_xor_sync(0xffffffffu, l1, 2);
    float inv0 = 1.0f / l0, inv1 = 1.0f / l1;

    size_t rb0 = (size_t)(b * SEQ + row0g) * DM;
    size_t rb1 = rb0 + 8 * DM;
    int dcol = h * DH + colbase;
    #pragma unroll
    for (int j = 0; j < 8; j++) {
        int d = dcol + 8 * j;
        *(uint32_t*)&Ch[rb0 + d] = pack_h2(acc[j][0] * inv0, acc[j][1] * inv0);
        *(uint32_t*)&Ch[rb1 + d] = pack_h2(acc[j][2] * inv1, acc[j][3] * inv1);
    }
}

// ---------------------------------------------------------------------------
// Launch
// ---------------------------------------------------------------------------
extern "C" void kernel_launch(void* const* d_in, const int* in_sizes, int n_in,
                              void* d_out, int out_size)
{
    const float* x  = (const float*)d_in[0];
    const float* Wq = (const float*)d_in[1];
    const float* Wk = (const float*)d_in[2];
    const float* Wv = (const float*)d_in[3];
    const float* Wo = (const float*)d_in[4];
    float* out = (float*)d_out;

    __half *px2, *pWc2, *pWot, *pCh, *pQh;
    cudaGetSymbolAddress((void**)&px2, g_x2);
    cudaGetSymbolAddress((void**)&pWc2, g_Wc2);
    cudaGetSymbolAddress((void**)&pWot, g_Wot);
    cudaGetSymbolAddress((void**)&pCh, g_Ch);
    cudaGetSymbolAddress((void**)&pQh, g_Qh);

    // Weight transposes (QKV fused into one launch)
    {
        dim3 blk(32, 8);
        transpose_qkv<<<dim3(48, 32), blk>>>(Wq, Wk, Wv, pWc2);
        transpose_wo<<<dim3(32, 32), blk>>>(Wo, pWot);
    }

    // x -> stacked fp16 [h|l]
    split2_rows<<<2048, 256>>>(x, px2, MTOK);

    // QKV projection GEMM (compensated, Kg=2048) -> fp16 plane
    cudaFuncSetAttribute(mma_gemm<1>, cudaFuncAttributeMaxDynamicSharedMemorySize, GEMM_SMEM);
    cudaFuncSetAttribute(mma_gemm<0>, cudaFuncAttributeMaxDynamicSharedMemorySize, GEMM_SMEM);
    {
        dim3 g(NQKV / BN, MTOK / BM);
        mma_gemm<1><<<g, 256, GEMM_SMEM>>>(px2, pWc2, nullptr, pQh, MTOK, NQKV, K2);
    }

    // RoPE on plane
    {
        int total = MTOK * 20 * 32;
        rope_kernel<<<(total + 255) / 256, 256>>>(pQh);
    }

    // Flash attention -> ctx plane
    {
        cudaFuncSetAttribute(attn_mma,
                             cudaFuncAttributeMaxDynamicSharedMemorySize,
                             ATTN_SMEM);
        dim3 ga(SEQ / 128, NHEAD, BATCH);
        attn_mma<<<ga, 256, ATTN_SMEM>>>(pQh, pCh);
    }

    // Output projection GEMM (single fp16, Kg=1024) -> fp32 out
    {
        dim3 g(DM / BN, MTOK / BM);
        mma_gemm<0><<<g, 256, GEMM_SMEM>>>(pCh, pWot, out, nullptr, MTOK, DM, DM);
    }
}

// round 11
// speedup vs baseline: 3.7849x; 1.2894x over previous
#include <cuda_runtime.h>
#include <cuda_fp16.h>
#include <math.h>
#include <cstdint>

#define NHEAD 16
#define NKV   4
#define DH    64
#define BATCH 2
#define SEQ   2048
#define MTOK  (BATCH*SEQ)     // 4096
#define DM    1024
#define NQKV  1536            // 1024(Q) + 256(K) + 256(V)

// ---------------------------------------------------------------------------
// Scratch (static device globals -- no allocation allowed)
// ---------------------------------------------------------------------------
__device__ __half g_x1[(size_t)MTOK * DM];       // x fp16              8 MB
__device__ __half g_Wct[(size_t)NQKV * DM];      // [Wq|Wk|Wv]^T fp16   3 MB
__device__ __half g_Wot[(size_t)DM * DM];        // Wo^T fp16           2 MB
__device__ __half g_Ch[(size_t)MTOK * DM];       // ctx plane           8 MB
__device__ __half g_Qh[(size_t)MTOK * NQKV];     // QKV plane          12 MB

// ---------------------------------------------------------------------------
// PTX helpers (portable sm_80-class)
// ---------------------------------------------------------------------------
__device__ __forceinline__ uint32_t smem_u32(const void* p) {
    return (uint32_t)__cvta_generic_to_shared(p);
}
__device__ __forceinline__ void cp_async16(uint32_t saddr, const void* gaddr) {
    asm volatile("cp.async.cg.shared.global [%0], [%1], 16;" :: "r"(saddr), "l"(gaddr));
}
__device__ __forceinline__ void cp_commit() {
    asm volatile("cp.async.commit_group;" ::: "memory");
}
template<int N>
__device__ __forceinline__ void cp_wait() {
    asm volatile("cp.async.wait_group %0;" :: "n"(N) : "memory");
}
__device__ __forceinline__ void ldmatrix_x4(uint32_t& r0, uint32_t& r1,
                                            uint32_t& r2, uint32_t& r3, uint32_t a) {
    asm volatile("ldmatrix.sync.aligned.m8n8.x4.shared.b16 {%0,%1,%2,%3}, [%4];"
                 : "=r"(r0), "=r"(r1), "=r"(r2), "=r"(r3) : "r"(a));
}
__device__ __forceinline__ void ldmatrix_x4_t(uint32_t& r0, uint32_t& r1,
                                              uint32_t& r2, uint32_t& r3, uint32_t a) {
    asm volatile("ldmatrix.sync.aligned.m8n8.x4.trans.shared.b16 {%0,%1,%2,%3}, [%4];"
                 : "=r"(r0), "=r"(r1), "=r"(r2), "=r"(r3) : "r"(a));
}
__device__ __forceinline__ void mma_f16(float* c, uint32_t a0, uint32_t a1,
                                        uint32_t a2, uint32_t a3,
                                        uint32_t b0, uint32_t b1) {
    asm volatile("mma.sync.aligned.m16n8k16.row.col.f32.f16.f16.f32 "
                 "{%0,%1,%2,%3}, {%4,%5,%6,%7}, {%8,%9}, {%0,%1,%2,%3};"
                 : "+f"(c[0]), "+f"(c[1]), "+f"(c[2]), "+f"(c[3])
                 : "r"(a0), "r"(a1), "r"(a2), "r"(a3), "r"(b0), "r"(b1));
}
__device__ __forceinline__ float ex2(float x) {
    float r; asm("ex2.approx.f32 %0, %1;" : "=f"(r) : "f"(x)); return r;
}
__device__ __forceinline__ uint32_t pack_h2(float x, float y) {
    __half2 t = __floats2half2_rn(x, y);
    return *reinterpret_cast<uint32_t*>(&t);
}

// ---------------------------------------------------------------------------
// Prep: fp32 -> fp16 convert (vectorized)
// ---------------------------------------------------------------------------
__global__ void convert_rows(const float* __restrict__ in, __half* __restrict__ out,
                             int n2)
{
    for (int i = blockIdx.x * blockDim.x + threadIdx.x; i < n2; i += gridDim.x * blockDim.x) {
        float2 v = ((const float2*)in)[i];
        ((__half2*)out)[i] = __floats2half2_rn(v.x, v.y);
    }
}

// Fused QKV weight transpose: Wq|Wk|Wv -> g_Wct rows [0,1536), fp16 single.
__global__ void transpose_qkv(const float* __restrict__ Wq,
                              const float* __restrict__ Wk,
                              const float* __restrict__ Wv,
                              __half* __restrict__ out)
{
    __shared__ float t[32][33];
    int n0 = blockIdx.x * 32, k0 = blockIdx.y * 32;
    int tx = threadIdx.x, ty = threadIdx.y;

    const float* W;
    int Ndim, nloc;
    if (n0 < 1024)      { W = Wq; Ndim = 1024; nloc = n0; }
    else if (n0 < 1280) { W = Wk; Ndim = 256;  nloc = n0 - 1024; }
    else                { W = Wv; Ndim = 256;  nloc = n0 - 1280; }

    #pragma unroll
    for (int i = 0; i < 32; i += 8)
        t[ty + i][tx] = W[(size_t)(k0 + ty + i) * Ndim + (nloc + tx)];
    __syncthreads();
    #pragma unroll
    for (int i = 0; i < 32; i += 8)
        out[(size_t)(n0 + ty + i) * DM + (k0 + tx)] = __float2half_rn(t[tx][ty + i]);
}

// Wo[1024,1024] -> Wo^T fp16 single
__global__ void transpose_wo(const float* __restrict__ W, __half* __restrict__ out)
{
    __shared__ float t[32][33];
    int n0 = blockIdx.x * 32, k0 = blockIdx.y * 32;
    int tx = threadIdx.x, ty = threadIdx.y;
    #pragma unroll
    for (int i = 0; i < 32; i += 8)
        t[ty + i][tx] = W[(size_t)(k0 + ty + i) * DM + (n0 + tx)];
    __syncthreads();
    #pragma unroll
    for (int i = 0; i < 32; i += 8)
        out[(size_t)(n0 + ty + i) * DM + (k0 + tx)] = __float2half_rn(t[tx][ty + i]);
}

// ---------------------------------------------------------------------------
// fp16 tensor-core GEMM, 3-stage cp.async, ONE barrier per K-iteration.
// C[M,N] = A[M,Kg] @ B[N,Kg]^T.
// OUT_MODE 0: fp32 C.  OUT_MODE 1: fp16 plane.
// ---------------------------------------------------------------------------
#define BM 128
#define BN 128
#define BKK 32
#define LDS_ROW 40
#define GEMM_BUF (BM * LDS_ROW * 2)
#define GEMM_SMEM (6 * GEMM_BUF)           // 61440

template<int OUT_MODE>
__global__ __launch_bounds__(256, 2) void mma_gemm(
    const __half* __restrict__ A, const __half* __restrict__ B,
    float* __restrict__ C, __half* __restrict__ Chi, int M, int N, int Kg)
{
    extern __shared__ char gsm[];
    uint32_t sabase = smem_u32(gsm);

    int tid = threadIdx.x;
    int lane = tid & 31;
    int wid = tid >> 5;
    int wm = wid & 3;
    int wn = wid >> 2;
    int m0 = blockIdx.y * BM;
    int n0 = blockIdx.x * BN;

    int r0 = (tid + 0)   >> 2, c0 = (tid + 0)   & 3;
    int r1 = (tid + 256) >> 2, c1 = (tid + 256) & 3;

    const __half* Ag = A + (size_t)m0 * Kg;
    const __half* Bg = B + (size_t)n0 * Kg;

    float acc[2][8][4];
    #pragma unroll
    for (int i = 0; i < 2; i++)
        #pragma unroll
        for (int j = 0; j < 8; j++)
            #pragma unroll
            for (int q = 0; q < 4; q++) acc[i][j][q] = 0.0f;

    const int nk = Kg / BKK;

    auto issue = [&](int kt, int s) {
        int kg = kt * BKK;
        uint32_t sa = sabase + s * GEMM_BUF;
        uint32_t sb = sabase + (3 + s) * GEMM_BUF;
        cp_async16(sa + (r0 * LDS_ROW + c0 * 8) * 2, Ag + (size_t)r0 * Kg + kg + c0 * 8);
        cp_async16(sa + (r1 * LDS_ROW + c1 * 8) * 2, Ag + (size_t)r1 * Kg + kg + c1 * 8);
        cp_async16(sb + (r0 * LDS_ROW + c0 * 8) * 2, Bg + (size_t)r0 * Kg + kg + c0 * 8);
        cp_async16(sb + (r1 * LDS_ROW + c1 * 8) * 2, Bg + (size_t)r1 * Kg + kg + c1 * 8);
        cp_commit();
    };

    issue(0, 0);
    issue(1, 1);

    int a_row = wm * 32 + (lane & 15);
    int a_colp = (lane >> 4) * 8;
    int b_row = wn * 64 + (lane & 7) + ((lane >> 4) << 3);
    int b_colp = ((lane >> 3) & 1) * 8;

    int buf = 0;
    for (int kt = 0; kt < nk; kt++) {
        if (kt + 1 < nk) { cp_wait<1>(); } else { cp_wait<0>(); }
        __syncthreads();
        // prefetch into the buffer consumed at kt-1 (fenced by the barrier above)
        if (kt + 2 < nk) issue(kt + 2, (kt + 2) % 3);

        uint32_t sa = sabase + buf * GEMM_BUF;
        uint32_t sb = sabase + (3 + buf) * GEMM_BUF;
        #pragma unroll
        for (int k16 = 0; k16 < 2; k16++) {
            uint32_t af[2][4];
            #pragma unroll
            for (int mi = 0; mi < 2; mi++) {
                uint32_t addr = sa + (((a_row + mi * 16) * LDS_ROW) + k16 * 16 + a_colp) * 2;
                ldmatrix_x4(af[mi][0], af[mi][1], af[mi][2], af[mi][3], addr);
            }
            uint32_t bfr[4][4];
            #pragma unroll
            for (int ni2 = 0; ni2 < 4; ni2++) {
                uint32_t addr = sb + (((b_row + ni2 * 16) * LDS_ROW) + k16 * 16 + b_colp) * 2;
                ldmatrix_x4(bfr[ni2][0], bfr[ni2][1], bfr[ni2][2], bfr[ni2][3], addr);
            }
            #pragma unroll
            for (int mi = 0; mi < 2; mi++)
                #pragma unroll
                for (int ni = 0; ni < 8; ni++) {
                    uint32_t bb0 = bfr[ni >> 1][(ni & 1) * 2];
                    uint32_t bb1 = bfr[ni >> 1][(ni & 1) * 2 + 1];
                    mma_f16(acc[mi][ni], af[mi][0], af[mi][1], af[mi][2], af[mi][3], bb0, bb1);
                }
        }
        buf = (buf + 1 == 3) ? 0 : buf + 1;
    }

    int cr = lane >> 2;
    int cc = (lane & 3) * 2;
    #pragma unroll
    for (int mi = 0; mi < 2; mi++) {
        #pragma unroll
        for (int ni = 0; ni < 8; ni++) {
            int row = m0 + wm * 32 + mi * 16 + cr;
            int col = n0 + wn * 64 + ni * 8 + cc;
            if (OUT_MODE == 0) {
                *(float2*)&C[(size_t)row * N + col] =
                    make_float2(acc[mi][ni][0], acc[mi][ni][1]);
                *(float2*)&C[(size_t)(row + 8) * N + col] =
                    make_float2(acc[mi][ni][2], acc[mi][ni][3]);
            } else {
                *(uint32_t*)&Chi[(size_t)row * N + col] =
                    pack_h2(acc[mi][ni][0], acc[mi][ni][1]);
                *(uint32_t*)&Chi[(size_t)(row + 8) * N + col] =
                    pack_h2(acc[mi][ni][2], acc[mi][ni][3]);
            }
        }
    }
}

// ---------------------------------------------------------------------------
// RoPE in-place on fp16 plane [MTOK, 1536] (Q heads 0-15, K heads at 1024+)
// ---------------------------------------------------------------------------
__global__ void rope_kernel(__half* __restrict__ hi)
{
    const int tot = MTOK * 20 * 32;
    int idx = blockIdx.x * blockDim.x + threadIdx.x;
    if (idx >= tot) return;

    int i    = idx & 31;
    int hh   = (idx >> 5) % 20;
    int tok  = idx / (32 * 20);
    int s    = tok % SEQ;
    int col  = (hh < 16) ? hh * DH : 1024 + (hh - 16) * DH;
    size_t base = (size_t)tok * NQKV + col;

    float invf = exp10f(-(float)i * 0.125f);
    float ang  = (float)s * invf;
    float c = cosf(ang), sn = sinf(ang);

    float x0 = __half2float(hi[base + i]);
    float x1 = __half2float(hi[base + i + 32]);
    hi[base + i]      = __float2half_rn(x0 * c - x1 * sn);
    hi[base + i + 32] = __float2half_rn(x1 * c + x0 * sn);
}

// ---------------------------------------------------------------------------
// fp16 tensor-core flash attention. Q, K, V single fp16. Double-buffered KV,
// ONE barrier per KV-iteration. Writes ctx plane into g_Ch.
// ---------------------------------------------------------------------------
#define AROW 72
#define ROWB (AROW*2)          // 144 bytes per row
#define SQ_HI 0
#define SKV0  (128*ROWB)       // 18432
#define KVSTG (2*64*ROWB)      // 18432 per stage (K,V)
#define ATTN_SMEM (SKV0 + 2*KVSTG)   // 55296

__global__ __launch_bounds__(256) void attn_mma(
    const __half* __restrict__ Phi, __half* __restrict__ Ch)
{
    extern __shared__ char smc[];
    uint32_t sb = smem_u32(smc);

    int qt = (int)gridDim.x - 1 - (int)blockIdx.x;
    int h  = blockIdx.y;
    int b  = blockIdx.z;
    int kh = h >> 2;

    int tid  = threadIdx.x;
    int lane = tid & 31;
    int wm   = tid >> 5;

    const int kcol = 1024 + kh * DH;
    const int vcol = 1280 + kh * DH;

    // --- issue Q tile + KV tile 0 as one group ---
    {
        #pragma unroll
        for (int it = 0; it < 4; it++) {
            int idx = tid + it * 256;        // 1024 chunks
            int r = idx >> 3, c = idx & 7;
            const __half* src = Phi
                + (size_t)(b * SEQ + qt * 128 + r) * NQKV + h * DH + c * 8;
            cp_async16(sb + SQ_HI + r * ROWB + c * 16, src);
        }
        #pragma unroll
        for (int it = 0; it < 4; it++) {
            int idx = tid + it * 256;        // 1024 chunks
            int sel = idx >> 9;              // 0 K, 1 V
            int j = idx & 511;
            int r = j >> 3, c = j & 7;
            int colb = (sel == 0) ? kcol : vcol;
            const __half* src = Phi + (size_t)(b * SEQ + r) * NQKV + colb + c * 8;
            uint32_t dst = sb + SKV0 + sel * (64 * ROWB) + r * ROWB + c * 16;
            cp_async16(dst, src);
        }
        cp_commit();
    }

    uint32_t qa_off = (uint32_t)((wm * 16 + (lane & 7) + ((lane >> 3) & 1) * 8) * ROWB
                                 + (lane >> 4) * 16);
    uint32_t kb_off = (uint32_t)(((lane & 7) + (lane >> 4) * 8) * ROWB
                                 + ((lane >> 3) & 1) * 16);
    uint32_t vb_off = (uint32_t)(((lane & 7) + ((lane >> 3) & 1) * 8) * ROWB
                                 + (lane >> 4) * 16);

    float acc[8][4];
    #pragma unroll
    for (int j = 0; j < 8; j++)
        #pragma unroll
        for (int q = 0; q < 4; q++) acc[j][q] = 0.0f;
    float m0 = -1e30f, m1 = -1e30f, l0 = 0.0f, l1 = 0.0f;

    const float SCL = 0.125f * 1.44269504f;
    int row0g = qt * 128 + wm * 16 + (lane >> 2);
    int colbase = 2 * (lane & 3);

    int nkt = 2 * qt + 2;
    for (int kt = 0; kt < nkt; kt++) {
        cp_wait<0>();
        __syncthreads();
        // prefetch next KV tile into the stage consumed at kt-1 (fenced above)
        if (kt + 1 < nkt) {
            int stg = (kt + 1) & 1;
            #pragma unroll
            for (int it = 0; it < 4; it++) {
                int idx = tid + it * 256;
                int sel = idx >> 9;
                int j = idx & 511;
                int r = j >> 3, c = j & 7;
                int colb = (sel == 0) ? kcol : vcol;
                const __half* src = Phi
                    + (size_t)(b * SEQ + (kt + 1) * 64 + r) * NQKV + colb + c * 8;
                uint32_t dst = sb + SKV0 + stg * KVSTG + sel * (64 * ROWB) + r * ROWB + c * 16;
                cp_async16(dst, src);
            }
            cp_commit();
        }

        uint32_t kvb = sb + SKV0 + (kt & 1) * KVSTG;
        uint32_t skh = kvb;
        uint32_t svh = kvb + 64 * ROWB;

        // --- S = Q K^T ---
        float sf[8][4];
        #pragma unroll
        for (int j = 0; j < 8; j++)
            #pragma unroll
            for (int q = 0; q < 4; q++) sf[j][q] = 0.0f;

        #pragma unroll
        for (int t = 0; t < 4; t++) {
            uint32_t qh[4];
            ldmatrix_x4(qh[0], qh[1], qh[2], qh[3], sb + SQ_HI + qa_off + t * 32);
            #pragma unroll
            for (int jj = 0; jj < 4; jj++) {
                uint32_t kmh[4];
                uint32_t off = kb_off + jj * 16 * ROWB + t * 32;
                ldmatrix_x4(kmh[0], kmh[1], kmh[2], kmh[3], skh + off);
                mma_f16(sf[2*jj],   qh[0], qh[1], qh[2], qh[3], kmh[0], kmh[1]);
                mma_f16(sf[2*jj+1], qh[0], qh[1], qh[2], qh[3], kmh[2], kmh[3]);
            }
        }

        // --- scale + causal mask ---
        bool need_mask = (kt * 64 + 63 > qt * 128 + wm * 16);
        if (need_mask) {
            #pragma unroll
            for (int j = 0; j < 8; j++) {
                int c0 = kt * 64 + 8 * j + colbase;
                sf[j][0] = (c0     <= row0g)     ? sf[j][0] * SCL : -1e30f;
                sf[j][1] = (c0 + 1 <= row0g)     ? sf[j][1] * SCL : -1e30f;
                sf[j][2] = (c0     <= row0g + 8) ? sf[j][2] * SCL : -1e30f;
                sf[j][3] = (c0 + 1 <= row0g + 8) ? sf[j][3] * SCL : -1e30f;
            }
        } else {
            #pragma unroll
            for (int j = 0; j < 8; j++)
                #pragma unroll
                for (int q = 0; q < 4; q++) sf[j][q] *= SCL;
        }

        // --- online softmax ---
        float mx0 = m0, mx1 = m1;
        #pragma unroll
        for (int j = 0; j < 8; j++) {
            mx0 = fmaxf(mx0, fmaxf(sf[j][0], sf[j][1]));
            mx1 = fmaxf(mx1, fmaxf(sf[j][2], sf[j][3]));
        }
        mx0 = fmaxf(mx0, __shfl_xor_sync(0xffffffffu, mx0, 1));
        mx0 = fmaxf(mx0, __shfl_xor_sync(0xffffffffu, mx0, 2));
        mx1 = fmaxf(mx1, __shfl_xor_sync(0xffffffffu, mx1, 1));
        mx1 = fmaxf(mx1, __shfl_xor_sync(0xffffffffu, mx1, 2));
        float corr0 = ex2(m0 - mx0);
        float corr1 = ex2(m1 - mx1);
        m0 = mx0; m1 = mx1;

        float ls0 = 0.0f, ls1 = 0.0f;
        #pragma unroll
        for (int j = 0; j < 8; j++) {
            sf[j][0] = ex2(sf[j][0] - mx0);
            sf[j][1] = ex2(sf[j][1] - mx0);
            sf[j][2] = ex2(sf[j][2] - mx1);
            sf[j][3] = ex2(sf[j][3] - mx1);
            ls0 += sf[j][0] + sf[j][1];
            ls1 += sf[j][2] + sf[j][3];
        }
        l0 = l0 * corr0 + ls0;
        l1 = l1 * corr1 + ls1;
        #pragma unroll
        for (int j = 0; j < 8; j++) {
            acc[j][0] *= corr0; acc[j][1] *= corr0;
            acc[j][2] *= corr1; acc[j][3] *= corr1;
        }

        // --- PV ---
        #pragma unroll
        for (int t = 0; t < 4; t++) {
            uint32_t aph[4];
            aph[0] = pack_h2(sf[2*t][0],   sf[2*t][1]);
            aph[1] = pack_h2(sf[2*t][2],   sf[2*t][3]);
            aph[2] = pack_h2(sf[2*t+1][0], sf[2*t+1][1]);
            aph[3] = pack_h2(sf[2*t+1][2], sf[2*t+1][3]);
            #pragma unroll
            for (int jj = 0; jj < 4; jj++) {
                uint32_t vh[4];
                uint32_t off = vb_off + t * 16 * ROWB + jj * 32;
                ldmatrix_x4_t(vh[0], vh[1], vh[2], vh[3], svh + off);
                mma_f16(acc[2*jj],   aph[0], aph[1], aph[2], aph[3], vh[0], vh[1]);
                mma_f16(acc[2*jj+1], aph[0], aph[1], aph[2], aph[3], vh[2], vh[3]);
            }
        }
    }

    // --- final normalize + write ctx plane ---
    l0 += __shfl_xor_sync(0xffffffffu, l0, 1);
    l0 += __shfl_xor_sync(0xffffffffu, l0, 2);
    l1 += __shfl_xor_sync(0xffffffffu, l1, 1);
    l1 += __shfl_xor_sync(0xffffffffu, l1, 2);
    float inv0 = 1.0f / l0, inv1 = 1.0f / l1;

    size_t rb0 = (size_t)(b * SEQ + row0g) * DM;
    size_t rb1 = rb0 + 8 * DM;
    int dcol = h * DH + colbase;
    #pragma unroll
    for (int j = 0; j < 8; j++) {
        int d = dcol + 8 * j;
        *(uint32_t*)&Ch[rb0 + d] = pack_h2(acc[j][0] * inv0, acc[j][1] * inv0);
        *(uint32_t*)&Ch[rb1 + d] = pack_h2(acc[j][2] * inv1, acc[j][3] * inv1);
    }
}

// ---------------------------------------------------------------------------
// Launch
// ---------------------------------------------------------------------------
extern "C" void kernel_launch(void* const* d_in, const int* in_sizes, int n_in,
                              void* d_out, int out_size)
{
    const float* x  = (const float*)d_in[0];
    const float* Wq = (const float*)d_in[1];
    const float* Wk = (const float*)d_in[2];
    const float* Wv = (const float*)d_in[3];
    const float* Wo = (const float*)d_in[4];
    float* out = (float*)d_out;

    __half *px1, *pWct, *pWot, *pCh, *pQh;
    cudaGetSymbolAddress((void**)&px1, g_x1);
    cudaGetSymbolAddress((void**)&pWct, g_Wct);
    cudaGetSymbolAddress((void**)&pWot, g_Wot);
    cudaGetSymbolAddress((void**)&pCh, g_Ch);
    cudaGetSymbolAddress((void**)&pQh, g_Qh);

    // Weight transposes
    {
        dim3 blk(32, 8);
        transpose_qkv<<<dim3(48, 32), blk>>>(Wq, Wk, Wv, pWct);
        transpose_wo<<<dim3(32, 32), blk>>>(Wo, pWot);
    }

    // x -> fp16
    convert_rows<<<1024, 256>>>(x, px1, MTOK * DM / 2);

    // QKV projection GEMM (fp16 single, Kg=1024) -> fp16 plane
    cudaFuncSetAttribute(mma_gemm<1>, cudaFuncAttributeMaxDynamicSharedMemorySize, GEMM_SMEM);
    cudaFuncSetAttribute(mma_gemm<0>, cudaFuncAttributeMaxDynamicSharedMemorySize, GEMM_SMEM);
    {
        dim3 g(NQKV / BN, MTOK / BM);
        mma_gemm<1><<<g, 256, GEMM_SMEM>>>(px1, pWct, nullptr, pQh, MTOK, NQKV, DM);
    }

    // RoPE on plane
    {
        int total = MTOK * 20 * 32;
        rope_kernel<<<(total + 255) / 256, 256>>>(pQh);
    }

    // Flash attention -> ctx plane
    {
        cudaFuncSetAttribute(attn_mma,
                             cudaFuncAttributeMaxDynamicSharedMemorySize,
                             ATTN_SMEM);
        dim3 ga(SEQ / 128, NHEAD, BATCH);
        attn_mma<<<ga, 256, ATTN_SMEM>>>(pQh, pCh);
    }

    // Output projection GEMM (fp16 single, Kg=1024) -> fp32 out
    {
        dim3 g(DM / BN, MTOK / BM);
        mma_gemm<0><<<g, 256, GEMM_SMEM>>>(pCh, pWot, out, nullptr, MTOK, DM, DM);
    }
}

// round 12
// speedup vs baseline: 3.9767x; 1.0507x over previous
#include <cuda_runtime.h>
#include <cuda_fp16.h>
#include <math.h>
#include <cstdint>

#define NHEAD 16
#define NKV   4
#define DH    64
#define BATCH 2
#define SEQ   2048
#define MTOK  (BATCH*SEQ)     // 4096
#define DM    1024
#define NQKV  1536            // 1024(Q) + 256(K) + 256(V)

// ---------------------------------------------------------------------------
// Scratch (static device globals -- no allocation allowed)
// ---------------------------------------------------------------------------
__device__ __half g_x1[(size_t)MTOK * DM];       // x fp16              8 MB
__device__ __half g_Wct[(size_t)NQKV * DM];      // [Wq|Wk|Wv]^T fp16   3 MB
__device__ __half g_Wot[(size_t)DM * DM];        // Wo^T fp16           2 MB
__device__ __half g_Ch[(size_t)MTOK * DM];       // ctx plane           8 MB
__device__ __half g_Qh[(size_t)MTOK * NQKV];     // QKV plane          12 MB

// ---------------------------------------------------------------------------
// PTX helpers (portable sm_80-class)
// ---------------------------------------------------------------------------
__device__ __forceinline__ uint32_t smem_u32(const void* p) {
    return (uint32_t)__cvta_generic_to_shared(p);
}
__device__ __forceinline__ void cp_async16(uint32_t saddr, const void* gaddr) {
    asm volatile("cp.async.cg.shared.global [%0], [%1], 16;" :: "r"(saddr), "l"(gaddr));
}
__device__ __forceinline__ void cp_commit() {
    asm volatile("cp.async.commit_group;" ::: "memory");
}
template<int N>
__device__ __forceinline__ void cp_wait() {
    asm volatile("cp.async.wait_group %0;" :: "n"(N) : "memory");
}
__device__ __forceinline__ void ldmatrix_x4(uint32_t& r0, uint32_t& r1,
                                            uint32_t& r2, uint32_t& r3, uint32_t a) {
    asm volatile("ldmatrix.sync.aligned.m8n8.x4.shared.b16 {%0,%1,%2,%3}, [%4];"
                 : "=r"(r0), "=r"(r1), "=r"(r2), "=r"(r3) : "r"(a));
}
__device__ __forceinline__ void ldmatrix_x4_t(uint32_t& r0, uint32_t& r1,
                                              uint32_t& r2, uint32_t& r3, uint32_t a) {
    asm volatile("ldmatrix.sync.aligned.m8n8.x4.trans.shared.b16 {%0,%1,%2,%3}, [%4];"
                 : "=r"(r0), "=r"(r1), "=r"(r2), "=r"(r3) : "r"(a));
}
__device__ __forceinline__ void mma_f16(float* c, uint32_t a0, uint32_t a1,
                                        uint32_t a2, uint32_t a3,
                                        uint32_t b0, uint32_t b1) {
    asm volatile("mma.sync.aligned.m16n8k16.row.col.f32.f16.f16.f32 "
                 "{%0,%1,%2,%3}, {%4,%5,%6,%7}, {%8,%9}, {%0,%1,%2,%3};"
                 : "+f"(c[0]), "+f"(c[1]), "+f"(c[2]), "+f"(c[3])
                 : "r"(a0), "r"(a1), "r"(a2), "r"(a3), "r"(b0), "r"(b1));
}
__device__ __forceinline__ float ex2(float x) {
    float r; asm("ex2.approx.f32 %0, %1;" : "=f"(r) : "f"(x)); return r;
}
__device__ __forceinline__ uint32_t pack_h2(float x, float y) {
    __half2 t = __floats2half2_rn(x, y);
    return *reinterpret_cast<uint32_t*>(&t);
}

// ---------------------------------------------------------------------------
// Prep: fp32 -> fp16 convert (vectorized)
// ---------------------------------------------------------------------------
__global__ void convert_rows(const float* __restrict__ in, __half* __restrict__ out,
                             int n2)
{
    for (int i = blockIdx.x * blockDim.x + threadIdx.x; i < n2; i += gridDim.x * blockDim.x) {
        float2 v = ((const float2*)in)[i];
        ((__half2*)out)[i] = __floats2half2_rn(v.x, v.y);
    }
}

// Fused weight transpose: blocks 0..47 -> Wq|Wk|Wv into outc[1536][1024],
// blocks 48..79 -> Wo into outo[1024][1024]. All fp16 single.
__global__ void transpose_all(const float* __restrict__ Wq,
                              const float* __restrict__ Wk,
                              const float* __restrict__ Wv,
                              const float* __restrict__ Wo,
                              __half* __restrict__ outc,
                              __half* __restrict__ outo)
{
    __shared__ float t[32][33];
    int bx = blockIdx.x;
    int k0 = blockIdx.y * 32;
    int tx = threadIdx.x, ty = threadIdx.y;

    const float* W;
    __half* out;
    int Ndim, nloc, n0;
    if (bx < 32)      { W = Wq; out = outc; Ndim = 1024; n0 = bx * 32;         nloc = n0; }
    else if (bx < 40) { W = Wk; out = outc; Ndim = 256;  n0 = bx * 32;         nloc = n0 - 1024; }
    else if (bx < 48) { W = Wv; out = outc; Ndim = 256;  n0 = bx * 32;         nloc = n0 - 1280; }
    else              { W = Wo; out = outo; Ndim = 1024; n0 = (bx - 48) * 32;  nloc = n0; }

    #pragma unroll
    for (int i = 0; i < 32; i += 8)
        t[ty + i][tx] = W[(size_t)(k0 + ty + i) * Ndim + (nloc + tx)];
    __syncthreads();
    #pragma unroll
    for (int i = 0; i < 32; i += 8)
        out[(size_t)(n0 + ty + i) * DM + (k0 + tx)] = __float2half_rn(t[tx][ty + i]);
}

// ---------------------------------------------------------------------------
// fp16 tensor-core GEMM, BKK=64, 3-stage cp.async, one barrier per K64 iter.
// C[M,N] = A[M,Kg] @ B[N,Kg]^T.
// OUT_MODE 0: fp32 C.  OUT_MODE 1: fp16 plane, with fused RoPE on
//             output tiles whose global col < 1280 (Q and K heads).
// ---------------------------------------------------------------------------
#define BM 128
#define BN 128
#define BKK 64
#define LDS_ROW 72                          // elements (144 B rows)
#define GEMM_BUF (BM * LDS_ROW * 2)         // 18432 B per operand-stage
#define GEMM_SMEM (6 * GEMM_BUF)            // 110592

template<int OUT_MODE>
__global__ __launch_bounds__(256, 2) void mma_gemm(
    const __half* __restrict__ A, const __half* __restrict__ B,
    float* __restrict__ C, __half* __restrict__ Chi, int M, int N, int Kg)
{
    extern __shared__ char gsm[];
    uint32_t sabase = smem_u32(gsm);

    int tid = threadIdx.x;
    int lane = tid & 31;
    int wid = tid >> 5;
    int wm = wid & 3;
    int wn = wid >> 2;
    int m0 = blockIdx.y * BM;
    int n0 = blockIdx.x * BN;

    const __half* Ag = A + (size_t)m0 * Kg;
    const __half* Bg = B + (size_t)n0 * Kg;

    float acc[2][8][4];
    #pragma unroll
    for (int i = 0; i < 2; i++)
        #pragma unroll
        for (int j = 0; j < 8; j++)
            #pragma unroll
            for (int q = 0; q < 4; q++) acc[i][j][q] = 0.0f;

    const int nk = Kg / BKK;

    // per-stage load: 128 rows x 64 elems per operand = 1024 chunks, 4/thread
    auto issue = [&](int kt, int s) {
        int kg = kt * BKK;
        uint32_t sa = sabase + s * GEMM_BUF;
        uint32_t sb = sabase + (3 + s) * GEMM_BUF;
        #pragma unroll
        for (int it = 0; it < 4; it++) {
            int idx = tid + it * 256;
            int r = idx >> 3, c = idx & 7;
            cp_async16(sa + (r * LDS_ROW + c * 8) * 2, Ag + (size_t)r * Kg + kg + c * 8);
            cp_async16(sb + (r * LDS_ROW + c * 8) * 2, Bg + (size_t)r * Kg + kg + c * 8);
        }
        cp_commit();
    };

    issue(0, 0);
    issue(1, 1);

    int a_row = wm * 32 + (lane & 15);
    int a_colp = (lane >> 4) * 8;
    int b_row = wn * 64 + (lane & 7) + ((lane >> 4) << 3);
    int b_colp = ((lane >> 3) & 1) * 8;

    int buf = 0;
    for (int kt = 0; kt < nk; kt++) {
        if (kt + 1 < nk) { cp_wait<1>(); } else { cp_wait<0>(); }
        __syncthreads();
        if (kt + 2 < nk) issue(kt + 2, (kt + 2) % 3);

        uint32_t sa = sabase + buf * GEMM_BUF;
        uint32_t sb = sabase + (3 + buf) * GEMM_BUF;
        #pragma unroll
        for (int k16 = 0; k16 < 4; k16++) {
            uint32_t af[2][4];
            #pragma unroll
            for (int mi = 0; mi < 2; mi++) {
                uint32_t addr = sa + (((a_row + mi * 16) * LDS_ROW) + k16 * 16 + a_colp) * 2;
                ldmatrix_x4(af[mi][0], af[mi][1], af[mi][2], af[mi][3], addr);
            }
            uint32_t bfr[4][4];
            #pragma unroll
            for (int ni2 = 0; ni2 < 4; ni2++) {
                uint32_t addr = sb + (((b_row + ni2 * 16) * LDS_ROW) + k16 * 16 + b_colp) * 2;
                ldmatrix_x4(bfr[ni2][0], bfr[ni2][1], bfr[ni2][2], bfr[ni2][3], addr);
            }
            #pragma unroll
            for (int mi = 0; mi < 2; mi++)
                #pragma unroll
                for (int ni = 0; ni < 8; ni++) {
                    uint32_t bb0 = bfr[ni >> 1][(ni & 1) * 2];
                    uint32_t bb1 = bfr[ni >> 1][(ni & 1) * 2 + 1];
                    mma_f16(acc[mi][ni], af[mi][0], af[mi][1], af[mi][2], af[mi][3], bb0, bb1);
                }
        }
        buf = (buf + 1 == 3) ? 0 : buf + 1;
    }

    int cr = lane >> 2;
    int cc = (lane & 3) * 2;

    // --- fused RoPE (OUT_MODE 1, Q/K tiles only): pairs (i, i+32) live at
    // acc[mi][ni][q] <-> acc[mi][ni+4][q]; i = ni*8 + cc + (q&1) < 32. ---
    if (OUT_MODE == 1 && n0 < 1280) {
        #pragma unroll
        for (int mi = 0; mi < 2; mi++) {
            int r0 = m0 + wm * 32 + mi * 16 + cr;
            int s0 = r0 & (SEQ - 1);
            int s1 = (r0 + 8) & (SEQ - 1);
            #pragma unroll
            for (int ni = 0; ni < 4; ni++) {
                #pragma unroll
                for (int q = 0; q < 4; q++) {
                    int i = ni * 8 + cc + (q & 1);
                    int s = (q < 2) ? s0 : s1;
                    float ang = (float)s * exp10f(-(float)i * 0.125f);
                    float cs = cosf(ang), sn = sinf(ang);
                    float x0 = acc[mi][ni][q], x1 = acc[mi][ni + 4][q];
                    acc[mi][ni][q]     = x0 * cs - x1 * sn;
                    acc[mi][ni + 4][q] = x1 * cs + x0 * sn;
                }
            }
        }
    }

    #pragma unroll
    for (int mi = 0; mi < 2; mi++) {
        #pragma unroll
        for (int ni = 0; ni < 8; ni++) {
            int row = m0 + wm * 32 + mi * 16 + cr;
            int col = n0 + wn * 64 + ni * 8 + cc;
            if (OUT_MODE == 0) {
                *(float2*)&C[(size_t)row * N + col] =
                    make_float2(acc[mi][ni][0], acc[mi][ni][1]);
                *(float2*)&C[(size_t)(row + 8) * N + col] =
                    make_float2(acc[mi][ni][2], acc[mi][ni][3]);
            } else {
                *(uint32_t*)&Chi[(size_t)row * N + col] =
                    pack_h2(acc[mi][ni][0], acc[mi][ni][1]);
                *(uint32_t*)&Chi[(size_t)(row + 8) * N + col] =
                    pack_h2(acc[mi][ni][2], acc[mi][ni][3]);
            }
        }
    }
}

// ---------------------------------------------------------------------------
// fp16 tensor-core flash attention. Q, K, V single fp16. Double-buffered KV,
// one barrier per KV-iteration. Writes ctx plane into g_Ch.
// ---------------------------------------------------------------------------
#define AROW 72
#define ROWB (AROW*2)          // 144 bytes per row
#define SQ_HI 0
#define SKV0  (128*ROWB)       // 18432
#define KVSTG (2*64*ROWB)      // 18432 per stage (K,V)
#define ATTN_SMEM (SKV0 + 2*KVSTG)   // 55296

__global__ __launch_bounds__(256) void attn_mma(
    const __half* __restrict__ Phi, __half* __restrict__ Ch)
{
    extern __shared__ char smc[];
    uint32_t sb = smem_u32(smc);

    int qt = (int)gridDim.x - 1 - (int)blockIdx.x;
    int h  = blockIdx.y;
    int b  = blockIdx.z;
    int kh = h >> 2;

    int tid  = threadIdx.x;
    int lane = tid & 31;
    int wm   = tid >> 5;

    const int kcol = 1024 + kh * DH;
    const int vcol = 1280 + kh * DH;

    {
        #pragma unroll
        for (int it = 0; it < 4; it++) {
            int idx = tid + it * 256;
            int r = idx >> 3, c = idx & 7;
            const __half* src = Phi
                + (size_t)(b * SEQ + qt * 128 + r) * NQKV + h * DH + c * 8;
            cp_async16(sb + SQ_HI + r * ROWB + c * 16, src);
        }
        #pragma unroll
        for (int it = 0; it < 4; it++) {
            int idx = tid + it * 256;
            int sel = idx >> 9;
            int j = idx & 511;
            int r = j >> 3, c = j & 7;
            int colb = (sel == 0) ? kcol : vcol;
            const __half* src = Phi + (size_t)(b * SEQ + r) * NQKV + colb + c * 8;
            uint32_t dst = sb + SKV0 + sel * (64 * ROWB) + r * ROWB + c * 16;
            cp_async16(dst, src);
        }
        cp_commit();
    }

    uint32_t qa_off = (uint32_t)((wm * 16 + (lane & 7) + ((lane >> 3) & 1) * 8) * ROWB
                                 + (lane >> 4) * 16);
    uint32_t kb_off = (uint32_t)(((lane & 7) + (lane >> 4) * 8) * ROWB
                                 + ((lane >> 3) & 1) * 16);
    uint32_t vb_off = (uint32_t)(((lane & 7) + ((lane >> 3) & 1) * 8) * ROWB
                                 + (lane >> 4) * 16);

    float acc[8][4];
    #pragma unroll
    for (int j = 0; j < 8; j++)
        #pragma unroll
        for (int q = 0; q < 4; q++) acc[j][q] = 0.0f;
    float m0 = -1e30f, m1 = -1e30f, l0 = 0.0f, l1 = 0.0f;

    const float SCL = 0.125f * 1.44269504f;
    int row0g = qt * 128 + wm * 16 + (lane >> 2);
    int colbase = 2 * (lane & 3);

    int nkt = 2 * qt + 2;
    for (int kt = 0; kt < nkt; kt++) {
        cp_wait<0>();
        __syncthreads();
        if (kt + 1 < nkt) {
            int stg = (kt + 1) & 1;
            #pragma unroll
            for (int it = 0; it < 4; it++) {
                int idx = tid + it * 256;
                int sel = idx >> 9;
                int j = idx & 511;
                int r = j >> 3, c = j & 7;
                int colb = (sel == 0) ? kcol : vcol;
                const __half* src = Phi
                    + (size_t)(b * SEQ + (kt + 1) * 64 + r) * NQKV + colb + c * 8;
                uint32_t dst = sb + SKV0 + stg * KVSTG + sel * (64 * ROWB) + r * ROWB + c * 16;
                cp_async16(dst, src);
            }
            cp_commit();
        }

        uint32_t kvb = sb + SKV0 + (kt & 1) * KVSTG;
        uint32_t skh = kvb;
        uint32_t svh = kvb + 64 * ROWB;

        float sf[8][4];
        #pragma unroll
        for (int j = 0; j < 8; j++)
            #pragma unroll
            for (int q = 0; q < 4; q++) sf[j][q] = 0.0f;

        #pragma unroll
        for (int t = 0; t < 4; t++) {
            uint32_t qh[4];
            ldmatrix_x4(qh[0], qh[1], qh[2], qh[3], sb + SQ_HI + qa_off + t * 32);
            #pragma unroll
            for (int jj = 0; jj < 4; jj++) {
                uint32_t kmh[4];
                uint32_t off = kb_off + jj * 16 * ROWB + t * 32;
                ldmatrix_x4(kmh[0], kmh[1], kmh[2], kmh[3], skh + off);
                mma_f16(sf[2*jj],   qh[0], qh[1], qh[2], qh[3], kmh[0], kmh[1]);
                mma_f16(sf[2*jj+1], qh[0], qh[1], qh[2], qh[3], kmh[2], kmh[3]);
            }
        }

        bool need_mask = (kt * 64 + 63 > qt * 128 + wm * 16);
        if (need_mask) {
            #pragma unroll
            for (int j = 0; j < 8; j++) {
                int c0 = kt * 64 + 8 * j + colbase;
                sf[j][0] = (c0     <= row0g)     ? sf[j][0] * SCL : -1e30f;
                sf[j][1] = (c0 + 1 <= row0g)     ? sf[j][1] * SCL : -1e30f;
                sf[j][2] = (c0     <= row0g + 8) ? sf[j][2] * SCL : -1e30f;
                sf[j][3] = (c0 + 1 <= row0g + 8) ? sf[j][3] * SCL : -1e30f;
            }
        } else {
            #pragma unroll
            for (int j = 0; j < 8; j++)
                #pragma unroll
                for (int q = 0; q < 4; q++) sf[j][q] *= SCL;
        }

        float mx0 = m0, mx1 = m1;
        #pragma unroll
        for (int j = 0; j < 8; j++) {
            mx0 = fmaxf(mx0, fmaxf(sf[j][0], sf[j][1]));
            mx1 = fmaxf(mx1, fmaxf(sf[j][2], sf[j][3]));
        }
        mx0 = fmaxf(mx0, __shfl_xor_sync(0xffffffffu, mx0, 1));
        mx0 = fmaxf(mx0, __shfl_xor_sync(0xffffffffu, mx0, 2));
        mx1 = fmaxf(mx1, __shfl_xor_sync(0xffffffffu, mx1, 1));
        mx1 = fmaxf(mx1, __shfl_xor_sync(0xffffffffu, mx1, 2));
        float corr0 = ex2(m0 - mx0);
        float corr1 = ex2(m1 - mx1);
        m0 = mx0; m1 = mx1;

        float ls0 = 0.0f, ls1 = 0.0f;
        #pragma unroll
        for (int j = 0; j < 8; j++) {
            sf[j][0] = ex2(sf[j][0] - mx0);
            sf[j][1] = ex2(sf[j][1] - mx0);
            sf[j][2] = ex2(sf[j][2] - mx1);
            sf[j][3] = ex2(sf[j][3] - mx1);
            ls0 += sf[j][0] + sf[j][1];
            ls1 += sf[j][2] + sf[j][3];
        }
        l0 = l0 * corr0 + ls0;
        l1 = l1 * corr1 + ls1;
        #pragma unroll
        for (int j = 0; j < 8; j++) {
            acc[j][0] *= corr0; acc[j][1] *= corr0;
            acc[j][2] *= corr1; acc[j][3] *= corr1;
        }

        #pragma unroll
        for (int t = 0; t < 4; t++) {
            uint32_t aph[4];
            aph[0] = pack_h2(sf[2*t][0],   sf[2*t][1]);
            aph[1] = pack_h2(sf[2*t][2],   sf[2*t][3]);
            aph[2] = pack_h2(sf[2*t+1][0], sf[2*t+1][1]);
            aph[3] = pack_h2(sf[2*t+1][2], sf[2*t+1][3]);
            #pragma unroll
            for (int jj = 0; jj < 4; jj++) {
                uint32_t vh[4];
                uint32_t off = vb_off + t * 16 * ROWB + jj * 32;
                ldmatrix_x4_t(vh[0], vh[1], vh[2], vh[3], svh + off);
                mma_f16(acc[2*jj],   aph[0], aph[1], aph[2], aph[3], vh[0], vh[1]);
                mma_f16(acc[2*jj+1], aph[0], aph[1], aph[2], aph[3], vh[2], vh[3]);
            }
        }
    }

    l0 += __shfl_xor_sync(0xffffffffu, l0, 1);
    l0 += __shfl_xor_sync(0xffffffffu, l0, 2);
    l1 += __shfl_xor_sync(0xffffffffu, l1, 1);
    l1 += __shfl_xor_sync(0xffffffffu, l1, 2);
    float inv0 = 1.0f / l0, inv1 = 1.0f / l1;

    size_t rb0 = (size_t)(b * SEQ + row0g) * DM;
    size_t rb1 = rb0 + 8 * DM;
    int dcol = h * DH + colbase;
    #pragma unroll
    for (int j = 0; j < 8; j++) {
        int d = dcol + 8 * j;
        *(uint32_t*)&Ch[rb0 + d] = pack_h2(acc[j][0] * inv0, acc[j][1] * inv0);
        *(uint32_t*)&Ch[rb1 + d] = pack_h2(acc[j][2] * inv1, acc[j][3] * inv1);
    }
}

// ---------------------------------------------------------------------------
// Launch
// ---------------------------------------------------------------------------
extern "C" void kernel_launch(void* const* d_in, const int* in_sizes, int n_in,
                              void* d_out, int out_size)
{
    const float* x  = (const float*)d_in[0];
    const float* Wq = (const float*)d_in[1];
    const float* Wk = (const float*)d_in[2];
    const float* Wv = (const float*)d_in[3];
    const float* Wo = (const float*)d_in[4];
    float* out = (float*)d_out;

    __half *px1, *pWct, *pWot, *pCh, *pQh;
    cudaGetSymbolAddress((void**)&px1, g_x1);
    cudaGetSymbolAddress((void**)&pWct, g_Wct);
    cudaGetSymbolAddress((void**)&pWot, g_Wot);
    cudaGetSymbolAddress((void**)&pCh, g_Ch);
    cudaGetSymbolAddress((void**)&pQh, g_Qh);

    // All weight transposes in one launch
    {
        dim3 blk(32, 8);
        transpose_all<<<dim3(80, 32), blk>>>(Wq, Wk, Wv, Wo, pWct, pWot);
    }

    // x -> fp16
    convert_rows<<<1024, 256>>>(x, px1, MTOK * DM / 2);

    // QKV projection GEMM with fused RoPE -> fp16 plane
    cudaFuncSetAttribute(mma_gemm<1>, cudaFuncAttributeMaxDynamicSharedMemorySize, GEMM_SMEM);
    cudaFuncSetAttribute(mma_gemm<0>, cudaFuncAttributeMaxDynamicSharedMemorySize, GEMM_SMEM);
    {
        dim3 g(NQKV / BN, MTOK / BM);
        mma_gemm<1><<<g, 256, GEMM_SMEM>>>(px1, pWct, nullptr, pQh, MTOK, NQKV, DM);
    }

    // Flash attention -> ctx plane
    {
        cudaFuncSetAttribute(attn_mma,
                             cudaFuncAttributeMaxDynamicSharedMemorySize,
                             ATTN_SMEM);
        dim3 ga(SEQ / 128, NHEAD, BATCH);
        attn_mma<<<ga, 256, ATTN_SMEM>>>(pQh, pCh);
    }

    // Output projection GEMM -> fp32 out
    {
        dim3 g(DM / BN, MTOK / BM);
        mma_gemm<0><<<g, 256, GEMM_SMEM>>>(pCh, pWot, out, nullptr, MTOK, DM, DM);
    }
}

// round 13
// speedup vs baseline: 4.1172x; 1.0353x over previous
#include <cuda_runtime.h>
#include <cuda_fp16.h>
#include <math.h>
#include <cstdint>

#define NHEAD 16
#define NKV   4
#define DH    64
#define BATCH 2
#define SEQ   2048
#define MTOK  (BATCH*SEQ)     // 4096
#define DM    1024
#define NQKV  1536            // 1024(Q) + 256(K) + 256(V)

// ---------------------------------------------------------------------------
// Scratch (static device globals -- no allocation allowed)
// ---------------------------------------------------------------------------
__device__ __half g_x1[(size_t)MTOK * DM];       // x fp16              8 MB
__device__ __half g_Wct[(size_t)NQKV * DM];      // [Wq|Wk|Wv]^T fp16   3 MB
__device__ __half g_Wot[(size_t)DM * DM];        // Wo^T fp16           2 MB
__device__ __half g_Ch[(size_t)MTOK * DM];       // ctx plane           8 MB
__device__ __half g_Qh[(size_t)MTOK * NQKV];     // QKV plane          12 MB

// ---------------------------------------------------------------------------
// PTX helpers (portable sm_80-class)
// ---------------------------------------------------------------------------
__device__ __forceinline__ uint32_t smem_u32(const void* p) {
    return (uint32_t)__cvta_generic_to_shared(p);
}
__device__ __forceinline__ void cp_async16(uint32_t saddr, const void* gaddr) {
    asm volatile("cp.async.cg.shared.global [%0], [%1], 16;" :: "r"(saddr), "l"(gaddr));
}
__device__ __forceinline__ void cp_commit() {
    asm volatile("cp.async.commit_group;" ::: "memory");
}
template<int N>
__device__ __forceinline__ void cp_wait() {
    asm volatile("cp.async.wait_group %0;" :: "n"(N) : "memory");
}
__device__ __forceinline__ void ldmatrix_x4(uint32_t& r0, uint32_t& r1,
                                            uint32_t& r2, uint32_t& r3, uint32_t a) {
    asm volatile("ldmatrix.sync.aligned.m8n8.x4.shared.b16 {%0,%1,%2,%3}, [%4];"
                 : "=r"(r0), "=r"(r1), "=r"(r2), "=r"(r3) : "r"(a));
}
__device__ __forceinline__ void ldmatrix_x4_t(uint32_t& r0, uint32_t& r1,
                                              uint32_t& r2, uint32_t& r3, uint32_t a) {
    asm volatile("ldmatrix.sync.aligned.m8n8.x4.trans.shared.b16 {%0,%1,%2,%3}, [%4];"
                 : "=r"(r0), "=r"(r1), "=r"(r2), "=r"(r3) : "r"(a));
}
__device__ __forceinline__ void mma_f16(float* c, uint32_t a0, uint32_t a1,
                                        uint32_t a2, uint32_t a3,
                                        uint32_t b0, uint32_t b1) {
    asm volatile("mma.sync.aligned.m16n8k16.row.col.f32.f16.f16.f32 "
                 "{%0,%1,%2,%3}, {%4,%5,%6,%7}, {%8,%9}, {%0,%1,%2,%3};"
                 : "+f"(c[0]), "+f"(c[1]), "+f"(c[2]), "+f"(c[3])
                 : "r"(a0), "r"(a1), "r"(a2), "r"(a3), "r"(b0), "r"(b1));
}
__device__ __forceinline__ float ex2(float x) {
    float r; asm("ex2.approx.f32 %0, %1;" : "=f"(r) : "f"(x)); return r;
}
__device__ __forceinline__ uint32_t pack_h2(float x, float y) {
    __half2 t = __floats2half2_rn(x, y);
    return *reinterpret_cast<uint32_t*>(&t);
}

// ---------------------------------------------------------------------------
// Prep: fp32 -> fp16 convert (vectorized)
// ---------------------------------------------------------------------------
__global__ void convert_rows(const float* __restrict__ in, __half* __restrict__ out,
                             int n2)
{
    for (int i = blockIdx.x * blockDim.x + threadIdx.x; i < n2; i += gridDim.x * blockDim.x) {
        float2 v = ((const float2*)in)[i];
        ((__half2*)out)[i] = __floats2half2_rn(v.x, v.y);
    }
}

// Fused weight transpose: blocks 0..47 -> Wq|Wk|Wv into outc[1536][1024],
// blocks 48..79 -> Wo into outo[1024][1024]. All fp16 single.
__global__ void transpose_all(const float* __restrict__ Wq,
                              const float* __restrict__ Wk,
                              const float* __restrict__ Wv,
                              const float* __restrict__ Wo,
                              __half* __restrict__ outc,
                              __half* __restrict__ outo)
{
    __shared__ float t[32][33];
    int bx = blockIdx.x;
    int k0 = blockIdx.y * 32;
    int tx = threadIdx.x, ty = threadIdx.y;

    const float* W;
    __half* out;
    int Ndim, nloc, n0;
    if (bx < 32)      { W = Wq; out = outc; Ndim = 1024; n0 = bx * 32;         nloc = n0; }
    else if (bx < 40) { W = Wk; out = outc; Ndim = 256;  n0 = bx * 32;         nloc = n0 - 1024; }
    else if (bx < 48) { W = Wv; out = outc; Ndim = 256;  n0 = bx * 32;         nloc = n0 - 1280; }
    else              { W = Wo; out = outo; Ndim = 1024; n0 = (bx - 48) * 32;  nloc = n0; }

    #pragma unroll
    for (int i = 0; i < 32; i += 8)
        t[ty + i][tx] = W[(size_t)(k0 + ty + i) * Ndim + (nloc + tx)];
    __syncthreads();
    #pragma unroll
    for (int i = 0; i < 32; i += 8)
        out[(size_t)(n0 + ty + i) * DM + (k0 + tx)] = __float2half_rn(t[tx][ty + i]);
}

// ---------------------------------------------------------------------------
// fp16 tensor-core GEMM, BKK=64, 3-stage cp.async, one barrier per K64 iter.
// OUT_MODE 0: fp32 C.  OUT_MODE 1: fp16 plane, fused RoPE on cols<1280,
//             fused softmax scale (0.125*log2e) on Q cols<1024.
// ---------------------------------------------------------------------------
#define BM 128
#define BN 128
#define BKK 64
#define LDS_ROW 72                          // elements (144 B rows)
#define GEMM_BUF (BM * LDS_ROW * 2)         // 18432 B per operand-stage
#define GEMM_SMEM (6 * GEMM_BUF)            // 110592

template<int OUT_MODE>
__global__ __launch_bounds__(256, 2) void mma_gemm(
    const __half* __restrict__ A, const __half* __restrict__ B,
    float* __restrict__ C, __half* __restrict__ Chi, int M, int N, int Kg)
{
    extern __shared__ char gsm[];
    uint32_t sabase = smem_u32(gsm);

    int tid = threadIdx.x;
    int lane = tid & 31;
    int wid = tid >> 5;
    int wm = wid & 3;
    int wn = wid >> 2;
    int m0 = blockIdx.y * BM;
    int n0 = blockIdx.x * BN;

    const __half* Ag = A + (size_t)m0 * Kg;
    const __half* Bg = B + (size_t)n0 * Kg;

    float acc[2][8][4];
    #pragma unroll
    for (int i = 0; i < 2; i++)
        #pragma unroll
        for (int j = 0; j < 8; j++)
            #pragma unroll
            for (int q = 0; q < 4; q++) acc[i][j][q] = 0.0f;

    const int nk = Kg / BKK;

    auto issue = [&](int kt, int s) {
        int kg = kt * BKK;
        uint32_t sa = sabase + s * GEMM_BUF;
        uint32_t sb = sabase + (3 + s) * GEMM_BUF;
        #pragma unroll
        for (int it = 0; it < 4; it++) {
            int idx = tid + it * 256;
            int r = idx >> 3, c = idx & 7;
            cp_async16(sa + (r * LDS_ROW + c * 8) * 2, Ag + (size_t)r * Kg + kg + c * 8);
            cp_async16(sb + (r * LDS_ROW + c * 8) * 2, Bg + (size_t)r * Kg + kg + c * 8);
        }
        cp_commit();
    };

    issue(0, 0);
    issue(1, 1);

    int a_row = wm * 32 + (lane & 15);
    int a_colp = (lane >> 4) * 8;
    int b_row = wn * 64 + (lane & 7) + ((lane >> 4) << 3);
    int b_colp = ((lane >> 3) & 1) * 8;

    int buf = 0;
    for (int kt = 0; kt < nk; kt++) {
        if (kt + 1 < nk) { cp_wait<1>(); } else { cp_wait<0>(); }
        __syncthreads();
        if (kt + 2 < nk) issue(kt + 2, (kt + 2) % 3);

        uint32_t sa = sabase + buf * GEMM_BUF;
        uint32_t sb = sabase + (3 + buf) * GEMM_BUF;
        #pragma unroll
        for (int k16 = 0; k16 < 4; k16++) {
            uint32_t af[2][4];
            #pragma unroll
            for (int mi = 0; mi < 2; mi++) {
                uint32_t addr = sa + (((a_row + mi * 16) * LDS_ROW) + k16 * 16 + a_colp) * 2;
                ldmatrix_x4(af[mi][0], af[mi][1], af[mi][2], af[mi][3], addr);
            }
            uint32_t bfr[4][4];
            #pragma unroll
            for (int ni2 = 0; ni2 < 4; ni2++) {
                uint32_t addr = sb + (((b_row + ni2 * 16) * LDS_ROW) + k16 * 16 + b_colp) * 2;
                ldmatrix_x4(bfr[ni2][0], bfr[ni2][1], bfr[ni2][2], bfr[ni2][3], addr);
            }
            #pragma unroll
            for (int mi = 0; mi < 2; mi++)
                #pragma unroll
                for (int ni = 0; ni < 8; ni++) {
                    uint32_t bb0 = bfr[ni >> 1][(ni & 1) * 2];
                    uint32_t bb1 = bfr[ni >> 1][(ni & 1) * 2 + 1];
                    mma_f16(acc[mi][ni], af[mi][0], af[mi][1], af[mi][2], af[mi][3], bb0, bb1);
                }
        }
        buf = (buf + 1 == 3) ? 0 : buf + 1;
    }

    int cr = lane >> 2;
    int cc = (lane & 3) * 2;

    if (OUT_MODE == 1 && n0 < 1024) {
        // fused softmax scale on Q (commutes with RoPE rotation)
        const float SCL = 0.125f * 1.44269504f;
        #pragma unroll
        for (int mi = 0; mi < 2; mi++)
            #pragma unroll
            for (int ni = 0; ni < 8; ni++)
                #pragma unroll
                for (int q = 0; q < 4; q++) acc[mi][ni][q] *= SCL;
    }

    // fused RoPE (Q and K tiles): pairs (i, i+32) at acc[mi][ni][q] <-> acc[mi][ni+4][q]
    if (OUT_MODE == 1 && n0 < 1280) {
        #pragma unroll
        for (int mi = 0; mi < 2; mi++) {
            int r0 = m0 + wm * 32 + mi * 16 + cr;
            int s0 = r0 & (SEQ - 1);
            int s1 = (r0 + 8) & (SEQ - 1);
            #pragma unroll
            for (int ni = 0; ni < 4; ni++) {
                #pragma unroll
                for (int q = 0; q < 4; q++) {
                    int i = ni * 8 + cc + (q & 1);
                    int s = (q < 2) ? s0 : s1;
                    float ang = (float)s * exp10f(-(float)i * 0.125f);
                    float cs = cosf(ang), sn = sinf(ang);
                    float x0 = acc[mi][ni][q], x1 = acc[mi][ni + 4][q];
                    acc[mi][ni][q]     = x0 * cs - x1 * sn;
                    acc[mi][ni + 4][q] = x1 * cs + x0 * sn;
                }
            }
        }
    }

    #pragma unroll
    for (int mi = 0; mi < 2; mi++) {
        #pragma unroll
        for (int ni = 0; ni < 8; ni++) {
            int row = m0 + wm * 32 + mi * 16 + cr;
            int col = n0 + wn * 64 + ni * 8 + cc;
            if (OUT_MODE == 0) {
                *(float2*)&C[(size_t)row * N + col] =
                    make_float2(acc[mi][ni][0], acc[mi][ni][1]);
                *(float2*)&C[(size_t)(row + 8) * N + col] =
                    make_float2(acc[mi][ni][2], acc[mi][ni][3]);
            } else {
                *(uint32_t*)&Chi[(size_t)row * N + col] =
                    pack_h2(acc[mi][ni][0], acc[mi][ni][1]);
                *(uint32_t*)&Chi[(size_t)(row + 8) * N + col] =
                    pack_h2(acc[mi][ni][2], acc[mi][ni][3]);
            }
        }
    }
}

// ---------------------------------------------------------------------------
// fp16 tensor-core flash attention. Q pre-scaled by 0.125*log2e (fused in
// QKV GEMM). Q fragments hoisted to registers (loop-invariant). Double-
// buffered KV, barrier after compute. Writes ctx plane into g_Ch.
// ---------------------------------------------------------------------------
#define AROW 72
#define ROWB (AROW*2)          // 144 bytes per row
#define SQ_HI 0
#define SKV0  (128*ROWB)       // 18432
#define KVSTG (2*64*ROWB)      // 18432 per stage (K,V)
#define ATTN_SMEM (SKV0 + 2*KVSTG)   // 55296

__global__ __launch_bounds__(256) void attn_mma(
    const __half* __restrict__ Phi, __half* __restrict__ Ch)
{
    extern __shared__ char smc[];
    uint32_t sb = smem_u32(smc);

    int qt = (int)gridDim.x - 1 - (int)blockIdx.x;
    int h  = blockIdx.y;
    int b  = blockIdx.z;
    int kh = h >> 2;

    int tid  = threadIdx.x;
    int lane = tid & 31;
    int wm   = tid >> 5;

    const int kcol = 1024 + kh * DH;
    const int vcol = 1280 + kh * DH;

    // --- issue Q tile + KV tile 0 ---
    {
        #pragma unroll
        for (int it = 0; it < 4; it++) {
            int idx = tid + it * 256;
            int r = idx >> 3, c = idx & 7;
            const __half* src = Phi
                + (size_t)(b * SEQ + qt * 128 + r) * NQKV + h * DH + c * 8;
            cp_async16(sb + SQ_HI + r * ROWB + c * 16, src);
        }
        #pragma unroll
        for (int it = 0; it < 4; it++) {
            int idx = tid + it * 256;
            int sel = idx >> 9;
            int j = idx & 511;
            int r = j >> 3, c = j & 7;
            int colb = (sel == 0) ? kcol : vcol;
            const __half* src = Phi + (size_t)(b * SEQ + r) * NQKV + colb + c * 8;
            uint32_t dst = sb + SKV0 + sel * (64 * ROWB) + r * ROWB + c * 16;
            cp_async16(dst, src);
        }
        cp_commit();
    }

    uint32_t qa_off = (uint32_t)((wm * 16 + (lane & 7) + ((lane >> 3) & 1) * 8) * ROWB
                                 + (lane >> 4) * 16);
    uint32_t kb_off = (uint32_t)(((lane & 7) + (lane >> 4) * 8) * ROWB
                                 + ((lane >> 3) & 1) * 16);
    uint32_t vb_off = (uint32_t)(((lane & 7) + ((lane >> 3) & 1) * 8) * ROWB
                                 + (lane >> 4) * 16);

    // wait for Q + KV0, then hoist Q fragments to registers (loop-invariant)
    cp_wait<0>();
    __syncthreads();
    uint32_t qf[4][4];
    #pragma unroll
    for (int t = 0; t < 4; t++)
        ldmatrix_x4(qf[t][0], qf[t][1], qf[t][2], qf[t][3],
                    sb + SQ_HI + qa_off + t * 32);

    float acc[8][4];
    #pragma unroll
    for (int j = 0; j < 8; j++)
        #pragma unroll
        for (int q = 0; q < 4; q++) acc[j][q] = 0.0f;
    float m0 = -1e30f, m1 = -1e30f, l0 = 0.0f, l1 = 0.0f;

    int row0g = qt * 128 + wm * 16 + (lane >> 2);
    int colbase = 2 * (lane & 3);

    int nkt = 2 * qt + 2;
    for (int kt = 0; kt < nkt; kt++) {
        // prefetch next tile (overlaps with compute below; barrier after compute)
        if (kt + 1 < nkt) {
            int stg = (kt + 1) & 1;
            #pragma unroll
            for (int it = 0; it < 4; it++) {
                int idx = tid + it * 256;
                int sel = idx >> 9;
                int j = idx & 511;
                int r = j >> 3, c = j & 7;
                int colb = (sel == 0) ? kcol : vcol;
                const __half* src = Phi
                    + (size_t)(b * SEQ + (kt + 1) * 64 + r) * NQKV + colb + c * 8;
                uint32_t dst = sb + SKV0 + stg * KVSTG + sel * (64 * ROWB) + r * ROWB + c * 16;
                cp_async16(dst, src);
            }
            cp_commit();
        }

        uint32_t kvb = sb + SKV0 + (kt & 1) * KVSTG;
        uint32_t skh = kvb;
        uint32_t svh = kvb + 64 * ROWB;

        // --- S = Q K^T (Q pre-scaled) ---
        float sf[8][4];
        #pragma unroll
        for (int j = 0; j < 8; j++)
            #pragma unroll
            for (int q = 0; q < 4; q++) sf[j][q] = 0.0f;

        #pragma unroll
        for (int t = 0; t < 4; t++) {
            #pragma unroll
            for (int jj = 0; jj < 4; jj++) {
                uint32_t kmh[4];
                uint32_t off = kb_off + jj * 16 * ROWB + t * 32;
                ldmatrix_x4(kmh[0], kmh[1], kmh[2], kmh[3], skh + off);
                mma_f16(sf[2*jj],   qf[t][0], qf[t][1], qf[t][2], qf[t][3], kmh[0], kmh[1]);
                mma_f16(sf[2*jj+1], qf[t][0], qf[t][1], qf[t][2], qf[t][3], kmh[2], kmh[3]);
            }
        }

        // --- causal mask (scores already scaled) ---
        bool need_mask = (kt * 64 + 63 > qt * 128 + wm * 16);
        if (need_mask) {
            #pragma unroll
            for (int j = 0; j < 8; j++) {
                int c0 = kt * 64 + 8 * j + colbase;
                if (c0     > row0g)     sf[j][0] = -1e30f;
                if (c0 + 1 > row0g)     sf[j][1] = -1e30f;
                if (c0     > row0g + 8) sf[j][2] = -1e30f;
                if (c0 + 1 > row0g + 8) sf[j][3] = -1e30f;
            }
        }

        // --- online softmax ---
        float mx0 = m0, mx1 = m1;
        #pragma unroll
        for (int j = 0; j < 8; j++) {
            mx0 = fmaxf(mx0, fmaxf(sf[j][0], sf[j][1]));
            mx1 = fmaxf(mx1, fmaxf(sf[j][2], sf[j][3]));
        }
        mx0 = fmaxf(mx0, __shfl_xor_sync(0xffffffffu, mx0, 1));
        mx0 = fmaxf(mx0, __shfl_xor_sync(0xffffffffu, mx0, 2));
        mx1 = fmaxf(mx1, __shfl_xor_sync(0xffffffffu, mx1, 1));
        mx1 = fmaxf(mx1, __shfl_xor_sync(0xffffffffu, mx1, 2));
        float corr0 = ex2(m0 - mx0);
        float corr1 = ex2(m1 - mx1);
        m0 = mx0; m1 = mx1;

        float ls0 = 0.0f, ls1 = 0.0f;
        #pragma unroll
        for (int j = 0; j < 8; j++) {
            sf[j][0] = ex2(sf[j][0] - mx0);
            sf[j][1] = ex2(sf[j][1] - mx0);
            sf[j][2] = ex2(sf[j][2] - mx1);
            sf[j][3] = ex2(sf[j][3] - mx1);
            ls0 += sf[j][0] + sf[j][1];
            ls1 += sf[j][2] + sf[j][3];
        }
        l0 = l0 * corr0 + ls0;
        l1 = l1 * corr1 + ls1;
        #pragma unroll
        for (int j = 0; j < 8; j++) {
            acc[j][0] *= corr0; acc[j][1] *= corr0;
            acc[j][2] *= corr1; acc[j][3] *= corr1;
        }

        // --- PV ---
        #pragma unroll
        for (int t = 0; t < 4; t++) {
            uint32_t aph[4];
            aph[0] = pack_h2(sf[2*t][0],   sf[2*t][1]);
            aph[1] = pack_h2(sf[2*t][2],   sf[2*t][3]);
            aph[2] = pack_h2(sf[2*t+1][0], sf[2*t+1][1]);
            aph[3] = pack_h2(sf[2*t+1][2], sf[2*t+1][3]);
            #pragma unroll
            for (int jj = 0; jj < 4; jj++) {
                uint32_t vh[4];
                uint32_t off = vb_off + t * 16 * ROWB + jj * 32;
                ldmatrix_x4_t(vh[0], vh[1], vh[2], vh[3], svh + off);
                mma_f16(acc[2*jj],   aph[0], aph[1], aph[2], aph[3], vh[0], vh[1]);
                mma_f16(acc[2*jj+1], aph[0], aph[1], aph[2], aph[3], vh[2], vh[3]);
            }
        }

        // barrier AFTER compute: next tile's data must be complete and all
        // warps done reading the stage that iteration kt+2 will overwrite
        if (kt + 1 < nkt) {
            cp_wait<0>();
            __syncthreads();
        }
    }

    // --- final normalize + write ctx plane ---
    l0 += __shfl_xor_sync(0xffffffffu, l0, 1);
    l0 += __shfl_xor_sync(0xffffffffu, l0, 2);
    l1 += __shfl_xor_sync(0xffffffffu, l1, 1);
    l1 += __shfl_xor_sync(0xffffffffu, l1, 2);
    float inv0 = 1.0f / l0, inv1 = 1.0f / l1;

    size_t rb0 = (size_t)(b * SEQ + row0g) * DM;
    size_t rb1 = rb0 + 8 * DM;
    int dcol = h * DH + colbase;
    #pragma unroll
    for (int j = 0; j < 8; j++) {
        int d = dcol + 8 * j;
        *(uint32_t*)&Ch[rb0 + d] = pack_h2(acc[j][0] * inv0, acc[j][1] * inv0);
        *(uint32_t*)&Ch[rb1 + d] = pack_h2(acc[j][2] * inv1, acc[j][3] * inv1);
    }
}

// ---------------------------------------------------------------------------
// Launch
// ---------------------------------------------------------------------------
extern "C" void kernel_launch(void* const* d_in, const int* in_sizes, int n_in,
                              void* d_out, int out_size)
{
    const float* x  = (const float*)d_in[0];
    const float* Wq = (const float*)d_in[1];
    const float* Wk = (const float*)d_in[2];
    const float* Wv = (const float*)d_in[3];
    const float* Wo = (const float*)d_in[4];
    float* out = (float*)d_out;

    __half *px1, *pWct, *pWot, *pCh, *pQh;
    cudaGetSymbolAddress((void**)&px1, g_x1);
    cudaGetSymbolAddress((void**)&pWct, g_Wct);
    cudaGetSymbolAddress((void**)&pWot, g_Wot);
    cudaGetSymbolAddress((void**)&pCh, g_Ch);
    cudaGetSymbolAddress((void**)&pQh, g_Qh);

    // All weight transposes in one launch
    {
        dim3 blk(32, 8);
        transpose_all<<<dim3(80, 32), blk>>>(Wq, Wk, Wv, Wo, pWct, pWot);
    }

    // x -> fp16
    convert_rows<<<1024, 256>>>(x, px1, MTOK * DM / 2);

    // QKV projection GEMM with fused RoPE + softmax scale -> fp16 plane
    cudaFuncSetAttribute(mma_gemm<1>, cudaFuncAttributeMaxDynamicSharedMemorySize, GEMM_SMEM);
    cudaFuncSetAttribute(mma_gemm<0>, cudaFuncAttributeMaxDynamicSharedMemorySize, GEMM_SMEM);
    {
        dim3 g(NQKV / BN, MTOK / BM);
        mma_gemm<1><<<g, 256, GEMM_SMEM>>>(px1, pWct, nullptr, pQh, MTOK, NQKV, DM);
    }

    // Flash attention -> ctx plane
    {
        cudaFuncSetAttribute(attn_mma,
                             cudaFuncAttributeMaxDynamicSharedMemorySize,
                             ATTN_SMEM);
        dim3 ga(SEQ / 128, NHEAD, BATCH);
        attn_mma<<<ga, 256, ATTN_SMEM>>>(pQh, pCh);
    }

    // Output projection GEMM -> fp32 out
    {
        dim3 g(DM / BN, MTOK / BM);
        mma_gemm<0><<<g, 256, GEMM_SMEM>>>(pCh, pWot, out, nullptr, MTOK, DM, DM);
    }
}

// round 14
// speedup vs baseline: 4.2462x; 1.0313x over previous
#include <cuda_runtime.h>
#include <cuda_fp16.h>
#include <math.h>
#include <cstdint>

#define NHEAD 16
#define NKV   4
#define DH    64
#define BATCH 2
#define SEQ   2048
#define MTOK  (BATCH*SEQ)     // 4096
#define DM    1024
#define NQKV  1536            // 1024(Q) + 256(K) + 256(V)

// ---------------------------------------------------------------------------
// Scratch (static device globals -- no allocation allowed)
// ---------------------------------------------------------------------------
__device__ __half g_x1[(size_t)MTOK * DM];       // x fp16              8 MB
__device__ __half g_Wct[(size_t)NQKV * DM];      // [Wq|Wk|Wv]^T fp16   3 MB
__device__ __half g_Wot[(size_t)DM * DM];        // Wo^T fp16           2 MB
__device__ __half g_Ch[(size_t)MTOK * DM];       // ctx plane           8 MB
__device__ __half g_Qh[(size_t)MTOK * NQKV];     // QKV plane          12 MB

// ---------------------------------------------------------------------------
// PTX helpers (portable sm_80-class)
// ---------------------------------------------------------------------------
__device__ __forceinline__ uint32_t smem_u32(const void* p) {
    return (uint32_t)__cvta_generic_to_shared(p);
}
__device__ __forceinline__ void cp_async16(uint32_t saddr, const void* gaddr) {
    asm volatile("cp.async.cg.shared.global [%0], [%1], 16;" :: "r"(saddr), "l"(gaddr));
}
__device__ __forceinline__ void cp_commit() {
    asm volatile("cp.async.commit_group;" ::: "memory");
}
template<int N>
__device__ __forceinline__ void cp_wait() {
    asm volatile("cp.async.wait_group %0;" :: "n"(N) : "memory");
}
__device__ __forceinline__ void ldmatrix_x4(uint32_t& r0, uint32_t& r1,
                                            uint32_t& r2, uint32_t& r3, uint32_t a) {
    asm volatile("ldmatrix.sync.aligned.m8n8.x4.shared.b16 {%0,%1,%2,%3}, [%4];"
                 : "=r"(r0), "=r"(r1), "=r"(r2), "=r"(r3) : "r"(a));
}
__device__ __forceinline__ void ldmatrix_x4_t(uint32_t& r0, uint32_t& r1,
                                              uint32_t& r2, uint32_t& r3, uint32_t a) {
    asm volatile("ldmatrix.sync.aligned.m8n8.x4.trans.shared.b16 {%0,%1,%2,%3}, [%4];"
                 : "=r"(r0), "=r"(r1), "=r"(r2), "=r"(r3) : "r"(a));
}
__device__ __forceinline__ void mma_f16(float* c, uint32_t a0, uint32_t a1,
                                        uint32_t a2, uint32_t a3,
                                        uint32_t b0, uint32_t b1) {
    asm volatile("mma.sync.aligned.m16n8k16.row.col.f32.f16.f16.f32 "
                 "{%0,%1,%2,%3}, {%4,%5,%6,%7}, {%8,%9}, {%0,%1,%2,%3};"
                 : "+f"(c[0]), "+f"(c[1]), "+f"(c[2]), "+f"(c[3])
                 : "r"(a0), "r"(a1), "r"(a2), "r"(a3), "r"(b0), "r"(b1));
}
__device__ __forceinline__ float ex2(float x) {
    float r; asm("ex2.approx.f32 %0, %1;" : "=f"(r) : "f"(x)); return r;
}
__device__ __forceinline__ uint32_t ex2_h2(uint32_t x) {
    uint32_t r; asm("ex2.approx.f16x2 %0, %1;" : "=r"(r) : "r"(x)); return r;
}
__device__ __forceinline__ uint32_t pack_h2(float x, float y) {
    __half2 t = __floats2half2_rn(x, y);
    return *reinterpret_cast<uint32_t*>(&t);
}
__device__ __forceinline__ float2 unpack_h2(uint32_t p) {
    __half2 t = *reinterpret_cast<__half2*>(&p);
    return __half22float2(t);
}

// ---------------------------------------------------------------------------
// Prep: fp32 -> fp16 convert (vectorized)
// ---------------------------------------------------------------------------
__global__ void convert_rows(const float* __restrict__ in, __half* __restrict__ out,
                             int n2)
{
    for (int i = blockIdx.x * blockDim.x + threadIdx.x; i < n2; i += gridDim.x * blockDim.x) {
        float2 v = ((const float2*)in)[i];
        ((__half2*)out)[i] = __floats2half2_rn(v.x, v.y);
    }
}

// Fused weight transpose: blocks 0..47 -> Wq|Wk|Wv into outc[1536][1024],
// blocks 48..79 -> Wo into outo[1024][1024]. All fp16 single.
__global__ void transpose_all(const float* __restrict__ Wq,
                              const float* __restrict__ Wk,
                              const float* __restrict__ Wv,
                              const float* __restrict__ Wo,
                              __half* __restrict__ outc,
                              __half* __restrict__ outo)
{
    __shared__ float t[32][33];
    int bx = blockIdx.x;
    int k0 = blockIdx.y * 32;
    int tx = threadIdx.x, ty = threadIdx.y;

    const float* W;
    __half* out;
    int Ndim, nloc, n0;
    if (bx < 32)      { W = Wq; out = outc; Ndim = 1024; n0 = bx * 32;         nloc = n0; }
    else if (bx < 40) { W = Wk; out = outc; Ndim = 256;  n0 = bx * 32;         nloc = n0 - 1024; }
    else if (bx < 48) { W = Wv; out = outc; Ndim = 256;  n0 = bx * 32;         nloc = n0 - 1280; }
    else              { W = Wo; out = outo; Ndim = 1024; n0 = (bx - 48) * 32;  nloc = n0; }

    #pragma unroll
    for (int i = 0; i < 32; i += 8)
        t[ty + i][tx] = W[(size_t)(k0 + ty + i) * Ndim + (nloc + tx)];
    __syncthreads();
    #pragma unroll
    for (int i = 0; i < 32; i += 8)
        out[(size_t)(n0 + ty + i) * DM + (k0 + tx)] = __float2half_rn(t[tx][ty + i]);
}

// ---------------------------------------------------------------------------
// fp16 tensor-core GEMM, BKK=64, 3-stage cp.async, one barrier per K64 iter.
// OUT_MODE 0: fp32 C.  OUT_MODE 1: fp16 plane, fused RoPE on cols<1280,
//             fused softmax scale (0.125*log2e) on Q cols<1024.
// ---------------------------------------------------------------------------
#define BM 128
#define BN 128
#define BKK 64
#define LDS_ROW 72                          // elements (144 B rows)
#define GEMM_BUF (BM * LDS_ROW * 2)         // 18432 B per operand-stage
#define GEMM_SMEM (6 * GEMM_BUF)            // 110592

template<int OUT_MODE>
__global__ __launch_bounds__(256, 2) void mma_gemm(
    const __half* __restrict__ A, const __half* __restrict__ B,
    float* __restrict__ C, __half* __restrict__ Chi, int M, int N, int Kg)
{
    extern __shared__ char gsm[];
    uint32_t sabase = smem_u32(gsm);

    int tid = threadIdx.x;
    int lane = tid & 31;
    int wid = tid >> 5;
    int wm = wid & 3;
    int wn = wid >> 2;
    int m0 = blockIdx.y * BM;
    int n0 = blockIdx.x * BN;

    const __half* Ag = A + (size_t)m0 * Kg;
    const __half* Bg = B + (size_t)n0 * Kg;

    float acc[2][8][4];
    #pragma unroll
    for (int i = 0; i < 2; i++)
        #pragma unroll
        for (int j = 0; j < 8; j++)
            #pragma unroll
            for (int q = 0; q < 4; q++) acc[i][j][q] = 0.0f;

    const int nk = Kg / BKK;

    auto issue = [&](int kt, int s) {
        int kg = kt * BKK;
        uint32_t sa = sabase + s * GEMM_BUF;
        uint32_t sb = sabase + (3 + s) * GEMM_BUF;
        #pragma unroll
        for (int it = 0; it < 4; it++) {
            int idx = tid + it * 256;
            int r = idx >> 3, c = idx & 7;
            cp_async16(sa + (r * LDS_ROW + c * 8) * 2, Ag + (size_t)r * Kg + kg + c * 8);
            cp_async16(sb + (r * LDS_ROW + c * 8) * 2, Bg + (size_t)r * Kg + kg + c * 8);
        }
        cp_commit();
    };

    issue(0, 0);
    issue(1, 1);

    int a_row = wm * 32 + (lane & 15);
    int a_colp = (lane >> 4) * 8;
    int b_row = wn * 64 + (lane & 7) + ((lane >> 4) << 3);
    int b_colp = ((lane >> 3) & 1) * 8;

    int buf = 0;
    for (int kt = 0; kt < nk; kt++) {
        if (kt + 1 < nk) { cp_wait<1>(); } else { cp_wait<0>(); }
        __syncthreads();
        if (kt + 2 < nk) issue(kt + 2, (kt + 2) % 3);

        uint32_t sa = sabase + buf * GEMM_BUF;
        uint32_t sb = sabase + (3 + buf) * GEMM_BUF;
        #pragma unroll
        for (int k16 = 0; k16 < 4; k16++) {
            uint32_t af[2][4];
            #pragma unroll
            for (int mi = 0; mi < 2; mi++) {
                uint32_t addr = sa + (((a_row + mi * 16) * LDS_ROW) + k16 * 16 + a_colp) * 2;
                ldmatrix_x4(af[mi][0], af[mi][1], af[mi][2], af[mi][3], addr);
            }
            uint32_t bfr[4][4];
            #pragma unroll
            for (int ni2 = 0; ni2 < 4; ni2++) {
                uint32_t addr = sb + (((b_row + ni2 * 16) * LDS_ROW) + k16 * 16 + b_colp) * 2;
                ldmatrix_x4(bfr[ni2][0], bfr[ni2][1], bfr[ni2][2], bfr[ni2][3], addr);
            }
            #pragma unroll
            for (int mi = 0; mi < 2; mi++)
                #pragma unroll
                for (int ni = 0; ni < 8; ni++) {
                    uint32_t bb0 = bfr[ni >> 1][(ni & 1) * 2];
                    uint32_t bb1 = bfr[ni >> 1][(ni & 1) * 2 + 1];
                    mma_f16(acc[mi][ni], af[mi][0], af[mi][1], af[mi][2], af[mi][3], bb0, bb1);
                }
        }
        buf = (buf + 1 == 3) ? 0 : buf + 1;
    }

    int cr = lane >> 2;
    int cc = (lane & 3) * 2;

    if (OUT_MODE == 1 && n0 < 1024) {
        const float SCL = 0.125f * 1.44269504f;
        #pragma unroll
        for (int mi = 0; mi < 2; mi++)
            #pragma unroll
            for (int ni = 0; ni < 8; ni++)
                #pragma unroll
                for (int q = 0; q < 4; q++) acc[mi][ni][q] *= SCL;
    }

    if (OUT_MODE == 1 && n0 < 1280) {
        #pragma unroll
        for (int mi = 0; mi < 2; mi++) {
            int r0 = m0 + wm * 32 + mi * 16 + cr;
            int s0 = r0 & (SEQ - 1);
            int s1 = (r0 + 8) & (SEQ - 1);
            #pragma unroll
            for (int ni = 0; ni < 4; ni++) {
                #pragma unroll
                for (int q = 0; q < 4; q++) {
                    int i = ni * 8 + cc + (q & 1);
                    int s = (q < 2) ? s0 : s1;
                    float ang = (float)s * exp10f(-(float)i * 0.125f);
                    float cs = cosf(ang), sn = sinf(ang);
                    float x0 = acc[mi][ni][q], x1 = acc[mi][ni + 4][q];
                    acc[mi][ni][q]     = x0 * cs - x1 * sn;
                    acc[mi][ni + 4][q] = x1 * cs + x0 * sn;
                }
            }
        }
    }

    #pragma unroll
    for (int mi = 0; mi < 2; mi++) {
        #pragma unroll
        for (int ni = 0; ni < 8; ni++) {
            int row = m0 + wm * 32 + mi * 16 + cr;
            int col = n0 + wn * 64 + ni * 8 + cc;
            if (OUT_MODE == 0) {
                *(float2*)&C[(size_t)row * N + col] =
                    make_float2(acc[mi][ni][0], acc[mi][ni][1]);
                *(float2*)&C[(size_t)(row + 8) * N + col] =
                    make_float2(acc[mi][ni][2], acc[mi][ni][3]);
            } else {
                *(uint32_t*)&Chi[(size_t)row * N + col] =
                    pack_h2(acc[mi][ni][0], acc[mi][ni][1]);
                *(uint32_t*)&Chi[(size_t)(row + 8) * N + col] =
                    pack_h2(acc[mi][ni][2], acc[mi][ni][3]);
            }
        }
    }
}

// ---------------------------------------------------------------------------
// fp16 tensor-core flash attention. Q pre-scaled (fused in QKV GEMM),
// Q fragments hoisted. ex2.approx.f16x2 softmax. Hoisted prefetch addresses.
// Double-buffered KV, barrier after compute. Writes ctx plane into g_Ch.
// ---------------------------------------------------------------------------
#define AROW 72
#define ROWB (AROW*2)          // 144 bytes per row
#define SQ_HI 0
#define SKV0  (128*ROWB)       // 18432
#define KVSTG (2*64*ROWB)      // 18432 per stage (K,V)
#define ATTN_SMEM (SKV0 + 2*KVSTG)   // 55296

__global__ __launch_bounds__(256) void attn_mma(
    const __half* __restrict__ Phi, __half* __restrict__ Ch)
{
    extern __shared__ char smc[];
    uint32_t sb = smem_u32(smc);

    int qt = (int)gridDim.x - 1 - (int)blockIdx.x;
    int h  = blockIdx.y;
    int b  = blockIdx.z;
    int kh = h >> 2;

    int tid  = threadIdx.x;
    int lane = tid & 31;
    int wm   = tid >> 5;

    const int kcol = 1024 + kh * DH;
    const int vcol = 1280 + kh * DH;

    // hoisted per-thread prefetch addressing: 4 chunks, sel/r/c fixed per thread
    const __half* kvbase = Phi + (size_t)(b * SEQ) * NQKV;
    uint32_t soff[4];   // element offsets into a 64-row KV tile
    uint32_t doff[4];   // dst offsets within a stage
    #pragma unroll
    for (int it = 0; it < 4; it++) {
        int idx = tid + it * 256;
        int sel = idx >> 9;
        int j = idx & 511;
        int r = j >> 3, c = j & 7;
        soff[it] = (uint32_t)(r * NQKV + ((sel == 0) ? kcol : vcol) + c * 8);
        doff[it] = (uint32_t)(sel * (64 * ROWB) + r * ROWB + c * 16);
    }

    // --- issue Q tile + KV tile 0 ---
    {
        #pragma unroll
        for (int it = 0; it < 4; it++) {
            int idx = tid + it * 256;
            int r = idx >> 3, c = idx & 7;
            const __half* src = Phi
                + (size_t)(b * SEQ + qt * 128 + r) * NQKV + h * DH + c * 8;
            cp_async16(sb + SQ_HI + r * ROWB + c * 16, src);
        }
        #pragma unroll
        for (int it = 0; it < 4; it++)
            cp_async16(sb + SKV0 + doff[it], kvbase + soff[it]);
        cp_commit();
    }

    uint32_t qa_off = (uint32_t)((wm * 16 + (lane & 7) + ((lane >> 3) & 1) * 8) * ROWB
                                 + (lane >> 4) * 16);
    uint32_t kb_off = (uint32_t)(((lane & 7) + (lane >> 4) * 8) * ROWB
                                 + ((lane >> 3) & 1) * 16);
    uint32_t vb_off = (uint32_t)(((lane & 7) + ((lane >> 3) & 1) * 8) * ROWB
                                 + (lane >> 4) * 16);

    cp_wait<0>();
    __syncthreads();
    uint32_t qf[4][4];
    #pragma unroll
    for (int t = 0; t < 4; t++)
        ldmatrix_x4(qf[t][0], qf[t][1], qf[t][2], qf[t][3],
                    sb + SQ_HI + qa_off + t * 32);

    float acc[8][4];
    #pragma unroll
    for (int j = 0; j < 8; j++)
        #pragma unroll
        for (int q = 0; q < 4; q++) acc[j][q] = 0.0f;
    float m0 = -1e30f, m1 = -1e30f, l0 = 0.0f, l1 = 0.0f;

    int row0g = qt * 128 + wm * 16 + (lane >> 2);
    int colbase = 2 * (lane & 3);

    int nkt = 2 * qt + 2;
    for (int kt = 0; kt < nkt; kt++) {
        // prefetch next tile (overlaps with compute; barrier after compute)
        if (kt + 1 < nkt) {
            const __half* srcb = kvbase + (size_t)(kt + 1) * 64 * NQKV;
            uint32_t dstb = sb + SKV0 + ((kt + 1) & 1) * KVSTG;
            #pragma unroll
            for (int it = 0; it < 4; it++)
                cp_async16(dstb + doff[it], srcb + soff[it]);
            cp_commit();
        }

        uint32_t kvb = sb + SKV0 + (kt & 1) * KVSTG;
        uint32_t skh = kvb;
        uint32_t svh = kvb + 64 * ROWB;

        // --- S = Q K^T (Q pre-scaled) ---
        float sf[8][4];
        #pragma unroll
        for (int j = 0; j < 8; j++)
            #pragma unroll
            for (int q = 0; q < 4; q++) sf[j][q] = 0.0f;

        #pragma unroll
        for (int t = 0; t < 4; t++) {
            #pragma unroll
            for (int jj = 0; jj < 4; jj++) {
                uint32_t kmh[4];
                uint32_t off = kb_off + jj * 16 * ROWB + t * 32;
                ldmatrix_x4(kmh[0], kmh[1], kmh[2], kmh[3], skh + off);
                mma_f16(sf[2*jj],   qf[t][0], qf[t][1], qf[t][2], qf[t][3], kmh[0], kmh[1]);
                mma_f16(sf[2*jj+1], qf[t][0], qf[t][1], qf[t][2], qf[t][3], kmh[2], kmh[3]);
            }
        }

        // --- causal mask ---
        bool need_mask = (kt * 64 + 63 > qt * 128 + wm * 16);
        if (need_mask) {
            #pragma unroll
            for (int j = 0; j < 8; j++) {
                int c0 = kt * 64 + 8 * j + colbase;
                if (c0     > row0g)     sf[j][0] = -1e30f;
                if (c0 + 1 > row0g)     sf[j][1] = -1e30f;
                if (c0     > row0g + 8) sf[j][2] = -1e30f;
                if (c0 + 1 > row0g + 8) sf[j][3] = -1e30f;
            }
        }

        // --- online softmax: row-max then P = ex2.f16x2(s - m) ---
        float mx0 = m0, mx1 = m1;
        #pragma unroll
        for (int j = 0; j < 8; j++) {
            mx0 = fmaxf(mx0, fmaxf(sf[j][0], sf[j][1]));
            mx1 = fmaxf(mx1, fmaxf(sf[j][2], sf[j][3]));
        }
        mx0 = fmaxf(mx0, __shfl_xor_sync(0xffffffffu, mx0, 1));
        mx0 = fmaxf(mx0, __shfl_xor_sync(0xffffffffu, mx0, 2));
        mx1 = fmaxf(mx1, __shfl_xor_sync(0xffffffffu, mx1, 1));
        mx1 = fmaxf(mx1, __shfl_xor_sync(0xffffffffu, mx1, 2));
        float corr0 = ex2(m0 - mx0);
        float corr1 = ex2(m1 - mx1);
        m0 = mx0; m1 = mx1;

        #pragma unroll
        for (int j = 0; j < 8; j++) {
            acc[j][0] *= corr0; acc[j][1] *= corr0;
            acc[j][2] *= corr1; acc[j][3] *= corr1;
        }

        // --- P (fp16) + ls + PV fused per t ---
        float ls0 = 0.0f, ls1 = 0.0f;
        #pragma unroll
        for (int t = 0; t < 4; t++) {
            uint32_t aph[4];
            aph[0] = ex2_h2(pack_h2(sf[2*t][0]   - mx0, sf[2*t][1]   - mx0));
            aph[1] = ex2_h2(pack_h2(sf[2*t][2]   - mx1, sf[2*t][3]   - mx1));
            aph[2] = ex2_h2(pack_h2(sf[2*t+1][0] - mx0, sf[2*t+1][1] - mx0));
            aph[3] = ex2_h2(pack_h2(sf[2*t+1][2] - mx1, sf[2*t+1][3] - mx1));
            float2 u0 = unpack_h2(aph[0]); ls0 += u0.x + u0.y;
            float2 u1 = unpack_h2(aph[1]); ls1 += u1.x + u1.y;
            float2 u2 = unpack_h2(aph[2]); ls0 += u2.x + u2.y;
            float2 u3 = unpack_h2(aph[3]); ls1 += u3.x + u3.y;
            #pragma unroll
            for (int jj = 0; jj < 4; jj++) {
                uint32_t vh[4];
                uint32_t off = vb_off + t * 16 * ROWB + jj * 32;
                ldmatrix_x4_t(vh[0], vh[1], vh[2], vh[3], svh + off);
                mma_f16(acc[2*jj],   aph[0], aph[1], aph[2], aph[3], vh[0], vh[1]);
                mma_f16(acc[2*jj+1], aph[0], aph[1], aph[2], aph[3], vh[2], vh[3]);
            }
        }
        l0 = l0 * corr0 + ls0;
        l1 = l1 * corr1 + ls1;

        // barrier AFTER compute: next tile complete, stage free for overwrite
        if (kt + 1 < nkt) {
            cp_wait<0>();
            __syncthreads();
        }
    }

    // --- final normalize + write ctx plane ---
    l0 += __shfl_xor_sync(0xffffffffu, l0, 1);
    l0 += __shfl_xor_sync(0xffffffffu, l0, 2);
    l1 += __shfl_xor_sync(0xffffffffu, l1, 1);
    l1 += __shfl_xor_sync(0xffffffffu, l1, 2);
    float inv0 = 1.0f / l0, inv1 = 1.0f / l1;

    size_t rb0 = (size_t)(b * SEQ + row0g) * DM;
    size_t rb1 = rb0 + 8 * DM;
    int dcol = h * DH + colbase;
    #pragma unroll
    for (int j = 0; j < 8; j++) {
        int d = dcol + 8 * j;
        *(uint32_t*)&Ch[rb0 + d] = pack_h2(acc[j][0] * inv0, acc[j][1] * inv0);
        *(uint32_t*)&Ch[rb1 + d] = pack_h2(acc[j][2] * inv1, acc[j][3] * inv1);
    }
}

// ---------------------------------------------------------------------------
// Launch
// ---------------------------------------------------------------------------
extern "C" void kernel_launch(void* const* d_in, const int* in_sizes, int n_in,
                              void* d_out, int out_size)
{
    const float* x  = (const float*)d_in[0];
    const float* Wq = (const float*)d_in[1];
    const float* Wk = (const float*)d_in[2];
    const float* Wv = (const float*)d_in[3];
    const float* Wo = (const float*)d_in[4];
    float* out = (float*)d_out;

    __half *px1, *pWct, *pWot, *pCh, *pQh;
    cudaGetSymbolAddress((void**)&px1, g_x1);
    cudaGetSymbolAddress((void**)&pWct, g_Wct);
    cudaGetSymbolAddress((void**)&pWot, g_Wot);
    cudaGetSymbolAddress((void**)&pCh, g_Ch);
    cudaGetSymbolAddress((void**)&pQh, g_Qh);

    // All weight transposes in one launch
    {
        dim3 blk(32, 8);
        transpose_all<<<dim3(80, 32), blk>>>(Wq, Wk, Wv, Wo, pWct, pWot);
    }

    // x -> fp16
    convert_rows<<<1024, 256>>>(x, px1, MTOK * DM / 2);

    // QKV projection GEMM with fused RoPE + softmax scale -> fp16 plane
    cudaFuncSetAttribute(mma_gemm<1>, cudaFuncAttributeMaxDynamicSharedMemorySize, GEMM_SMEM);
    cudaFuncSetAttribute(mma_gemm<0>, cudaFuncAttributeMaxDynamicSharedMemorySize, GEMM_SMEM);
    {
        dim3 g(NQKV / BN, MTOK / BM);
        mma_gemm<1><<<g, 256, GEMM_SMEM>>>(px1, pWct, nullptr, pQh, MTOK, NQKV, DM);
    }

    // Flash attention -> ctx plane
    {
        cudaFuncSetAttribute(attn_mma,
                             cudaFuncAttributeMaxDynamicSharedMemorySize,
                             ATTN_SMEM);
        dim3 ga(SEQ / 128, NHEAD, BATCH);
        attn_mma<<<ga, 256, ATTN_SMEM>>>(pQh, pCh);
    }

    // Output projection GEMM -> fp32 out
    {
        dim3 g(DM / BN, MTOK / BM);
        mma_gemm<0><<<g, 256, GEMM_SMEM>>>(pCh, pWot, out, nullptr, MTOK, DM, DM);
    }
}